// round 1
// baseline (speedup 1.0000x reference)
#include <cuda_runtime.h>
#include <math.h>

#define Bq 4
#define Lq 2048
#define DM 1024
#define DI 2048
#define HN 32
#define HD 64
#define DS 128
#define CDIM 2304
#define PROJ 4384
#define CH 64
#define NC 32
#define BL 8192

// ---------------- scratch (device globals; no allocations) ----------------
__device__ float g_xn[BL * DM];                 // rmsnorm(x)
__device__ float g_zx[(size_t)BL * PROJ];       // zxbcdt
__device__ float g_xBC[(size_t)BL * CDIM];      // conv+silu output
__device__ float g_dt[BL * HN];                 // softplus dt
__device__ float g_Y[(size_t)BL * DI];          // SSD output (Yd then +=Yo)
__device__ float g_states[(size_t)Bq * NC * HN * HD * DS];  // per-chunk states
__device__ float g_sin[(size_t)Bq * NC * HN * HD * DS];     // prefix (incoming) states
__device__ float g_asum[Bq * HN * NC];          // per-chunk sum of dt*A
__device__ float g_yn[(size_t)BL * DI];         // gated+normed Y

// ---------------- helpers ----------------
__device__ __forceinline__ float block_sum(float v) {
    __shared__ float red[8];
    #pragma unroll
    for (int o = 16; o; o >>= 1) v += __shfl_down_sync(0xffffffffu, v, o);
    if ((threadIdx.x & 31) == 0) red[threadIdx.x >> 5] = v;
    __syncthreads();
    if (threadIdx.x < 32) {
        v = (threadIdx.x < 8) ? red[threadIdx.x] : 0.f;
        #pragma unroll
        for (int o = 4; o; o >>= 1) v += __shfl_down_sync(0xffffffffu, v, o);
        if (threadIdx.x == 0) red[0] = v;
    }
    __syncthreads();
    return red[0];
}

// ---------------- K1: rmsnorm(x) -> g_xn ----------------
__global__ void __launch_bounds__(256) k_rmsnorm(const float* __restrict__ x,
                                                 const float* __restrict__ w) {
    int row = blockIdx.x;
    const float* xr = x + (size_t)row * DM;
    float s = 0.f;
    for (int i = threadIdx.x; i < DM; i += 256) { float v = xr[i]; s += v * v; }
    float tot = block_sum(s);
    float inv = rsqrtf(tot / DM + 1e-5f);
    for (int i = threadIdx.x; i < DM; i += 256)
        g_xn[(size_t)row * DM + i] = xr[i] * inv * w[i];
}

// ---------------- tiled fp32 GEMM: C[M,N] = A[M,K] * B[N,K]^T (+Res) --------
__device__ __forceinline__ void gemm_body(const float* __restrict__ A,
                                          const float* __restrict__ B,
                                          const float* __restrict__ Res,
                                          float* __restrict__ C,
                                          int M, int Nn, int K) {
    __shared__ float As[16][68];
    __shared__ float Bs[16][68];
    int bm = blockIdx.y * 64, bn = blockIdx.x * 64;
    int tid = threadIdx.x;
    int tx = tid & 15, ty = tid >> 4;
    int lr = tid >> 2;            // 0..63
    int lc = (tid & 3) * 4;       // 0,4,8,12
    float acc[4][4] = {};
    const float* Aptr = A + (size_t)(bm + lr) * K + lc;
    bool bok = (bn + lr) < Nn;
    const float* Bptr = B + (size_t)(bn + lr) * K + lc;
    for (int k0 = 0; k0 < K; k0 += 16) {
        float4 av = *(const float4*)(Aptr + k0);
        float4 bv = bok ? *(const float4*)(Bptr + k0) : make_float4(0.f, 0.f, 0.f, 0.f);
        As[lc][lr] = av.x; As[lc + 1][lr] = av.y; As[lc + 2][lr] = av.z; As[lc + 3][lr] = av.w;
        Bs[lc][lr] = bv.x; Bs[lc + 1][lr] = bv.y; Bs[lc + 2][lr] = bv.z; Bs[lc + 3][lr] = bv.w;
        __syncthreads();
        #pragma unroll
        for (int kk = 0; kk < 16; kk++) {
            float a[4], b[4];
            #pragma unroll
            for (int i = 0; i < 4; i++) a[i] = As[kk][ty * 4 + i];
            #pragma unroll
            for (int j = 0; j < 4; j++) b[j] = Bs[kk][tx * 4 + j];
            #pragma unroll
            for (int i = 0; i < 4; i++)
                #pragma unroll
                for (int j = 0; j < 4; j++) acc[i][j] += a[i] * b[j];
        }
        __syncthreads();
    }
    #pragma unroll
    for (int i = 0; i < 4; i++) {
        int row = bm + ty * 4 + i;
        #pragma unroll
        for (int j = 0; j < 4; j++) {
            int col = bn + tx * 4 + j;
            if (col < Nn) {
                float v = acc[i][j];
                if (Res) v += Res[(size_t)row * Nn + col];
                C[(size_t)row * Nn + col] = v;
            }
        }
    }
}

__global__ void __launch_bounds__(256) k_gemm1(const float* __restrict__ W) {
    gemm_body(g_xn, W, nullptr, g_zx, BL, PROJ, DM);
}
__global__ void __launch_bounds__(256) k_gemm2(const float* __restrict__ W,
                                               const float* __restrict__ x,
                                               float* __restrict__ out) {
    gemm_body(g_yn, W, x, out, BL, DM, DI);
}

// ---------------- K3: causal depthwise conv (w=4) + silu -> g_xBC ----------
__global__ void __launch_bounds__(256) k_conv(const float* __restrict__ cw,
                                              const float* __restrict__ cb) {
    int idx = blockIdx.x * 256 + threadIdx.x;
    if (idx >= BL * CDIM) return;
    int ch = idx % CDIM;
    int bl = idx / CDIM;
    int l = bl % Lq;
    float acc = cb[ch];
    #pragma unroll
    for (int k = 0; k < 4; k++) {
        int ls = l - 3 + k;
        if (ls >= 0)
            acc += g_zx[(size_t)(bl - l + ls) * PROJ + DI + ch] * cw[k * CDIM + ch];
    }
    acc = acc / (1.f + expf(-acc));
    g_xBC[(size_t)bl * CDIM + ch] = acc;
}

// ---------------- K3b: dt = softplus(raw + bias) ----------------
__global__ void __launch_bounds__(256) k_dt(const float* __restrict__ dt_bias) {
    int idx = blockIdx.x * 256 + threadIdx.x;
    if (idx >= BL * HN) return;
    int h = idx & 31;
    float v = g_zx[(size_t)(idx >> 5) * PROJ + DI + CDIM + h] + dt_bias[h];
    g_dt[idx] = (v > 20.f) ? v : log1pf(expf(v));
}

// ---------------- K4: intra-chunk (G, Yd, chunk states) ----------------
#define SMEM_K4 ((64 * 128 + 64 * 128 + 64 * 64 + 64 * 64) * 4)  // 96 KB
__global__ void __launch_bounds__(256) k_chunk(const float* __restrict__ A_log) {
    extern __shared__ float sm[];
    float* sB = sm;            // [64][128]
    float* sC = sm + 8192;     // [64][128]
    float* sX = sm + 16384;    // [64][64]  (xs * dt)
    float* sG = sm + 20480;    // [64][64]
    __shared__ float sDt[64], sAc[64], sDec[64];

    int bid = blockIdx.x;
    int h = bid & 31, c = (bid >> 5) & 31, b = bid >> 10;
    int tid = threadIdx.x;
    float Aval = -expf(A_log[h]);
    int posBase = b * Lq + c * 64;

    if (tid < 64) sDt[tid] = g_dt[(posBase + tid) * HN + h];
    __syncthreads();
    if (tid == 0) {
        float acc = 0.f;
        for (int s = 0; s < 64; s++) { acc += sDt[s] * Aval; sAc[s] = acc; }
    }
    // loads: B, C (64x128), X*dt (64x64)
    #pragma unroll
    for (int k = 0; k < 8; k++) {
        int e4 = tid + k * 256;          // 2048 float4
        int row = e4 >> 5, col4 = e4 & 31;
        const float* base = &g_xBC[(size_t)(posBase + row) * CDIM + DI];
        ((float4*)sB)[e4] = ((const float4*)base)[col4];
        ((float4*)sC)[e4] = ((const float4*)(base + DS))[col4];
    }
    #pragma unroll
    for (int k = 0; k < 4; k++) {
        int e4 = tid + k * 256;          // 1024 float4
        int row = e4 >> 4, col4 = e4 & 15;
        float4 v = ((const float4*)&g_xBC[(size_t)(posBase + row) * CDIM + h * 64])[col4];
        float d = sDt[row];
        v.x *= d; v.y *= d; v.z *= d; v.w *= d;
        ((float4*)sX)[e4] = v;
    }
    __syncthreads();
    if (tid < 64) sDec[tid] = expf(sAc[63] - sAc[tid]);
    __syncthreads();

    // G[l][s] = 1{l>=s} exp(Ac[l]-Ac[s]) * <C[l], B[s]>
    #pragma unroll
    for (int k = 0; k < 16; k++) {
        int e = tid + k * 256;
        int l = e >> 6, s = e & 63;
        float g = 0.f;
        if (l >= s) {
            const float4* c4 = (const float4*)(sC + l * 128);
            const float4* b4 = (const float4*)(sB + s * 128);
            float dot = 0.f;
            #pragma unroll 8
            for (int n = 0; n < 32; n++) {
                float4 cv = c4[n], bv = b4[n];
                dot += cv.x * bv.x + cv.y * bv.y + cv.z * bv.z + cv.w * bv.w;
            }
            g = expf(sAc[l] - sAc[s]) * dot;
        }
        sG[e] = g;
    }
    __syncthreads();

    // Yd[l][p] = sum_s G[l][s] * X[s][p]
    #pragma unroll
    for (int k = 0; k < 4; k++) {
        int e4 = tid + k * 256;          // 1024 float4 outputs
        int l = e4 >> 4, p4 = e4 & 15;
        float4 acc = make_float4(0.f, 0.f, 0.f, 0.f);
        #pragma unroll 8
        for (int s = 0; s < 64; s++) {
            float g = sG[l * 64 + s];
            float4 xv = ((const float4*)(sX + s * 64))[p4];
            acc.x += g * xv.x; acc.y += g * xv.y; acc.z += g * xv.z; acc.w += g * xv.w;
        }
        ((float4*)&g_Y[(size_t)(posBase + l) * DI + h * 64])[p4] = acc;
    }

    // state[p][n] = sum_s B[s][n] * exp(Ac[63]-Ac[s]) * X[s][p]
    size_t sbase = ((size_t)((b * NC + c) * HN + h)) * (64 * 128);
    #pragma unroll
    for (int k = 0; k < 8; k++) {
        int e4 = tid + k * 256;          // 2048 float4 outputs
        int p = e4 >> 5, n4 = e4 & 31;
        float4 acc = make_float4(0.f, 0.f, 0.f, 0.f);
        #pragma unroll 8
        for (int s = 0; s < 64; s++) {
            float xd = sX[s * 64 + p] * sDec[s];
            float4 bv = ((const float4*)(sB + s * 128))[n4];
            acc.x += xd * bv.x; acc.y += xd * bv.y; acc.z += xd * bv.z; acc.w += xd * bv.w;
        }
        ((float4*)&g_states[sbase])[e4] = acc;
    }
    if (tid == 0) g_asum[(b * HN + h) * NC + c] = sAc[63];
}

// ---------------- K5: inter-chunk prefix scan of states ----------------
__global__ void __launch_bounds__(256) k_scan() {
    int bh = blockIdx.x;
    int b = bh >> 5, h = bh & 31;
    int tid = threadIdx.x;
    float S[32];
    #pragma unroll
    for (int j = 0; j < 32; j++) S[j] = 0.f;
    for (int c = 0; c < NC; c++) {
        size_t base = ((size_t)((b * NC + c) * HN + h)) * 8192;
        float dec = expf(g_asum[(b * HN + h) * NC + c]);
        #pragma unroll
        for (int j = 0; j < 32; j++) {
            int e = tid + j * 256;
            g_sin[base + e] = S[j];
            S[j] = S[j] * dec + g_states[base + e];
        }
    }
}

// ---------------- K6: Yo from prefix state; Y += Yo + xs*D ----------------
#define SMEM_K6 ((8192 + 8192) * 4)  // 64 KB
__global__ void __launch_bounds__(256) k_inter(const float* __restrict__ A_log,
                                               const float* __restrict__ Dp) {
    extern __shared__ float sm[];
    float* sC = sm;            // [64][128]
    float* sS = sm + 8192;     // [64][128] prefix state (p, n)
    __shared__ float sDt[64], sAc[64];

    int bid = blockIdx.x;
    int h = bid & 31, c = (bid >> 5) & 31, b = bid >> 10;
    int tid = threadIdx.x;
    float Aval = -expf(A_log[h]);
    float Dv = Dp[h];
    int posBase = b * Lq + c * 64;

    if (tid < 64) sDt[tid] = g_dt[(posBase + tid) * HN + h];
    __syncthreads();
    if (tid == 0) {
        float acc = 0.f;
        for (int s = 0; s < 64; s++) { acc += sDt[s] * Aval; sAc[s] = acc; }
    }
    size_t sbase = ((size_t)((b * NC + c) * HN + h)) * 8192;
    #pragma unroll
    for (int k = 0; k < 8; k++) {
        int e4 = tid + k * 256;
        int row = e4 >> 5, col4 = e4 & 31;
        ((float4*)sC)[e4] =
            ((const float4*)&g_xBC[(size_t)(posBase + row) * CDIM + DI + DS])[col4];
        ((float4*)sS)[e4] = ((const float4*)&g_sin[sbase])[e4];
    }
    __syncthreads();

    #pragma unroll
    for (int k = 0; k < 16; k++) {
        int e = tid + k * 256;
        int l = e >> 6, p = e & 63;
        const float4* c4 = (const float4*)(sC + l * 128);
        const float4* s4 = (const float4*)(sS + p * 128);
        float dot = 0.f;
        #pragma unroll 8
        for (int n = 0; n < 32; n++) {
            float4 cv = c4[n], sv = s4[n];
            dot += cv.x * sv.x + cv.y * sv.y + cv.z * sv.z + cv.w * sv.w;
        }
        float yo = expf(sAc[l]) * dot;
        size_t yi = (size_t)(posBase + l) * DI + h * 64 + p;
        float xs = g_xBC[(size_t)(posBase + l) * CDIM + h * 64 + p];
        g_Y[yi] += yo + xs * Dv;
    }
}

// ---------------- K7: gated rmsnorm: yn = rms(Y * silu(z)) * w ------------
__global__ void __launch_bounds__(256) k_gate(const float* __restrict__ w) {
    __shared__ float sv[DI];
    int row = blockIdx.x;
    int tid = threadIdx.x;
    float s = 0.f;
    for (int i = tid; i < DI; i += 256) {
        float z = g_zx[(size_t)row * PROJ + i];
        float y = g_Y[(size_t)row * DI + i];
        float v = y * z / (1.f + expf(-z));
        sv[i] = v;
        s += v * v;
    }
    float tot = block_sum(s);
    float inv = rsqrtf(tot / DI + 1e-5f);
    for (int i = tid; i < DI; i += 256)
        g_yn[(size_t)row * DI + i] = sv[i] * inv * w[i];
}

// ---------------- launcher ----------------
extern "C" void kernel_launch(void* const* d_in, const int* in_sizes, int n_in,
                              void* d_out, int out_size) {
    const float* x       = (const float*)d_in[0];
    const float* norm_w  = (const float*)d_in[1];
    const float* in_W    = (const float*)d_in[2];
    const float* conv_w  = (const float*)d_in[3];
    const float* conv_b  = (const float*)d_in[4];
    const float* dt_bias = (const float*)d_in[5];
    const float* A_log   = (const float*)d_in[6];
    const float* Dp      = (const float*)d_in[7];
    const float* ni_w    = (const float*)d_in[8];
    const float* out_W   = (const float*)d_in[9];
    float* out = (float*)d_out;

    cudaFuncSetAttribute(k_chunk, cudaFuncAttributeMaxDynamicSharedMemorySize, SMEM_K4);
    cudaFuncSetAttribute(k_inter, cudaFuncAttributeMaxDynamicSharedMemorySize, SMEM_K6);

    k_rmsnorm<<<BL, 256>>>(x, norm_w);
    k_gemm1<<<dim3((PROJ + 63) / 64, BL / 64), 256>>>(in_W);
    k_conv<<<(BL * CDIM + 255) / 256, 256>>>(conv_w, conv_b);
    k_dt<<<(BL * HN + 255) / 256, 256>>>(dt_bias);
    k_chunk<<<Bq * NC * HN, 256, SMEM_K4>>>(A_log);
    k_scan<<<Bq * HN, 256>>>();
    k_inter<<<Bq * NC * HN, 256, SMEM_K6>>>(A_log, Dp);
    k_gate<<<BL, 256>>>(ni_w);
    k_gemm2<<<dim3(DM / 64, BL / 64), 256>>>(out_W, x, out);
}

// round 2
// speedup vs baseline: 1.4582x; 1.4582x over previous
#include <cuda_runtime.h>
#include <math.h>
#include <stdint.h>

#define Bq 4
#define Lq 2048
#define DM 1024
#define DI 2048
#define HN 32
#define HD 64
#define DS 128
#define CDIM 2304
#define PROJ 4384
#define CH 64
#define NC 32
#define BL 8192

// ---------------- scratch (device globals; no allocations) ----------------
__device__ float g_xn[BL * DM];                 // rmsnorm(x)
__device__ float g_zx[(size_t)BL * PROJ];       // zxbcdt
__device__ float g_xBC[(size_t)BL * CDIM];      // conv+silu output
__device__ float g_dt[BL * HN];                 // softplus dt
__device__ float g_Y[(size_t)BL * DI];          // SSD output (Yd then +=Yo)
__device__ float g_states[(size_t)Bq * NC * HN * HD * DS];  // per-chunk states
__device__ float g_sin[(size_t)Bq * NC * HN * HD * DS];     // prefix (incoming) states
__device__ float g_asum[Bq * HN * NC];          // per-chunk sum of dt*A
__device__ float g_yn[(size_t)BL * DI];         // gated+normed Y

// ---------------- helpers ----------------
__device__ __forceinline__ float block_sum(float v) {
    __shared__ float red[8];
    #pragma unroll
    for (int o = 16; o; o >>= 1) v += __shfl_down_sync(0xffffffffu, v, o);
    if ((threadIdx.x & 31) == 0) red[threadIdx.x >> 5] = v;
    __syncthreads();
    if (threadIdx.x < 32) {
        v = (threadIdx.x < 8) ? red[threadIdx.x] : 0.f;
        #pragma unroll
        for (int o = 4; o; o >>= 1) v += __shfl_down_sync(0xffffffffu, v, o);
        if (threadIdx.x == 0) red[0] = v;
    }
    __syncthreads();
    return red[0];
}

__device__ __forceinline__ uint32_t f2tf(float x) {
    uint32_t u;
    asm("cvt.rna.tf32.f32 %0, %1;" : "=r"(u) : "f"(x));
    return u;
}

__device__ __forceinline__ void mma_tf32(float c[4], const uint32_t a[4], const uint32_t b[2]) {
    asm volatile(
        "mma.sync.aligned.m16n8k8.row.col.f32.tf32.tf32.f32 "
        "{%0,%1,%2,%3}, {%4,%5,%6,%7}, {%8,%9}, {%0,%1,%2,%3};"
        : "+f"(c[0]), "+f"(c[1]), "+f"(c[2]), "+f"(c[3])
        : "r"(a[0]), "r"(a[1]), "r"(a[2]), "r"(a[3]), "r"(b[0]), "r"(b[1]));
}

// ---------------- K1: rmsnorm(x) -> g_xn ----------------
__global__ void __launch_bounds__(256) k_rmsnorm(const float* __restrict__ x,
                                                 const float* __restrict__ w) {
    int row = blockIdx.x;
    const float* xr = x + (size_t)row * DM;
    float s = 0.f;
    for (int i = threadIdx.x; i < DM; i += 256) { float v = xr[i]; s += v * v; }
    float tot = block_sum(s);
    float inv = rsqrtf(tot / DM + 1e-5f);
    for (int i = threadIdx.x; i < DM; i += 256)
        g_xn[(size_t)row * DM + i] = xr[i] * inv * w[i];
}

// ---------------- TF32 tensor-core GEMM: C[M,N] = A[M,K] * B[N,K]^T (+Res) --
// CTA tile 128x128, K-step 32. 8 warps, each owns a 32x64 warp tile.
// smem layout: [row][k] with row stride 36 floats (144B = 9*16B, float4 ok,
// conflict-free for both fill and fragment loads).
__device__ __forceinline__ void gemm_tf32_body(const float* __restrict__ A,
                                               const float* __restrict__ Bw,
                                               const float* __restrict__ Res,
                                               float* __restrict__ C,
                                               int M, int Nn, int K) {
    __shared__ float sA[128 * 36];
    __shared__ float sB[128 * 36];
    int bm = blockIdx.y * 128, bn = blockIdx.x * 128;
    int tid = threadIdx.x;
    int w = tid >> 5, lane = tid & 31;
    int g = lane >> 2, t = lane & 3;
    int wm = (w >> 1) * 32, wn = (w & 1) * 64;

    float acc[2][8][4];
    #pragma unroll
    for (int im = 0; im < 2; im++)
        #pragma unroll
        for (int in = 0; in < 8; in++)
            #pragma unroll
            for (int q = 0; q < 4; q++) acc[im][in][q] = 0.f;

    for (int k0 = 0; k0 < K; k0 += 32) {
        #pragma unroll
        for (int i = 0; i < 4; i++) {
            int idx = tid + 256 * i;
            int row = idx >> 3, c0 = (idx & 7) * 4;
            float4 av = *(const float4*)(A + (size_t)(bm + row) * K + k0 + c0);
            float* sa = sA + row * 36 + c0;
            sa[0] = __uint_as_float(f2tf(av.x));
            sa[1] = __uint_as_float(f2tf(av.y));
            sa[2] = __uint_as_float(f2tf(av.z));
            sa[3] = __uint_as_float(f2tf(av.w));
            int n = bn + row;
            float4 bv = (n < Nn) ? *(const float4*)(Bw + (size_t)n * K + k0 + c0)
                                 : make_float4(0.f, 0.f, 0.f, 0.f);
            float* sb = sB + row * 36 + c0;
            sb[0] = __uint_as_float(f2tf(bv.x));
            sb[1] = __uint_as_float(f2tf(bv.y));
            sb[2] = __uint_as_float(f2tf(bv.z));
            sb[3] = __uint_as_float(f2tf(bv.w));
        }
        __syncthreads();
        #pragma unroll
        for (int kk = 0; kk < 4; kk++) {
            int k = kk * 8;
            uint32_t af[2][4];
            #pragma unroll
            for (int im = 0; im < 2; im++) {
                int r0 = wm + im * 16 + g;
                af[im][0] = __float_as_uint(sA[r0 * 36 + k + t]);
                af[im][1] = __float_as_uint(sA[(r0 + 8) * 36 + k + t]);
                af[im][2] = __float_as_uint(sA[r0 * 36 + k + t + 4]);
                af[im][3] = __float_as_uint(sA[(r0 + 8) * 36 + k + t + 4]);
            }
            uint32_t bf[8][2];
            #pragma unroll
            for (int in = 0; in < 8; in++) {
                int n0 = wn + in * 8 + g;
                bf[in][0] = __float_as_uint(sB[n0 * 36 + k + t]);
                bf[in][1] = __float_as_uint(sB[n0 * 36 + k + t + 4]);
            }
            #pragma unroll
            for (int im = 0; im < 2; im++)
                #pragma unroll
                for (int in = 0; in < 8; in++)
                    mma_tf32(acc[im][in], af[im], bf[in]);
        }
        __syncthreads();
    }

    // epilogue: c0/c1 at (row, col/col+1), c2/c3 at (row+8, col/col+1)
    #pragma unroll
    for (int im = 0; im < 2; im++) {
        int row = bm + wm + im * 16 + g;
        #pragma unroll
        for (int in = 0; in < 8; in++) {
            int col = bn + wn + in * 8 + 2 * t;
            if (col < Nn) {
                size_t o0 = (size_t)row * Nn + col;
                size_t o1 = (size_t)(row + 8) * Nn + col;
                float v0 = acc[im][in][0], v1 = acc[im][in][1];
                float v2 = acc[im][in][2], v3 = acc[im][in][3];
                if (Res) {
                    v0 += Res[o0]; v1 += Res[o0 + 1];
                    v2 += Res[o1]; v3 += Res[o1 + 1];
                }
                C[o0] = v0; C[o0 + 1] = v1;
                C[o1] = v2; C[o1 + 1] = v3;
            }
        }
    }
}

__global__ void __launch_bounds__(256) k_gemm1(const float* __restrict__ W) {
    gemm_tf32_body(g_xn, W, nullptr, g_zx, BL, PROJ, DM);
}
__global__ void __launch_bounds__(256) k_gemm2(const float* __restrict__ W,
                                               const float* __restrict__ x,
                                               float* __restrict__ out) {
    gemm_tf32_body(g_yn, W, x, out, BL, DM, DI);
}

// ---------------- K3: causal depthwise conv (w=4) + silu -> g_xBC ----------
__global__ void __launch_bounds__(256) k_conv(const float* __restrict__ cw,
                                              const float* __restrict__ cb) {
    int idx = blockIdx.x * 256 + threadIdx.x;
    if (idx >= BL * CDIM) return;
    int ch = idx % CDIM;
    int bl = idx / CDIM;
    int l = bl % Lq;
    float acc = cb[ch];
    #pragma unroll
    for (int k = 0; k < 4; k++) {
        int ls = l - 3 + k;
        if (ls >= 0)
            acc += g_zx[(size_t)(bl - l + ls) * PROJ + DI + ch] * cw[k * CDIM + ch];
    }
    acc = acc / (1.f + expf(-acc));
    g_xBC[(size_t)bl * CDIM + ch] = acc;
}

// ---------------- K3b: dt = softplus(raw + bias) ----------------
__global__ void __launch_bounds__(256) k_dt(const float* __restrict__ dt_bias) {
    int idx = blockIdx.x * 256 + threadIdx.x;
    if (idx >= BL * HN) return;
    int h = idx & 31;
    float v = g_zx[(size_t)(idx >> 5) * PROJ + DI + CDIM + h] + dt_bias[h];
    g_dt[idx] = (v > 20.f) ? v : log1pf(expf(v));
}

// ---------------- K4: intra-chunk (G, Yd, chunk states) ----------------
#define SMEM_K4 ((64 * 128 + 64 * 128 + 64 * 64 + 64 * 64) * 4)  // 96 KB
__global__ void __launch_bounds__(256) k_chunk(const float* __restrict__ A_log) {
    extern __shared__ float sm[];
    float* sB = sm;            // [64][128]
    float* sC = sm + 8192;     // [64][128]
    float* sX = sm + 16384;    // [64][64]  (xs * dt)
    float* sG = sm + 20480;    // [64][64]
    __shared__ float sDt[64], sAc[64], sDec[64];

    int bid = blockIdx.x;
    int h = bid & 31, c = (bid >> 5) & 31, b = bid >> 10;
    int tid = threadIdx.x;
    float Aval = -expf(A_log[h]);
    int posBase = b * Lq + c * 64;

    if (tid < 64) sDt[tid] = g_dt[(posBase + tid) * HN + h];
    __syncthreads();
    if (tid == 0) {
        float acc = 0.f;
        for (int s = 0; s < 64; s++) { acc += sDt[s] * Aval; sAc[s] = acc; }
    }
    // loads: B, C (64x128), X*dt (64x64)
    #pragma unroll
    for (int k = 0; k < 8; k++) {
        int e4 = tid + k * 256;          // 2048 float4
        int row = e4 >> 5, col4 = e4 & 31;
        const float* base = &g_xBC[(size_t)(posBase + row) * CDIM + DI];
        ((float4*)sB)[e4] = ((const float4*)base)[col4];
        ((float4*)sC)[e4] = ((const float4*)(base + DS))[col4];
    }
    #pragma unroll
    for (int k = 0; k < 4; k++) {
        int e4 = tid + k * 256;          // 1024 float4
        int row = e4 >> 4, col4 = e4 & 15;
        float4 v = ((const float4*)&g_xBC[(size_t)(posBase + row) * CDIM + h * 64])[col4];
        float d = sDt[row];
        v.x *= d; v.y *= d; v.z *= d; v.w *= d;
        ((float4*)sX)[e4] = v;
    }
    __syncthreads();
    if (tid < 64) sDec[tid] = expf(sAc[63] - sAc[tid]);
    __syncthreads();

    // G[l][s] = 1{l>=s} exp(Ac[l]-Ac[s]) * <C[l], B[s]>
    #pragma unroll
    for (int k = 0; k < 16; k++) {
        int e = tid + k * 256;
        int l = e >> 6, s = e & 63;
        float g = 0.f;
        if (l >= s) {
            const float4* c4 = (const float4*)(sC + l * 128);
            const float4* b4 = (const float4*)(sB + s * 128);
            float dot = 0.f;
            #pragma unroll 8
            for (int n = 0; n < 32; n++) {
                float4 cv = c4[n], bv = b4[n];
                dot += cv.x * bv.x + cv.y * bv.y + cv.z * bv.z + cv.w * bv.w;
            }
            g = expf(sAc[l] - sAc[s]) * dot;
        }
        sG[e] = g;
    }
    __syncthreads();

    // Yd[l][p] = sum_s G[l][s] * X[s][p]
    #pragma unroll
    for (int k = 0; k < 4; k++) {
        int e4 = tid + k * 256;          // 1024 float4 outputs
        int l = e4 >> 4, p4 = e4 & 15;
        float4 acc = make_float4(0.f, 0.f, 0.f, 0.f);
        #pragma unroll 8
        for (int s = 0; s < 64; s++) {
            float g = sG[l * 64 + s];
            float4 xv = ((const float4*)(sX + s * 64))[p4];
            acc.x += g * xv.x; acc.y += g * xv.y; acc.z += g * xv.z; acc.w += g * xv.w;
        }
        ((float4*)&g_Y[(size_t)(posBase + l) * DI + h * 64])[p4] = acc;
    }

    // state[p][n] = sum_s B[s][n] * exp(Ac[63]-Ac[s]) * X[s][p]
    size_t sbase = ((size_t)((b * NC + c) * HN + h)) * (64 * 128);
    #pragma unroll
    for (int k = 0; k < 8; k++) {
        int e4 = tid + k * 256;          // 2048 float4 outputs
        int p = e4 >> 5, n4 = e4 & 31;
        float4 acc = make_float4(0.f, 0.f, 0.f, 0.f);
        #pragma unroll 8
        for (int s = 0; s < 64; s++) {
            float xd = sX[s * 64 + p] * sDec[s];
            float4 bv = ((const float4*)(sB + s * 128))[n4];
            acc.x += xd * bv.x; acc.y += xd * bv.y; acc.z += xd * bv.z; acc.w += xd * bv.w;
        }
        ((float4*)&g_states[sbase])[e4] = acc;
    }
    if (tid == 0) g_asum[(b * HN + h) * NC + c] = sAc[63];
}

// ---------------- K5: inter-chunk prefix scan of states ----------------
__global__ void __launch_bounds__(256) k_scan() {
    int bh = blockIdx.x;
    int b = bh >> 5, h = bh & 31;
    int tid = threadIdx.x;
    float S[32];
    #pragma unroll
    for (int j = 0; j < 32; j++) S[j] = 0.f;
    for (int c = 0; c < NC; c++) {
        size_t base = ((size_t)((b * NC + c) * HN + h)) * 8192;
        float dec = expf(g_asum[(b * HN + h) * NC + c]);
        #pragma unroll
        for (int j = 0; j < 32; j++) {
            int e = tid + j * 256;
            g_sin[base + e] = S[j];
            S[j] = S[j] * dec + g_states[base + e];
        }
    }
}

// ---------------- K6: Yo from prefix state; Y += Yo + xs*D ----------------
#define SMEM_K6 ((8192 + 8192) * 4)  // 64 KB
__global__ void __launch_bounds__(256) k_inter(const float* __restrict__ A_log,
                                               const float* __restrict__ Dp) {
    extern __shared__ float sm[];
    float* sC = sm;            // [64][128]
    float* sS = sm + 8192;     // [64][128] prefix state (p, n)
    __shared__ float sDt[64], sAc[64];

    int bid = blockIdx.x;
    int h = bid & 31, c = (bid >> 5) & 31, b = bid >> 10;
    int tid = threadIdx.x;
    float Aval = -expf(A_log[h]);
    float Dv = Dp[h];
    int posBase = b * Lq + c * 64;

    if (tid < 64) sDt[tid] = g_dt[(posBase + tid) * HN + h];
    __syncthreads();
    if (tid == 0) {
        float acc = 0.f;
        for (int s = 0; s < 64; s++) { acc += sDt[s] * Aval; sAc[s] = acc; }
    }
    size_t sbase = ((size_t)((b * NC + c) * HN + h)) * 8192;
    #pragma unroll
    for (int k = 0; k < 8; k++) {
        int e4 = tid + k * 256;
        int row = e4 >> 5, col4 = e4 & 31;
        ((float4*)sC)[e4] =
            ((const float4*)&g_xBC[(size_t)(posBase + row) * CDIM + DI + DS])[col4];
        ((float4*)sS)[e4] = ((const float4*)&g_sin[sbase])[e4];
    }
    __syncthreads();

    #pragma unroll
    for (int k = 0; k < 16; k++) {
        int e = tid + k * 256;
        int l = e >> 6, p = e & 63;
        const float4* c4 = (const float4*)(sC + l * 128);
        const float4* s4 = (const float4*)(sS + p * 128);
        float dot = 0.f;
        #pragma unroll 8
        for (int n = 0; n < 32; n++) {
            float4 cv = c4[n], sv = s4[n];
            dot += cv.x * sv.x + cv.y * sv.y + cv.z * sv.z + cv.w * sv.w;
        }
        float yo = expf(sAc[l]) * dot;
        size_t yi = (size_t)(posBase + l) * DI + h * 64 + p;
        float xs = g_xBC[(size_t)(posBase + l) * CDIM + h * 64 + p];
        g_Y[yi] += yo + xs * Dv;
    }
}

// ---------------- K7: gated rmsnorm: yn = rms(Y * silu(z)) * w ------------
__global__ void __launch_bounds__(256) k_gate(const float* __restrict__ w) {
    __shared__ float sv[DI];
    int row = blockIdx.x;
    int tid = threadIdx.x;
    float s = 0.f;
    for (int i = tid; i < DI; i += 256) {
        float z = g_zx[(size_t)row * PROJ + i];
        float y = g_Y[(size_t)row * DI + i];
        float v = y * z / (1.f + expf(-z));
        sv[i] = v;
        s += v * v;
    }
    float tot = block_sum(s);
    float inv = rsqrtf(tot / DI + 1e-5f);
    for (int i = tid; i < DI; i += 256)
        g_yn[(size_t)row * DI + i] = sv[i] * inv * w[i];
}

// ---------------- launcher ----------------
extern "C" void kernel_launch(void* const* d_in, const int* in_sizes, int n_in,
                              void* d_out, int out_size) {
    const float* x       = (const float*)d_in[0];
    const float* norm_w  = (const float*)d_in[1];
    const float* in_W    = (const float*)d_in[2];
    const float* conv_w  = (const float*)d_in[3];
    const float* conv_b  = (const float*)d_in[4];
    const float* dt_bias = (const float*)d_in[5];
    const float* A_log   = (const float*)d_in[6];
    const float* Dp      = (const float*)d_in[7];
    const float* ni_w    = (const float*)d_in[8];
    const float* out_W   = (const float*)d_in[9];
    float* out = (float*)d_out;

    cudaFuncSetAttribute(k_chunk, cudaFuncAttributeMaxDynamicSharedMemorySize, SMEM_K4);
    cudaFuncSetAttribute(k_inter, cudaFuncAttributeMaxDynamicSharedMemorySize, SMEM_K6);

    k_rmsnorm<<<BL, 256>>>(x, norm_w);
    k_gemm1<<<dim3((PROJ + 127) / 128, BL / 128), 256>>>(in_W);
    k_conv<<<(BL * CDIM + 255) / 256, 256>>>(conv_w, conv_b);
    k_dt<<<(BL * HN + 255) / 256, 256>>>(dt_bias);
    k_chunk<<<Bq * NC * HN, 256, SMEM_K4>>>(A_log);
    k_scan<<<Bq * HN, 256>>>();
    k_inter<<<Bq * NC * HN, 256, SMEM_K6>>>(A_log, Dp);
    k_gate<<<BL, 256>>>(ni_w);
    k_gemm2<<<dim3(DM / 128, BL / 128), 256>>>(out_W, x, out);
}

// round 3
// speedup vs baseline: 1.4773x; 1.0131x over previous
#include <cuda_runtime.h>
#include <math.h>
#include <stdint.h>

#define Bq 4
#define Lq 2048
#define DM 1024
#define DI 2048
#define HN 32
#define HD 64
#define DS 128
#define CDIM 2304
#define PROJ 4384
#define CH 64
#define NC 32
#define BL 8192

// ---------------- scratch (device globals; no allocations) ----------------
__device__ float g_xn[BL * DM];                 // rmsnorm(x), tf32-rounded
__device__ float g_zx[(size_t)BL * PROJ];       // zxbcdt
__device__ float g_xBC[(size_t)BL * CDIM];      // conv+silu output
__device__ float g_dt[BL * HN];                 // softplus dt
__device__ float g_Y[(size_t)BL * DI];          // SSD output (Yd then +=Yo)
__device__ float g_states[(size_t)Bq * NC * HN * HD * DS];
__device__ float g_sin[(size_t)Bq * NC * HN * HD * DS];
__device__ float g_asum[Bq * HN * NC];
__device__ float g_yn[(size_t)BL * DI];         // gated+normed Y, tf32-rounded
__device__ float g_Win[(size_t)PROJ * DM];      // tf32-rounded in_proj_W
__device__ float g_Wout[(size_t)DM * DI];       // tf32-rounded out_proj_W

// ---------------- helpers ----------------
__device__ __forceinline__ float block_sum(float v) {
    __shared__ float red[8];
    #pragma unroll
    for (int o = 16; o; o >>= 1) v += __shfl_down_sync(0xffffffffu, v, o);
    if ((threadIdx.x & 31) == 0) red[threadIdx.x >> 5] = v;
    __syncthreads();
    if (threadIdx.x < 32) {
        v = (threadIdx.x < 8) ? red[threadIdx.x] : 0.f;
        #pragma unroll
        for (int o = 4; o; o >>= 1) v += __shfl_down_sync(0xffffffffu, v, o);
        if (threadIdx.x == 0) red[0] = v;
    }
    __syncthreads();
    return red[0];
}

__device__ __forceinline__ float f2tf(float x) {
    uint32_t u;
    asm("cvt.rna.tf32.f32 %0, %1;" : "=r"(u) : "f"(x));
    return __uint_as_float(u);
}

__device__ __forceinline__ void mma_tf32(float c[4], const uint32_t a[4], const uint32_t b[2]) {
    asm volatile(
        "mma.sync.aligned.m16n8k8.row.col.f32.tf32.tf32.f32 "
        "{%0,%1,%2,%3}, {%4,%5,%6,%7}, {%8,%9}, {%0,%1,%2,%3};"
        : "+f"(c[0]), "+f"(c[1]), "+f"(c[2]), "+f"(c[3])
        : "r"(a[0]), "r"(a[1]), "r"(a[2]), "r"(a[3]), "r"(b[0]), "r"(b[1]));
}

// ---------------- K0: tf32-round weights into scratch ----------------
__global__ void __launch_bounds__(256) k_cvt(const float* __restrict__ src,
                                             float* __restrict__ dst, int n4) {
    int i = blockIdx.x * 256 + threadIdx.x;
    if (i >= n4) return;
    float4 v = ((const float4*)src)[i];
    v.x = f2tf(v.x); v.y = f2tf(v.y); v.z = f2tf(v.z); v.w = f2tf(v.w);
    ((float4*)dst)[i] = v;
}

// ---------------- K1: rmsnorm(x) -> g_xn (tf32-rounded) ----------------
__global__ void __launch_bounds__(256) k_rmsnorm(const float* __restrict__ x,
                                                 const float* __restrict__ w) {
    int row = blockIdx.x;
    const float* xr = x + (size_t)row * DM;
    float s = 0.f;
    for (int i = threadIdx.x; i < DM; i += 256) { float v = xr[i]; s += v * v; }
    float tot = block_sum(s);
    float inv = rsqrtf(tot / DM + 1e-5f);
    for (int i = threadIdx.x; i < DM; i += 256)
        g_xn[(size_t)row * DM + i] = f2tf(xr[i] * inv * w[i]);
}

// ---------------- TF32 pipelined GEMM: C[M,N] = A[M,K]*B[N,K]^T (+Res) -----
// CTA tile 256x128, K-step 32, double-buffered cp.async.
// 8 warps, each 64x64. smem row stride 36 floats (conflict-free, 16B aligned).
#define SA_FLOATS (256 * 36)       // 9216
#define SB_FLOATS (128 * 36)       // 4608
#define STAGE_FLOATS (SA_FLOATS + SB_FLOATS)
#define SMEM_GEMM (STAGE_FLOATS * 2 * 4)   // 110592 bytes

__device__ __forceinline__ void stage_copy(const float* __restrict__ A,
                                           const float* __restrict__ Bw,
                                           float* sA, float* sB,
                                           int bm, int bn, int Nn, int K,
                                           int k0, int tid) {
    #pragma unroll
    for (int i = 0; i < 8; i++) {
        int c = tid + 256 * i;                 // 2048 16B chunks
        int row = c >> 3, col4 = (c & 7) * 4;
        uint32_t d = (uint32_t)__cvta_generic_to_shared(sA + row * 36 + col4);
        const float* g = A + (size_t)(bm + row) * K + k0 + col4;
        asm volatile("cp.async.cg.shared.global [%0], [%1], 16;" :: "r"(d), "l"(g));
    }
    #pragma unroll
    for (int i = 0; i < 4; i++) {
        int c = tid + 256 * i;                 // 1024 16B chunks
        int row = c >> 3, col4 = (c & 7) * 4;
        uint32_t d = (uint32_t)__cvta_generic_to_shared(sB + row * 36 + col4);
        int n = bn + row;
        int ok = (n < Nn);
        const float* g = Bw + (size_t)(ok ? n : 0) * K + k0 + col4;
        int sz = ok ? 16 : 0;
        asm volatile("cp.async.cg.shared.global [%0], [%1], 16, %2;" :: "r"(d), "l"(g), "r"(sz));
    }
}

__device__ __forceinline__ void stage_compute(const float* sA, const float* sB,
                                              float acc[4][8][4],
                                              int wm, int wn, int g, int t) {
    #pragma unroll
    for (int kk = 0; kk < 4; kk++) {
        int k = kk * 8;
        uint32_t af[4][4];
        #pragma unroll
        for (int im = 0; im < 4; im++) {
            int r0 = wm + im * 16 + g;
            af[im][0] = __float_as_uint(sA[r0 * 36 + k + t]);
            af[im][1] = __float_as_uint(sA[(r0 + 8) * 36 + k + t]);
            af[im][2] = __float_as_uint(sA[r0 * 36 + k + t + 4]);
            af[im][3] = __float_as_uint(sA[(r0 + 8) * 36 + k + t + 4]);
        }
        uint32_t bf[8][2];
        #pragma unroll
        for (int in = 0; in < 8; in++) {
            int n0 = wn + in * 8 + g;
            bf[in][0] = __float_as_uint(sB[n0 * 36 + k + t]);
            bf[in][1] = __float_as_uint(sB[n0 * 36 + k + t + 4]);
        }
        #pragma unroll
        for (int im = 0; im < 4; im++)
            #pragma unroll
            for (int in = 0; in < 8; in++)
                mma_tf32(acc[im][in], af[im], bf[in]);
    }
}

__device__ __forceinline__ void gemm_tf32_body(const float* __restrict__ A,
                                               const float* __restrict__ Bw,
                                               const float* __restrict__ Res,
                                               float* __restrict__ C,
                                               int M, int Nn, int K) {
    extern __shared__ float smp[];
    float* sAb[2] = { smp, smp + STAGE_FLOATS };
    float* sBb[2] = { smp + SA_FLOATS, smp + STAGE_FLOATS + SA_FLOATS };
    int bm = blockIdx.y * 256, bn = blockIdx.x * 128;
    int tid = threadIdx.x;
    int w = tid >> 5, lane = tid & 31, g = lane >> 2, t = lane & 3;
    int wm = (w & 3) * 64, wn = (w >> 2) * 64;

    float acc[4][8][4] = {};

    stage_copy(A, Bw, sAb[0], sBb[0], bm, bn, Nn, K, 0, tid);
    asm volatile("cp.async.commit_group;");

    int nk = K / 32;
    for (int kt = 0; kt < nk; kt++) {
        int cur = kt & 1;
        if (kt + 1 < nk) {
            stage_copy(A, Bw, sAb[cur ^ 1], sBb[cur ^ 1], bm, bn, Nn, K, (kt + 1) * 32, tid);
            asm volatile("cp.async.commit_group;");
            asm volatile("cp.async.wait_group 1;");
        } else {
            asm volatile("cp.async.wait_group 0;");
        }
        __syncthreads();
        stage_compute(sAb[cur], sBb[cur], acc, wm, wn, g, t);
        __syncthreads();
    }

    #pragma unroll
    for (int im = 0; im < 4; im++) {
        int row = bm + wm + im * 16 + g;
        #pragma unroll
        for (int in = 0; in < 8; in++) {
            int col = bn + wn + in * 8 + 2 * t;
            if (col < Nn) {
                size_t o0 = (size_t)row * Nn + col;
                size_t o1 = (size_t)(row + 8) * Nn + col;
                float v0 = acc[im][in][0], v1 = acc[im][in][1];
                float v2 = acc[im][in][2], v3 = acc[im][in][3];
                if (Res) {
                    v0 += Res[o0]; v1 += Res[o0 + 1];
                    v2 += Res[o1]; v3 += Res[o1 + 1];
                }
                C[o0] = v0; C[o0 + 1] = v1;
                C[o1] = v2; C[o1 + 1] = v3;
            }
        }
    }
}

__global__ void __launch_bounds__(256) k_gemm1() {
    gemm_tf32_body(g_xn, g_Win, nullptr, g_zx, BL, PROJ, DM);
}
__global__ void __launch_bounds__(256) k_gemm2(const float* __restrict__ x,
                                               float* __restrict__ out) {
    gemm_tf32_body(g_yn, g_Wout, x, out, BL, DM, DI);
}

// ---------------- K3: causal depthwise conv (w=4) + silu -> g_xBC ----------
__global__ void __launch_bounds__(256) k_conv(const float* __restrict__ cw,
                                              const float* __restrict__ cb) {
    int idx = blockIdx.x * 256 + threadIdx.x;
    if (idx >= BL * CDIM) return;
    int ch = idx % CDIM;
    int bl = idx / CDIM;
    int l = bl % Lq;
    float acc = cb[ch];
    #pragma unroll
    for (int k = 0; k < 4; k++) {
        int ls = l - 3 + k;
        if (ls >= 0)
            acc += g_zx[(size_t)(bl - l + ls) * PROJ + DI + ch] * cw[k * CDIM + ch];
    }
    acc = acc / (1.f + expf(-acc));
    g_xBC[(size_t)bl * CDIM + ch] = acc;
}

// ---------------- K3b: dt = softplus(raw + bias) ----------------
__global__ void __launch_bounds__(256) k_dt(const float* __restrict__ dt_bias) {
    int idx = blockIdx.x * 256 + threadIdx.x;
    if (idx >= BL * HN) return;
    int h = idx & 31;
    float v = g_zx[(size_t)(idx >> 5) * PROJ + DI + CDIM + h] + dt_bias[h];
    g_dt[idx] = (v > 20.f) ? v : log1pf(expf(v));
}

// ---------------- K4: intra-chunk (G, Yd, chunk states) ----------------
#define SMEM_K4 ((64 * 128 + 64 * 128 + 64 * 64 + 64 * 64) * 4)  // 96 KB
__global__ void __launch_bounds__(256) k_chunk(const float* __restrict__ A_log) {
    extern __shared__ float sm[];
    float* sB = sm;            // [64][128]
    float* sC = sm + 8192;     // [64][128]
    float* sX = sm + 16384;    // [64][64]  (xs * dt)
    float* sG = sm + 20480;    // [64][64]
    __shared__ float sDt[64], sAc[64], sDec[64];

    int bid = blockIdx.x;
    int h = bid & 31, c = (bid >> 5) & 31, b = bid >> 10;
    int tid = threadIdx.x;
    float Aval = -expf(A_log[h]);
    int posBase = b * Lq + c * 64;

    if (tid < 64) sDt[tid] = g_dt[(posBase + tid) * HN + h];
    __syncthreads();
    if (tid == 0) {
        float acc = 0.f;
        for (int s = 0; s < 64; s++) { acc += sDt[s] * Aval; sAc[s] = acc; }
    }
    #pragma unroll
    for (int k = 0; k < 8; k++) {
        int e4 = tid + k * 256;
        int row = e4 >> 5, col4 = e4 & 31;
        const float* base = &g_xBC[(size_t)(posBase + row) * CDIM + DI];
        ((float4*)sB)[e4] = ((const float4*)base)[col4];
        ((float4*)sC)[e4] = ((const float4*)(base + DS))[col4];
    }
    #pragma unroll
    for (int k = 0; k < 4; k++) {
        int e4 = tid + k * 256;
        int row = e4 >> 4, col4 = e4 & 15;
        float4 v = ((const float4*)&g_xBC[(size_t)(posBase + row) * CDIM + h * 64])[col4];
        float d = sDt[row];
        v.x *= d; v.y *= d; v.z *= d; v.w *= d;
        ((float4*)sX)[e4] = v;
    }
    __syncthreads();
    if (tid < 64) sDec[tid] = expf(sAc[63] - sAc[tid]);
    __syncthreads();

    #pragma unroll
    for (int k = 0; k < 16; k++) {
        int e = tid + k * 256;
        int l = e >> 6, s = e & 63;
        float g = 0.f;
        if (l >= s) {
            const float4* c4 = (const float4*)(sC + l * 128);
            const float4* b4 = (const float4*)(sB + s * 128);
            float dot = 0.f;
            #pragma unroll 8
            for (int n = 0; n < 32; n++) {
                float4 cv = c4[n], bv = b4[n];
                dot += cv.x * bv.x + cv.y * bv.y + cv.z * bv.z + cv.w * bv.w;
            }
            g = expf(sAc[l] - sAc[s]) * dot;
        }
        sG[e] = g;
    }
    __syncthreads();

    #pragma unroll
    for (int k = 0; k < 4; k++) {
        int e4 = tid + k * 256;
        int l = e4 >> 4, p4 = e4 & 15;
        float4 acc = make_float4(0.f, 0.f, 0.f, 0.f);
        #pragma unroll 8
        for (int s = 0; s < 64; s++) {
            float g = sG[l * 64 + s];
            float4 xv = ((const float4*)(sX + s * 64))[p4];
            acc.x += g * xv.x; acc.y += g * xv.y; acc.z += g * xv.z; acc.w += g * xv.w;
        }
        ((float4*)&g_Y[(size_t)(posBase + l) * DI + h * 64])[p4] = acc;
    }

    size_t sbase = ((size_t)((b * NC + c) * HN + h)) * (64 * 128);
    #pragma unroll
    for (int k = 0; k < 8; k++) {
        int e4 = tid + k * 256;
        int p = e4 >> 5, n4 = e4 & 31;
        float4 acc = make_float4(0.f, 0.f, 0.f, 0.f);
        #pragma unroll 8
        for (int s = 0; s < 64; s++) {
            float xd = sX[s * 64 + p] * sDec[s];
            float4 bv = ((const float4*)(sB + s * 128))[n4];
            acc.x += xd * bv.x; acc.y += xd * bv.y; acc.z += xd * bv.z; acc.w += xd * bv.w;
        }
        ((float4*)&g_states[sbase])[e4] = acc;
    }
    if (tid == 0) g_asum[(b * HN + h) * NC + c] = sAc[63];
}

// ---------------- K5: inter-chunk prefix scan of states ----------------
__global__ void __launch_bounds__(256) k_scan() {
    int bh = blockIdx.x;
    int b = bh >> 5, h = bh & 31;
    int tid = threadIdx.x;
    float S[32];
    #pragma unroll
    for (int j = 0; j < 32; j++) S[j] = 0.f;
    for (int c = 0; c < NC; c++) {
        size_t base = ((size_t)((b * NC + c) * HN + h)) * 8192;
        float dec = expf(g_asum[(b * HN + h) * NC + c]);
        #pragma unroll
        for (int j = 0; j < 32; j++) {
            int e = tid + j * 256;
            g_sin[base + e] = S[j];
            S[j] = S[j] * dec + g_states[base + e];
        }
    }
}

// ---------------- K6: Yo from prefix state; Y += Yo + xs*D ----------------
#define SMEM_K6 ((8192 + 8192) * 4)  // 64 KB
__global__ void __launch_bounds__(256) k_inter(const float* __restrict__ A_log,
                                               const float* __restrict__ Dp) {
    extern __shared__ float sm[];
    float* sC = sm;            // [64][128]
    float* sS = sm + 8192;     // [64][128] prefix state (p, n)
    __shared__ float sDt[64], sAc[64];

    int bid = blockIdx.x;
    int h = bid & 31, c = (bid >> 5) & 31, b = bid >> 10;
    int tid = threadIdx.x;
    float Aval = -expf(A_log[h]);
    float Dv = Dp[h];
    int posBase = b * Lq + c * 64;

    if (tid < 64) sDt[tid] = g_dt[(posBase + tid) * HN + h];
    __syncthreads();
    if (tid == 0) {
        float acc = 0.f;
        for (int s = 0; s < 64; s++) { acc += sDt[s] * Aval; sAc[s] = acc; }
    }
    size_t sbase = ((size_t)((b * NC + c) * HN + h)) * 8192;
    #pragma unroll
    for (int k = 0; k < 8; k++) {
        int e4 = tid + k * 256;
        int row = e4 >> 5, col4 = e4 & 31;
        ((float4*)sC)[e4] =
            ((const float4*)&g_xBC[(size_t)(posBase + row) * CDIM + DI + DS])[col4];
        ((float4*)sS)[e4] = ((const float4*)&g_sin[sbase])[e4];
    }
    __syncthreads();

    #pragma unroll
    for (int k = 0; k < 16; k++) {
        int e = tid + k * 256;
        int l = e >> 6, p = e & 63;
        const float4* c4 = (const float4*)(sC + l * 128);
        const float4* s4 = (const float4*)(sS + p * 128);
        float dot = 0.f;
        #pragma unroll 8
        for (int n = 0; n < 32; n++) {
            float4 cv = c4[n], sv = s4[n];
            dot += cv.x * sv.x + cv.y * sv.y + cv.z * sv.z + cv.w * sv.w;
        }
        float yo = expf(sAc[l]) * dot;
        size_t yi = (size_t)(posBase + l) * DI + h * 64 + p;
        float xs = g_xBC[(size_t)(posBase + l) * CDIM + h * 64 + p];
        g_Y[yi] += yo + xs * Dv;
    }
}

// ---------------- K7: gated rmsnorm -> g_yn (tf32-rounded) ----------------
__global__ void __launch_bounds__(256) k_gate(const float* __restrict__ w) {
    __shared__ float sv[DI];
    int row = blockIdx.x;
    int tid = threadIdx.x;
    float s = 0.f;
    for (int i = tid; i < DI; i += 256) {
        float z = g_zx[(size_t)row * PROJ + i];
        float y = g_Y[(size_t)row * DI + i];
        float v = y * z / (1.f + expf(-z));
        sv[i] = v;
        s += v * v;
    }
    float tot = block_sum(s);
    float inv = rsqrtf(tot / DI + 1e-5f);
    for (int i = tid; i < DI; i += 256)
        g_yn[(size_t)row * DI + i] = f2tf(sv[i] * inv * w[i]);
}

// ---------------- launcher ----------------
extern "C" void kernel_launch(void* const* d_in, const int* in_sizes, int n_in,
                              void* d_out, int out_size) {
    const float* x       = (const float*)d_in[0];
    const float* norm_w  = (const float*)d_in[1];
    const float* in_W    = (const float*)d_in[2];
    const float* conv_w  = (const float*)d_in[3];
    const float* conv_b  = (const float*)d_in[4];
    const float* dt_bias = (const float*)d_in[5];
    const float* A_log   = (const float*)d_in[6];
    const float* Dp      = (const float*)d_in[7];
    const float* ni_w    = (const float*)d_in[8];
    const float* out_W   = (const float*)d_in[9];
    float* out = (float*)d_out;

    cudaFuncSetAttribute(k_gemm1, cudaFuncAttributeMaxDynamicSharedMemorySize, SMEM_GEMM);
    cudaFuncSetAttribute(k_gemm2, cudaFuncAttributeMaxDynamicSharedMemorySize, SMEM_GEMM);
    cudaFuncSetAttribute(k_chunk, cudaFuncAttributeMaxDynamicSharedMemorySize, SMEM_K4);
    cudaFuncSetAttribute(k_inter, cudaFuncAttributeMaxDynamicSharedMemorySize, SMEM_K6);

    float* d_Win;  cudaGetSymbolAddress((void**)&d_Win, g_Win);
    float* d_Wout; cudaGetSymbolAddress((void**)&d_Wout, g_Wout);

    k_cvt<<<(PROJ * DM / 4 + 255) / 256, 256>>>(in_W, d_Win, PROJ * DM / 4);
    k_cvt<<<(DM * DI / 4 + 255) / 256, 256>>>(out_W, d_Wout, DM * DI / 4);
    k_rmsnorm<<<BL, 256>>>(x, norm_w);
    k_gemm1<<<dim3((PROJ + 127) / 128, BL / 256), 256, SMEM_GEMM>>>();
    k_conv<<<(BL * CDIM + 255) / 256, 256>>>(conv_w, conv_b);
    k_dt<<<(BL * HN + 255) / 256, 256>>>(dt_bias);
    k_chunk<<<Bq * NC * HN, 256, SMEM_K4>>>(A_log);
    k_scan<<<Bq * HN, 256>>>();
    k_inter<<<Bq * NC * HN, 256, SMEM_K6>>>(A_log, Dp);
    k_gate<<<BL, 256>>>(ni_w);
    k_gemm2<<<dim3(DM / 128, BL / 256), 256, SMEM_GEMM>>>(x, out);
}

// round 4
// speedup vs baseline: 4.1910x; 2.8370x over previous
#include <cuda_runtime.h>
#include <math.h>
#include <stdint.h>

#define Bq 4
#define Lq 2048
#define DM 1024
#define DI 2048
#define HN 32
#define HD 64
#define DS 128
#define CDIM 2304
#define PROJ 4384
#define CH 64
#define NC 32
#define BL 8192

// ---------------- scratch (device globals; no allocations) ----------------
__device__ float g_xn[BL * DM];                 // rmsnorm(x), tf32-rounded
__device__ float g_zx[(size_t)BL * PROJ];       // zxbcdt
__device__ float g_xBC[(size_t)BL * CDIM];      // conv+silu output
__device__ float g_dt[BL * HN];                 // softplus dt
__device__ float g_Y[(size_t)BL * DI];          // SSD output (Yd then +=Yo)
__device__ float g_states[(size_t)Bq * NC * HN * HD * DS];
__device__ float g_sin[(size_t)Bq * NC * HN * HD * DS];
__device__ float g_asum[Bq * HN * NC];
__device__ float g_yn[(size_t)BL * DI];         // gated+normed Y, tf32-rounded
__device__ float g_Win[(size_t)PROJ * DM];      // tf32-rounded in_proj_W
__device__ float g_Wout[(size_t)DM * DI];       // tf32-rounded out_proj_W

// ---------------- helpers ----------------
__device__ __forceinline__ float block_sum(float v) {
    __shared__ float red[8];
    #pragma unroll
    for (int o = 16; o; o >>= 1) v += __shfl_down_sync(0xffffffffu, v, o);
    if ((threadIdx.x & 31) == 0) red[threadIdx.x >> 5] = v;
    __syncthreads();
    if (threadIdx.x < 32) {
        v = (threadIdx.x < 8) ? red[threadIdx.x] : 0.f;
        #pragma unroll
        for (int o = 4; o; o >>= 1) v += __shfl_down_sync(0xffffffffu, v, o);
        if (threadIdx.x == 0) red[0] = v;
    }
    __syncthreads();
    return red[0];
}

__device__ __forceinline__ float f2tf(float x) {
    uint32_t u;
    asm("cvt.rna.tf32.f32 %0, %1;" : "=r"(u) : "f"(x));
    return __uint_as_float(u);
}

__device__ __forceinline__ void mma_tf32(float c[4], const uint32_t a[4], const uint32_t b[2]) {
    asm volatile(
        "mma.sync.aligned.m16n8k8.row.col.f32.tf32.tf32.f32 "
        "{%0,%1,%2,%3}, {%4,%5,%6,%7}, {%8,%9}, {%0,%1,%2,%3};"
        : "+f"(c[0]), "+f"(c[1]), "+f"(c[2]), "+f"(c[3])
        : "r"(a[0]), "r"(a[1]), "r"(a[2]), "r"(a[3]), "r"(b[0]), "r"(b[1]));
}

// ---------------- K0: tf32-round weights into scratch ----------------
__global__ void __launch_bounds__(256) k_cvt(const float* __restrict__ src,
                                             float* __restrict__ dst, int n4) {
    int i = blockIdx.x * 256 + threadIdx.x;
    if (i >= n4) return;
    float4 v = ((const float4*)src)[i];
    v.x = f2tf(v.x); v.y = f2tf(v.y); v.z = f2tf(v.z); v.w = f2tf(v.w);
    ((float4*)dst)[i] = v;
}

// ---------------- K1: rmsnorm(x) -> g_xn (tf32-rounded) ----------------
__global__ void __launch_bounds__(256) k_rmsnorm(const float* __restrict__ x,
                                                 const float* __restrict__ w) {
    int row = blockIdx.x;
    const float* xr = x + (size_t)row * DM;
    float s = 0.f;
    for (int i = threadIdx.x; i < DM; i += 256) { float v = xr[i]; s += v * v; }
    float tot = block_sum(s);
    float inv = rsqrtf(tot / DM + 1e-5f);
    for (int i = threadIdx.x; i < DM; i += 256)
        g_xn[(size_t)row * DM + i] = f2tf(xr[i] * inv * w[i]);
}

// ---------------- TF32 pipelined GEMM: C[M,N] = A[M,K]*B[N,K]^T (+Res) -----
#define SA_FLOATS (256 * 36)
#define SB_FLOATS (128 * 36)
#define STAGE_FLOATS (SA_FLOATS + SB_FLOATS)
#define SMEM_GEMM (STAGE_FLOATS * 2 * 4)

__device__ __forceinline__ void stage_copy(const float* __restrict__ A,
                                           const float* __restrict__ Bw,
                                           float* sA, float* sB,
                                           int bm, int bn, int Nn, int K,
                                           int k0, int tid) {
    #pragma unroll
    for (int i = 0; i < 8; i++) {
        int c = tid + 256 * i;
        int row = c >> 3, col4 = (c & 7) * 4;
        uint32_t d = (uint32_t)__cvta_generic_to_shared(sA + row * 36 + col4);
        const float* g = A + (size_t)(bm + row) * K + k0 + col4;
        asm volatile("cp.async.cg.shared.global [%0], [%1], 16;" :: "r"(d), "l"(g));
    }
    #pragma unroll
    for (int i = 0; i < 4; i++) {
        int c = tid + 256 * i;
        int row = c >> 3, col4 = (c & 7) * 4;
        uint32_t d = (uint32_t)__cvta_generic_to_shared(sB + row * 36 + col4);
        int n = bn + row;
        int ok = (n < Nn);
        const float* g = Bw + (size_t)(ok ? n : 0) * K + k0 + col4;
        int sz = ok ? 16 : 0;
        asm volatile("cp.async.cg.shared.global [%0], [%1], 16, %2;" :: "r"(d), "l"(g), "r"(sz));
    }
}

__device__ __forceinline__ void stage_compute(const float* sA, const float* sB,
                                              float acc[4][8][4],
                                              int wm, int wn, int g, int t) {
    #pragma unroll
    for (int kk = 0; kk < 4; kk++) {
        int k = kk * 8;
        uint32_t af[4][4];
        #pragma unroll
        for (int im = 0; im < 4; im++) {
            int r0 = wm + im * 16 + g;
            af[im][0] = __float_as_uint(sA[r0 * 36 + k + t]);
            af[im][1] = __float_as_uint(sA[(r0 + 8) * 36 + k + t]);
            af[im][2] = __float_as_uint(sA[r0 * 36 + k + t + 4]);
            af[im][3] = __float_as_uint(sA[(r0 + 8) * 36 + k + t + 4]);
        }
        uint32_t bf[8][2];
        #pragma unroll
        for (int in = 0; in < 8; in++) {
            int n0 = wn + in * 8 + g;
            bf[in][0] = __float_as_uint(sB[n0 * 36 + k + t]);
            bf[in][1] = __float_as_uint(sB[n0 * 36 + k + t + 4]);
        }
        #pragma unroll
        for (int im = 0; im < 4; im++)
            #pragma unroll
            for (int in = 0; in < 8; in++)
                mma_tf32(acc[im][in], af[im], bf[in]);
    }
}

__device__ __forceinline__ void gemm_tf32_body(const float* __restrict__ A,
                                               const float* __restrict__ Bw,
                                               const float* __restrict__ Res,
                                               float* __restrict__ C,
                                               int M, int Nn, int K) {
    extern __shared__ float smp[];
    float* sAb[2] = { smp, smp + STAGE_FLOATS };
    float* sBb[2] = { smp + SA_FLOATS, smp + STAGE_FLOATS + SA_FLOATS };
    int bm = blockIdx.y * 256, bn = blockIdx.x * 128;
    int tid = threadIdx.x;
    int w = tid >> 5, lane = tid & 31, g = lane >> 2, t = lane & 3;
    int wm = (w & 3) * 64, wn = (w >> 2) * 64;

    float acc[4][8][4] = {};

    stage_copy(A, Bw, sAb[0], sBb[0], bm, bn, Nn, K, 0, tid);
    asm volatile("cp.async.commit_group;");

    int nk = K / 32;
    for (int kt = 0; kt < nk; kt++) {
        int cur = kt & 1;
        if (kt + 1 < nk) {
            stage_copy(A, Bw, sAb[cur ^ 1], sBb[cur ^ 1], bm, bn, Nn, K, (kt + 1) * 32, tid);
            asm volatile("cp.async.commit_group;");
            asm volatile("cp.async.wait_group 1;");
        } else {
            asm volatile("cp.async.wait_group 0;");
        }
        __syncthreads();
        stage_compute(sAb[cur], sBb[cur], acc, wm, wn, g, t);
        __syncthreads();
    }

    #pragma unroll
    for (int im = 0; im < 4; im++) {
        int row = bm + wm + im * 16 + g;
        #pragma unroll
        for (int in = 0; in < 8; in++) {
            int col = bn + wn + in * 8 + 2 * t;
            if (col < Nn) {
                size_t o0 = (size_t)row * Nn + col;
                size_t o1 = (size_t)(row + 8) * Nn + col;
                float v0 = acc[im][in][0], v1 = acc[im][in][1];
                float v2 = acc[im][in][2], v3 = acc[im][in][3];
                if (Res) {
                    v0 += Res[o0]; v1 += Res[o0 + 1];
                    v2 += Res[o1]; v3 += Res[o1 + 1];
                }
                C[o0] = v0; C[o0 + 1] = v1;
                C[o1] = v2; C[o1 + 1] = v3;
            }
        }
    }
}

__global__ void __launch_bounds__(256) k_gemm1() {
    gemm_tf32_body(g_xn, g_Win, nullptr, g_zx, BL, PROJ, DM);
}
__global__ void __launch_bounds__(256) k_gemm2(const float* __restrict__ x,
                                               float* __restrict__ out) {
    gemm_tf32_body(g_yn, g_Wout, x, out, BL, DM, DI);
}

// ---------------- K3: causal depthwise conv (w=4) + silu -> g_xBC ----------
__global__ void __launch_bounds__(256) k_conv(const float* __restrict__ cw,
                                              const float* __restrict__ cb) {
    int idx = blockIdx.x * 256 + threadIdx.x;
    if (idx >= BL * CDIM) return;
    int ch = idx % CDIM;
    int bl = idx / CDIM;
    int l = bl % Lq;
    float acc = cb[ch];
    #pragma unroll
    for (int k = 0; k < 4; k++) {
        int ls = l - 3 + k;
        if (ls >= 0)
            acc += g_zx[(size_t)(bl - l + ls) * PROJ + DI + ch] * cw[k * CDIM + ch];
    }
    acc = acc / (1.f + expf(-acc));
    g_xBC[(size_t)bl * CDIM + ch] = acc;
}

// ---------------- K3b: dt = softplus(raw + bias) ----------------
__global__ void __launch_bounds__(256) k_dt(const float* __restrict__ dt_bias) {
    int idx = blockIdx.x * 256 + threadIdx.x;
    if (idx >= BL * HN) return;
    int h = idx & 31;
    float v = g_zx[(size_t)(idx >> 5) * PROJ + DI + CDIM + h] + dt_bias[h];
    g_dt[idx] = (v > 20.f) ? v : log1pf(expf(v));
}

// ---------------- K4: intra-chunk via TF32 mma ----------------
// smem float offsets (strides padded: 132 for 128-wide, 68 for 64-wide)
#define SBSTR 132
#define SXSTR 68
#define OFF_C  0
#define OFF_B  8448
#define OFF_XT 16896
#define OFF_XD 21248
#define OFF_G  25600
#define OFF_BT 29952
#define SMEM_K4 ((29952 + 128 * 68) * 4)   // 154624 bytes

__global__ void __launch_bounds__(256) k_chunk(const float* __restrict__ A_log) {
    extern __shared__ float sm[];
    float* sC  = sm + OFF_C;    // [64][132] C (tf32)
    float* sB  = sm + OFF_B;    // [64][132] B (tf32)
    float* sXT = sm + OFF_XT;   // [64p][68s] X^T (tf32)
    float* sXD = sm + OFF_XD;   // [64p][68s] (X*dec)^T (tf32)
    float* sG  = sm + OFF_G;    // [64l][68s] masked decay*G (tf32)
    float* sBT = sm + OFF_BT;   // [128n][68s] B^T (tf32)
    __shared__ float sDt[64], sAc[64], sDec[64];

    int bid = blockIdx.x;
    int h = bid & 31, c = (bid >> 5) & 31, b = bid >> 10;
    int tid = threadIdx.x;
    int w = tid >> 5, lane = tid & 31, gq = lane >> 2, tq = lane & 3;
    float Aval = -expf(A_log[h]);
    int posBase = b * Lq + c * 64;

    // fill B, C (tf32-rounded) + dt
    if (tid < 64) sDt[tid] = g_dt[(posBase + tid) * HN + h];
    #pragma unroll
    for (int k = 0; k < 8; k++) {
        int e4 = tid + k * 256;              // 2048
        int row = e4 >> 5, col = (e4 & 31) * 4;
        const float* base = &g_xBC[(size_t)(posBase + row) * CDIM + DI];
        float4 bv = *(const float4*)(base + col);
        float4 cv = *(const float4*)(base + DS + col);
        bv.x = f2tf(bv.x); bv.y = f2tf(bv.y); bv.z = f2tf(bv.z); bv.w = f2tf(bv.w);
        cv.x = f2tf(cv.x); cv.y = f2tf(cv.y); cv.z = f2tf(cv.z); cv.w = f2tf(cv.w);
        *(float4*)(sB + row * SBSTR + col) = bv;
        *(float4*)(sC + row * SBSTR + col) = cv;
    }
    __syncthreads();
    // cumsum + BT build
    if (tid == 0) {
        float acc = 0.f;
        for (int s = 0; s < 64; s++) { acc += sDt[s] * Aval; sAc[s] = acc; }
    }
    #pragma unroll
    for (int k = 0; k < 32; k++) {
        int e = tid + k * 256;               // 8192
        int n = e & 127, s = e >> 7;
        sBT[n * SXSTR + s] = sB[s * SBSTR + n];
    }
    __syncthreads();
    if (tid < 64) sDec[tid] = expf(sAc[63] - sAc[tid]);
    __syncthreads();
    // fill XT, XD
    #pragma unroll
    for (int k = 0; k < 16; k++) {
        int e = tid + k * 256;               // 4096
        int p = e & 63, s = e >> 6;
        float xv = g_xBC[(size_t)(posBase + s) * CDIM + h * 64 + p] * sDt[s];
        sXT[p * SXSTR + s] = f2tf(xv);
        sXD[p * SXSTR + s] = f2tf(xv * sDec[s]);
    }
    __syncthreads();

    // --- G = C * B^T (M=64 l, N=64 s, K=128 n), warp tile 16x32 ---
    {
        int wm = (w >> 1) * 16, wn = (w & 1) * 32;
        float acc[4][4] = {};
        #pragma unroll
        for (int kk = 0; kk < 16; kk++) {
            int k = kk * 8;
            uint32_t af[4];
            int r0 = wm + gq;
            af[0] = __float_as_uint(sC[r0 * SBSTR + k + tq]);
            af[1] = __float_as_uint(sC[(r0 + 8) * SBSTR + k + tq]);
            af[2] = __float_as_uint(sC[r0 * SBSTR + k + tq + 4]);
            af[3] = __float_as_uint(sC[(r0 + 8) * SBSTR + k + tq + 4]);
            #pragma unroll
            for (int in = 0; in < 4; in++) {
                int n0 = wn + in * 8 + gq;
                uint32_t bf[2];
                bf[0] = __float_as_uint(sB[n0 * SBSTR + k + tq]);
                bf[1] = __float_as_uint(sB[n0 * SBSTR + k + tq + 4]);
                mma_tf32(acc[in], af, bf);
            }
        }
        // mask + decay, store tf32 G
        int l0 = wm + gq, l1 = l0 + 8;
        float a0 = sAc[l0], a1 = sAc[l1];
        #pragma unroll
        for (int in = 0; in < 4; in++) {
            int s0 = wn + in * 8 + 2 * tq, s1 = s0 + 1;
            float as0 = sAc[s0], as1 = sAc[s1];
            sG[l0 * SXSTR + s0] = (l0 >= s0) ? f2tf(expf(a0 - as0) * acc[in][0]) : 0.f;
            sG[l0 * SXSTR + s1] = (l0 >= s1) ? f2tf(expf(a0 - as1) * acc[in][1]) : 0.f;
            sG[l1 * SXSTR + s0] = (l1 >= s0) ? f2tf(expf(a1 - as0) * acc[in][2]) : 0.f;
            sG[l1 * SXSTR + s1] = (l1 >= s1) ? f2tf(expf(a1 - as1) * acc[in][3]) : 0.f;
        }
    }
    __syncthreads();

    // --- Yd = G * X (M=64 l, N=64 p, K=64 s) ---
    {
        int wm = (w >> 1) * 16, wn = (w & 1) * 32;
        float acc[4][4] = {};
        #pragma unroll
        for (int kk = 0; kk < 8; kk++) {
            int k = kk * 8;
            uint32_t af[4];
            int r0 = wm + gq;
            af[0] = __float_as_uint(sG[r0 * SXSTR + k + tq]);
            af[1] = __float_as_uint(sG[(r0 + 8) * SXSTR + k + tq]);
            af[2] = __float_as_uint(sG[r0 * SXSTR + k + tq + 4]);
            af[3] = __float_as_uint(sG[(r0 + 8) * SXSTR + k + tq + 4]);
            #pragma unroll
            for (int in = 0; in < 4; in++) {
                int n0 = wn + in * 8 + gq;
                uint32_t bf[2];
                bf[0] = __float_as_uint(sXT[n0 * SXSTR + k + tq]);
                bf[1] = __float_as_uint(sXT[n0 * SXSTR + k + tq + 4]);
                mma_tf32(acc[in], af, bf);
            }
        }
        int l0 = wm + gq, l1 = l0 + 8;
        float* y0 = &g_Y[(size_t)(posBase + l0) * DI + h * 64];
        float* y1 = &g_Y[(size_t)(posBase + l1) * DI + h * 64];
        #pragma unroll
        for (int in = 0; in < 4; in++) {
            int p0 = wn + in * 8 + 2 * tq;
            y0[p0] = acc[in][0]; y0[p0 + 1] = acc[in][1];
            y1[p0] = acc[in][2]; y1[p0 + 1] = acc[in][3];
        }
    }

    // --- states = XD^T-form: st[p][n] = sum_s XD[p][s] * BT[n][s] ---
    {
        int wm = (w >> 1) * 16, wn = (w & 1) * 64;
        float acc[8][4] = {};
        #pragma unroll
        for (int kk = 0; kk < 8; kk++) {
            int k = kk * 8;
            uint32_t af[4];
            int r0 = wm + gq;
            af[0] = __float_as_uint(sXD[r0 * SXSTR + k + tq]);
            af[1] = __float_as_uint(sXD[(r0 + 8) * SXSTR + k + tq]);
            af[2] = __float_as_uint(sXD[r0 * SXSTR + k + tq + 4]);
            af[3] = __float_as_uint(sXD[(r0 + 8) * SXSTR + k + tq + 4]);
            #pragma unroll
            for (int in = 0; in < 8; in++) {
                int n0 = wn + in * 8 + gq;
                uint32_t bf[2];
                bf[0] = __float_as_uint(sBT[n0 * SXSTR + k + tq]);
                bf[1] = __float_as_uint(sBT[n0 * SXSTR + k + tq + 4]);
                mma_tf32(acc[in], af, bf);
            }
        }
        size_t sbase = ((size_t)((b * NC + c) * HN + h)) * (64 * 128);
        int p0 = wm + gq, p1 = p0 + 8;
        #pragma unroll
        for (int in = 0; in < 8; in++) {
            int n0 = wn + in * 8 + 2 * tq;
            g_states[sbase + (size_t)p0 * 128 + n0]     = acc[in][0];
            g_states[sbase + (size_t)p0 * 128 + n0 + 1] = acc[in][1];
            g_states[sbase + (size_t)p1 * 128 + n0]     = acc[in][2];
            g_states[sbase + (size_t)p1 * 128 + n0 + 1] = acc[in][3];
        }
    }
    if (tid == 0) g_asum[(b * HN + h) * NC + c] = sAc[63];
}

// ---------------- K5: inter-chunk prefix scan of states (float4) ----------
__global__ void __launch_bounds__(256) k_scan() {
    int bh = blockIdx.x;
    int b = bh >> 5, h = bh & 31;
    int tid = threadIdx.x;
    float4 S[8];
    #pragma unroll
    for (int j = 0; j < 8; j++) S[j] = make_float4(0.f, 0.f, 0.f, 0.f);
    for (int c = 0; c < NC; c++) {
        size_t base4 = ((size_t)((b * NC + c) * HN + h)) * 2048;
        float dec = expf(g_asum[(b * HN + h) * NC + c]);
        #pragma unroll
        for (int j = 0; j < 8; j++) {
            int e = tid + j * 256;
            ((float4*)g_sin)[base4 + e] = S[j];
            float4 st = ((const float4*)g_states)[base4 + e];
            S[j].x = S[j].x * dec + st.x;
            S[j].y = S[j].y * dec + st.y;
            S[j].z = S[j].z * dec + st.z;
            S[j].w = S[j].w * dec + st.w;
        }
    }
}

// ---------------- K6: Yo = exp(Ac) * C * S^T via mma; Y += Yo + xs*D -------
#define SMEM_K6 (8448 * 2 * 4)   // 67584 bytes
__global__ void __launch_bounds__(256) k_inter(const float* __restrict__ A_log,
                                               const float* __restrict__ Dp) {
    extern __shared__ float sm[];
    float* sC = sm;            // [64l][132n] (tf32)
    float* sS = sm + 8448;     // [64p][132n] (tf32)
    __shared__ float sDt[64], sAc[64];

    int bid = blockIdx.x;
    int h = bid & 31, c = (bid >> 5) & 31, b = bid >> 10;
    int tid = threadIdx.x;
    int w = tid >> 5, lane = tid & 31, gq = lane >> 2, tq = lane & 3;
    float Aval = -expf(A_log[h]);
    float Dv = Dp[h];
    int posBase = b * Lq + c * 64;

    if (tid < 64) sDt[tid] = g_dt[(posBase + tid) * HN + h];
    size_t sbase = ((size_t)((b * NC + c) * HN + h)) * 8192;
    #pragma unroll
    for (int k = 0; k < 8; k++) {
        int e4 = tid + k * 256;
        int row = e4 >> 5, col = (e4 & 31) * 4;
        float4 cv = *(const float4*)&g_xBC[(size_t)(posBase + row) * CDIM + DI + DS + col];
        float4 sv = *(const float4*)&g_sin[sbase + (size_t)row * 128 + col];
        cv.x = f2tf(cv.x); cv.y = f2tf(cv.y); cv.z = f2tf(cv.z); cv.w = f2tf(cv.w);
        sv.x = f2tf(sv.x); sv.y = f2tf(sv.y); sv.z = f2tf(sv.z); sv.w = f2tf(sv.w);
        *(float4*)(sC + row * SBSTR + col) = cv;
        *(float4*)(sS + row * SBSTR + col) = sv;
    }
    __syncthreads();
    if (tid == 0) {
        float acc = 0.f;
        for (int s = 0; s < 64; s++) { acc += sDt[s] * Aval; sAc[s] = acc; }
    }
    __syncthreads();

    // Yo[l][p] = sum_n C[l][n] * S[p][n]  (M=64, N=64, K=128)
    int wm = (w >> 1) * 16, wn = (w & 1) * 32;
    float acc[4][4] = {};
    #pragma unroll
    for (int kk = 0; kk < 16; kk++) {
        int k = kk * 8;
        uint32_t af[4];
        int r0 = wm + gq;
        af[0] = __float_as_uint(sC[r0 * SBSTR + k + tq]);
        af[1] = __float_as_uint(sC[(r0 + 8) * SBSTR + k + tq]);
        af[2] = __float_as_uint(sC[r0 * SBSTR + k + tq + 4]);
        af[3] = __float_as_uint(sC[(r0 + 8) * SBSTR + k + tq + 4]);
        #pragma unroll
        for (int in = 0; in < 4; in++) {
            int n0 = wn + in * 8 + gq;
            uint32_t bf[2];
            bf[0] = __float_as_uint(sS[n0 * SBSTR + k + tq]);
            bf[1] = __float_as_uint(sS[n0 * SBSTR + k + tq + 4]);
            mma_tf32(acc[in], af, bf);
        }
    }
    int l0 = wm + gq, l1 = l0 + 8;
    float e0 = expf(sAc[l0]), e1 = expf(sAc[l1]);
    float* y0 = &g_Y[(size_t)(posBase + l0) * DI + h * 64];
    float* y1 = &g_Y[(size_t)(posBase + l1) * DI + h * 64];
    const float* x0 = &g_xBC[(size_t)(posBase + l0) * CDIM + h * 64];
    const float* x1 = &g_xBC[(size_t)(posBase + l1) * CDIM + h * 64];
    #pragma unroll
    for (int in = 0; in < 4; in++) {
        int p0 = wn + in * 8 + 2 * tq;
        y0[p0]     += e0 * acc[in][0] + x0[p0] * Dv;
        y0[p0 + 1] += e0 * acc[in][1] + x0[p0 + 1] * Dv;
        y1[p0]     += e1 * acc[in][2] + x1[p0] * Dv;
        y1[p0 + 1] += e1 * acc[in][3] + x1[p0 + 1] * Dv;
    }
}

// ---------------- K7: gated rmsnorm -> g_yn (tf32-rounded) ----------------
__global__ void __launch_bounds__(256) k_gate(const float* __restrict__ w) {
    __shared__ float sv[DI];
    int row = blockIdx.x;
    int tid = threadIdx.x;
    float s = 0.f;
    for (int i = tid; i < DI; i += 256) {
        float z = g_zx[(size_t)row * PROJ + i];
        float y = g_Y[(size_t)row * DI + i];
        float v = y * z / (1.f + expf(-z));
        sv[i] = v;
        s += v * v;
    }
    float tot = block_sum(s);
    float inv = rsqrtf(tot / DI + 1e-5f);
    for (int i = tid; i < DI; i += 256)
        g_yn[(size_t)row * DI + i] = f2tf(sv[i] * inv * w[i]);
}

// ---------------- launcher ----------------
extern "C" void kernel_launch(void* const* d_in, const int* in_sizes, int n_in,
                              void* d_out, int out_size) {
    const float* x       = (const float*)d_in[0];
    const float* norm_w  = (const float*)d_in[1];
    const float* in_W    = (const float*)d_in[2];
    const float* conv_w  = (const float*)d_in[3];
    const float* conv_b  = (const float*)d_in[4];
    const float* dt_bias = (const float*)d_in[5];
    const float* A_log   = (const float*)d_in[6];
    const float* Dp      = (const float*)d_in[7];
    const float* ni_w    = (const float*)d_in[8];
    const float* out_W   = (const float*)d_in[9];
    float* out = (float*)d_out;

    cudaFuncSetAttribute(k_gemm1, cudaFuncAttributeMaxDynamicSharedMemorySize, SMEM_GEMM);
    cudaFuncSetAttribute(k_gemm2, cudaFuncAttributeMaxDynamicSharedMemorySize, SMEM_GEMM);
    cudaFuncSetAttribute(k_chunk, cudaFuncAttributeMaxDynamicSharedMemorySize, SMEM_K4);
    cudaFuncSetAttribute(k_inter, cudaFuncAttributeMaxDynamicSharedMemorySize, SMEM_K6);

    float* d_Win;  cudaGetSymbolAddress((void**)&d_Win, g_Win);
    float* d_Wout; cudaGetSymbolAddress((void**)&d_Wout, g_Wout);

    k_cvt<<<(PROJ * DM / 4 + 255) / 256, 256>>>(in_W, d_Win, PROJ * DM / 4);
    k_cvt<<<(DM * DI / 4 + 255) / 256, 256>>>(out_W, d_Wout, DM * DI / 4);
    k_rmsnorm<<<BL, 256>>>(x, norm_w);
    k_gemm1<<<dim3((PROJ + 127) / 128, BL / 256), 256, SMEM_GEMM>>>();
    k_conv<<<(BL * CDIM + 255) / 256, 256>>>(conv_w, conv_b);
    k_dt<<<(BL * HN + 255) / 256, 256>>>(dt_bias);
    k_chunk<<<Bq * NC * HN, 256, SMEM_K4>>>(A_log);
    k_scan<<<Bq * HN, 256>>>();
    k_inter<<<Bq * NC * HN, 256, SMEM_K6>>>(A_log, Dp);
    k_gate<<<BL, 256>>>(ni_w);
    k_gemm2<<<dim3(DM / 128, BL / 256), 256, SMEM_GEMM>>>(x, out);
}

// round 5
// speedup vs baseline: 4.3533x; 1.0387x over previous
#include <cuda_runtime.h>
#include <math.h>
#include <stdint.h>

#define Bq 4
#define Lq 2048
#define DM 1024
#define DI 2048
#define HN 32
#define HD 64
#define DS 128
#define CDIM 2304
#define PROJ 4384
#define CH 64
#define NC 32
#define BL 8192

// ---------------- scratch (device globals; no allocations) ----------------
__device__ float g_xn[BL * DM];                 // rmsnorm(x), tf32-rounded
__device__ float g_zx[(size_t)BL * PROJ];       // zxbcdt
__device__ float g_xBC[(size_t)BL * CDIM];      // conv+silu output
__device__ float g_dt[BL * HN];                 // softplus dt
__device__ float g_Y[(size_t)BL * DI];          // SSD output (Yd then +=Yo)
__device__ float g_states[(size_t)Bq * NC * HN * HD * DS];
__device__ float g_sin[(size_t)Bq * NC * HN * HD * DS];
__device__ float g_asum[Bq * HN * NC];
__device__ float g_yn[(size_t)BL * DI];         // gated+normed Y, tf32-rounded
__device__ float g_Win[(size_t)PROJ * DM];      // tf32-rounded in_proj_W
__device__ float g_Wout[(size_t)DM * DI];       // tf32-rounded out_proj_W

// ---------------- helpers ----------------
__device__ __forceinline__ float block_sum(float v) {
    __shared__ float red[8];
    #pragma unroll
    for (int o = 16; o; o >>= 1) v += __shfl_down_sync(0xffffffffu, v, o);
    if ((threadIdx.x & 31) == 0) red[threadIdx.x >> 5] = v;
    __syncthreads();
    if (threadIdx.x < 32) {
        v = (threadIdx.x < 8) ? red[threadIdx.x] : 0.f;
        #pragma unroll
        for (int o = 4; o; o >>= 1) v += __shfl_down_sync(0xffffffffu, v, o);
        if (threadIdx.x == 0) red[0] = v;
    }
    __syncthreads();
    return red[0];
}

__device__ __forceinline__ float f2tf(float x) {
    uint32_t u;
    asm("cvt.rna.tf32.f32 %0, %1;" : "=r"(u) : "f"(x));
    return __uint_as_float(u);
}

__device__ __forceinline__ void mma_tf32(float c[4], const uint32_t a[4], const uint32_t b[2]) {
    asm volatile(
        "mma.sync.aligned.m16n8k8.row.col.f32.tf32.tf32.f32 "
        "{%0,%1,%2,%3}, {%4,%5,%6,%7}, {%8,%9}, {%0,%1,%2,%3};"
        : "+f"(c[0]), "+f"(c[1]), "+f"(c[2]), "+f"(c[3])
        : "r"(a[0]), "r"(a[1]), "r"(a[2]), "r"(a[3]), "r"(b[0]), "r"(b[1]));
}

// ---------------- K0: tf32-round weights into scratch ----------------
__global__ void __launch_bounds__(256) k_cvt(const float* __restrict__ src,
                                             float* __restrict__ dst, int n4) {
    int i = blockIdx.x * 256 + threadIdx.x;
    if (i >= n4) return;
    float4 v = ((const float4*)src)[i];
    v.x = f2tf(v.x); v.y = f2tf(v.y); v.z = f2tf(v.z); v.w = f2tf(v.w);
    ((float4*)dst)[i] = v;
}

// ---------------- K1: rmsnorm(x) -> g_xn (tf32-rounded) ----------------
__global__ void __launch_bounds__(256) k_rmsnorm(const float* __restrict__ x,
                                                 const float* __restrict__ w) {
    int row = blockIdx.x;
    const float* xr = x + (size_t)row * DM;
    float s = 0.f;
    for (int i = threadIdx.x; i < DM; i += 256) { float v = xr[i]; s += v * v; }
    float tot = block_sum(s);
    float inv = rsqrtf(tot / DM + 1e-5f);
    for (int i = threadIdx.x; i < DM; i += 256)
        g_xn[(size_t)row * DM + i] = f2tf(xr[i] * inv * w[i]);
}

// ---------------- TF32 pipelined GEMM: C[M,N] = A[M,K]*B[N,K]^T (+Res) -----
// CTA 256x128, k-step 32, 3-stage cp.async pipeline, ONE syncthreads/iter.
#define SA_FLOATS (256 * 36)
#define SB_FLOATS (128 * 36)
#define STAGE_FLOATS (SA_FLOATS + SB_FLOATS)
#define NSTAGE 3
#define SMEM_GEMM (STAGE_FLOATS * NSTAGE * 4)   // 165888 bytes

__device__ __forceinline__ void stage_copy(const float* __restrict__ A,
                                           const float* __restrict__ Bw,
                                           float* sA, float* sB,
                                           int bm, int bn, int Nn, int K,
                                           int k0, int tid) {
    #pragma unroll
    for (int i = 0; i < 8; i++) {
        int c = tid + 256 * i;
        int row = c >> 3, col4 = (c & 7) * 4;
        uint32_t d = (uint32_t)__cvta_generic_to_shared(sA + row * 36 + col4);
        const float* g = A + (size_t)(bm + row) * K + k0 + col4;
        asm volatile("cp.async.cg.shared.global [%0], [%1], 16;" :: "r"(d), "l"(g));
    }
    #pragma unroll
    for (int i = 0; i < 4; i++) {
        int c = tid + 256 * i;
        int row = c >> 3, col4 = (c & 7) * 4;
        uint32_t d = (uint32_t)__cvta_generic_to_shared(sB + row * 36 + col4);
        int n = bn + row;
        int ok = (n < Nn);
        const float* g = Bw + (size_t)(ok ? n : 0) * K + k0 + col4;
        int sz = ok ? 16 : 0;
        asm volatile("cp.async.cg.shared.global [%0], [%1], 16, %2;" :: "r"(d), "l"(g), "r"(sz));
    }
}

__device__ __forceinline__ void stage_compute(const float* sA, const float* sB,
                                              float acc[4][8][4],
                                              int wm, int wn, int g, int t) {
    #pragma unroll
    for (int kk = 0; kk < 4; kk++) {
        int k = kk * 8;
        uint32_t af[4][4];
        #pragma unroll
        for (int im = 0; im < 4; im++) {
            int r0 = wm + im * 16 + g;
            af[im][0] = __float_as_uint(sA[r0 * 36 + k + t]);
            af[im][1] = __float_as_uint(sA[(r0 + 8) * 36 + k + t]);
            af[im][2] = __float_as_uint(sA[r0 * 36 + k + t + 4]);
            af[im][3] = __float_as_uint(sA[(r0 + 8) * 36 + k + t + 4]);
        }
        uint32_t bf[8][2];
        #pragma unroll
        for (int in = 0; in < 8; in++) {
            int n0 = wn + in * 8 + g;
            bf[in][0] = __float_as_uint(sB[n0 * 36 + k + t]);
            bf[in][1] = __float_as_uint(sB[n0 * 36 + k + t + 4]);
        }
        #pragma unroll
        for (int im = 0; im < 4; im++)
            #pragma unroll
            for (int in = 0; in < 8; in++)
                mma_tf32(acc[im][in], af[im], bf[in]);
    }
}

__device__ __forceinline__ void gemm_tf32_body(const float* __restrict__ A,
                                               const float* __restrict__ Bw,
                                               const float* __restrict__ Res,
                                               float* __restrict__ C,
                                               int M, int Nn, int K) {
    extern __shared__ float smp[];
    int bm = blockIdx.y * 256, bn = blockIdx.x * 128;
    int tid = threadIdx.x;
    int w = tid >> 5, lane = tid & 31, g = lane >> 2, t = lane & 3;
    int wm = (w & 3) * 64, wn = (w >> 2) * 64;

    float acc[4][8][4] = {};

    // prologue: prefetch stages 0,1
    stage_copy(A, Bw, smp, smp + SA_FLOATS, bm, bn, Nn, K, 0, tid);
    asm volatile("cp.async.commit_group;");
    stage_copy(A, Bw, smp + STAGE_FLOATS, smp + STAGE_FLOATS + SA_FLOATS,
               bm, bn, Nn, K, 32, tid);
    asm volatile("cp.async.commit_group;");

    int nk = K / 32;
    for (int kt = 0; kt < nk; kt++) {
        asm volatile("cp.async.wait_group 1;");
        __syncthreads();
        if (kt + 2 < nk) {
            int s = (kt + 2) % NSTAGE;
            stage_copy(A, Bw, smp + s * STAGE_FLOATS, smp + s * STAGE_FLOATS + SA_FLOATS,
                       bm, bn, Nn, K, (kt + 2) * 32, tid);
        }
        asm volatile("cp.async.commit_group;");
        int cur = kt % NSTAGE;
        stage_compute(smp + cur * STAGE_FLOATS, smp + cur * STAGE_FLOATS + SA_FLOATS,
                      acc, wm, wn, g, t);
    }

    #pragma unroll
    for (int im = 0; im < 4; im++) {
        int row = bm + wm + im * 16 + g;
        #pragma unroll
        for (int in = 0; in < 8; in++) {
            int col = bn + wn + in * 8 + 2 * t;
            if (col < Nn) {
                size_t o0 = (size_t)row * Nn + col;
                size_t o1 = (size_t)(row + 8) * Nn + col;
                float v0 = acc[im][in][0], v1 = acc[im][in][1];
                float v2 = acc[im][in][2], v3 = acc[im][in][3];
                if (Res) {
                    v0 += Res[o0]; v1 += Res[o0 + 1];
                    v2 += Res[o1]; v3 += Res[o1 + 1];
                }
                C[o0] = v0; C[o0 + 1] = v1;
                C[o1] = v2; C[o1 + 1] = v3;
            }
        }
    }
}

__global__ void __launch_bounds__(256) k_gemm1() {
    gemm_tf32_body(g_xn, g_Win, nullptr, g_zx, BL, PROJ, DM);
}
__global__ void __launch_bounds__(256) k_gemm2(const float* __restrict__ x,
                                               float* __restrict__ out) {
    gemm_tf32_body(g_yn, g_Wout, x, out, BL, DM, DI);
}

// ---------------- K3: causal depthwise conv (w=4) + silu -> g_xBC ----------
__global__ void __launch_bounds__(256) k_conv(const float* __restrict__ cw,
                                              const float* __restrict__ cb) {
    int idx = blockIdx.x * 256 + threadIdx.x;
    if (idx >= BL * CDIM) return;
    int ch = idx % CDIM;
    int bl = idx / CDIM;
    int l = bl % Lq;
    float acc = cb[ch];
    #pragma unroll
    for (int k = 0; k < 4; k++) {
        int ls = l - 3 + k;
        if (ls >= 0)
            acc += g_zx[(size_t)(bl - l + ls) * PROJ + DI + ch] * cw[k * CDIM + ch];
    }
    acc = acc / (1.f + expf(-acc));
    g_xBC[(size_t)bl * CDIM + ch] = acc;
}

// ---------------- K3b: dt = softplus(raw + bias) ----------------
__global__ void __launch_bounds__(256) k_dt(const float* __restrict__ dt_bias) {
    int idx = blockIdx.x * 256 + threadIdx.x;
    if (idx >= BL * HN) return;
    int h = idx & 31;
    float v = g_zx[(size_t)(idx >> 5) * PROJ + DI + CDIM + h] + dt_bias[h];
    g_dt[idx] = (v > 20.f) ? v : log1pf(expf(v));
}

// ---------------- K4: intra-chunk via TF32 mma ----------------
#define SBSTR 132
#define SXSTR 68
#define OFF_C  0
#define OFF_B  8448
#define OFF_XT 16896
#define OFF_XD 21248
#define OFF_G  25600
#define OFF_BT 29952
#define SMEM_K4 ((29952 + 128 * 68) * 4)   // 154624 bytes

__global__ void __launch_bounds__(256) k_chunk(const float* __restrict__ A_log) {
    extern __shared__ float sm[];
    float* sC  = sm + OFF_C;
    float* sB  = sm + OFF_B;
    float* sXT = sm + OFF_XT;
    float* sXD = sm + OFF_XD;
    float* sG  = sm + OFF_G;
    float* sBT = sm + OFF_BT;
    __shared__ float sDt[64], sAc[64], sDec[64];

    int bid = blockIdx.x;
    int h = bid & 31, c = (bid >> 5) & 31, b = bid >> 10;
    int tid = threadIdx.x;
    int w = tid >> 5, lane = tid & 31, gq = lane >> 2, tq = lane & 3;
    float Aval = -expf(A_log[h]);
    int posBase = b * Lq + c * 64;

    if (tid < 64) sDt[tid] = g_dt[(posBase + tid) * HN + h];
    #pragma unroll
    for (int k = 0; k < 8; k++) {
        int e4 = tid + k * 256;
        int row = e4 >> 5, col = (e4 & 31) * 4;
        const float* base = &g_xBC[(size_t)(posBase + row) * CDIM + DI];
        float4 bv = *(const float4*)(base + col);
        float4 cv = *(const float4*)(base + DS + col);
        bv.x = f2tf(bv.x); bv.y = f2tf(bv.y); bv.z = f2tf(bv.z); bv.w = f2tf(bv.w);
        cv.x = f2tf(cv.x); cv.y = f2tf(cv.y); cv.z = f2tf(cv.z); cv.w = f2tf(cv.w);
        *(float4*)(sB + row * SBSTR + col) = bv;
        *(float4*)(sC + row * SBSTR + col) = cv;
    }
    __syncthreads();
    if (tid == 0) {
        float acc = 0.f;
        for (int s = 0; s < 64; s++) { acc += sDt[s] * Aval; sAc[s] = acc; }
    }
    #pragma unroll
    for (int k = 0; k < 32; k++) {
        int e = tid + k * 256;
        int n = e & 127, s = e >> 7;
        sBT[n * SXSTR + s] = sB[s * SBSTR + n];
    }
    __syncthreads();
    if (tid < 64) sDec[tid] = expf(sAc[63] - sAc[tid]);
    __syncthreads();
    #pragma unroll
    for (int k = 0; k < 16; k++) {
        int e = tid + k * 256;
        int p = e & 63, s = e >> 6;
        float xv = g_xBC[(size_t)(posBase + s) * CDIM + h * 64 + p] * sDt[s];
        sXT[p * SXSTR + s] = f2tf(xv);
        sXD[p * SXSTR + s] = f2tf(xv * sDec[s]);
    }
    __syncthreads();

    {
        int wm = (w >> 1) * 16, wn = (w & 1) * 32;
        float acc[4][4] = {};
        #pragma unroll
        for (int kk = 0; kk < 16; kk++) {
            int k = kk * 8;
            uint32_t af[4];
            int r0 = wm + gq;
            af[0] = __float_as_uint(sC[r0 * SBSTR + k + tq]);
            af[1] = __float_as_uint(sC[(r0 + 8) * SBSTR + k + tq]);
            af[2] = __float_as_uint(sC[r0 * SBSTR + k + tq + 4]);
            af[3] = __float_as_uint(sC[(r0 + 8) * SBSTR + k + tq + 4]);
            #pragma unroll
            for (int in = 0; in < 4; in++) {
                int n0 = wn + in * 8 + gq;
                uint32_t bf[2];
                bf[0] = __float_as_uint(sB[n0 * SBSTR + k + tq]);
                bf[1] = __float_as_uint(sB[n0 * SBSTR + k + tq + 4]);
                mma_tf32(acc[in], af, bf);
            }
        }
        int l0 = wm + gq, l1 = l0 + 8;
        float a0 = sAc[l0], a1 = sAc[l1];
        #pragma unroll
        for (int in = 0; in < 4; in++) {
            int s0 = wn + in * 8 + 2 * tq, s1 = s0 + 1;
            float as0 = sAc[s0], as1 = sAc[s1];
            sG[l0 * SXSTR + s0] = (l0 >= s0) ? f2tf(expf(a0 - as0) * acc[in][0]) : 0.f;
            sG[l0 * SXSTR + s1] = (l0 >= s1) ? f2tf(expf(a0 - as1) * acc[in][1]) : 0.f;
            sG[l1 * SXSTR + s0] = (l1 >= s0) ? f2tf(expf(a1 - as0) * acc[in][2]) : 0.f;
            sG[l1 * SXSTR + s1] = (l1 >= s1) ? f2tf(expf(a1 - as1) * acc[in][3]) : 0.f;
        }
    }
    __syncthreads();

    {
        int wm = (w >> 1) * 16, wn = (w & 1) * 32;
        float acc[4][4] = {};
        #pragma unroll
        for (int kk = 0; kk < 8; kk++) {
            int k = kk * 8;
            uint32_t af[4];
            int r0 = wm + gq;
            af[0] = __float_as_uint(sG[r0 * SXSTR + k + tq]);
            af[1] = __float_as_uint(sG[(r0 + 8) * SXSTR + k + tq]);
            af[2] = __float_as_uint(sG[r0 * SXSTR + k + tq + 4]);
            af[3] = __float_as_uint(sG[(r0 + 8) * SXSTR + k + tq + 4]);
            #pragma unroll
            for (int in = 0; in < 4; in++) {
                int n0 = wn + in * 8 + gq;
                uint32_t bf[2];
                bf[0] = __float_as_uint(sXT[n0 * SXSTR + k + tq]);
                bf[1] = __float_as_uint(sXT[n0 * SXSTR + k + tq + 4]);
                mma_tf32(acc[in], af, bf);
            }
        }
        int l0 = wm + gq, l1 = l0 + 8;
        float* y0 = &g_Y[(size_t)(posBase + l0) * DI + h * 64];
        float* y1 = &g_Y[(size_t)(posBase + l1) * DI + h * 64];
        #pragma unroll
        for (int in = 0; in < 4; in++) {
            int p0 = wn + in * 8 + 2 * tq;
            y0[p0] = acc[in][0]; y0[p0 + 1] = acc[in][1];
            y1[p0] = acc[in][2]; y1[p0 + 1] = acc[in][3];
        }
    }

    {
        int wm = (w >> 1) * 16, wn = (w & 1) * 64;
        float acc[8][4] = {};
        #pragma unroll
        for (int kk = 0; kk < 8; kk++) {
            int k = kk * 8;
            uint32_t af[4];
            int r0 = wm + gq;
            af[0] = __float_as_uint(sXD[r0 * SXSTR + k + tq]);
            af[1] = __float_as_uint(sXD[(r0 + 8) * SXSTR + k + tq]);
            af[2] = __float_as_uint(sXD[r0 * SXSTR + k + tq + 4]);
            af[3] = __float_as_uint(sXD[(r0 + 8) * SXSTR + k + tq + 4]);
            #pragma unroll
            for (int in = 0; in < 8; in++) {
                int n0 = wn + in * 8 + gq;
                uint32_t bf[2];
                bf[0] = __float_as_uint(sBT[n0 * SXSTR + k + tq]);
                bf[1] = __float_as_uint(sBT[n0 * SXSTR + k + tq + 4]);
                mma_tf32(acc[in], af, bf);
            }
        }
        size_t sbase = ((size_t)((b * NC + c) * HN + h)) * (64 * 128);
        int p0 = wm + gq, p1 = p0 + 8;
        #pragma unroll
        for (int in = 0; in < 8; in++) {
            int n0 = wn + in * 8 + 2 * tq;
            g_states[sbase + (size_t)p0 * 128 + n0]     = acc[in][0];
            g_states[sbase + (size_t)p0 * 128 + n0 + 1] = acc[in][1];
            g_states[sbase + (size_t)p1 * 128 + n0]     = acc[in][2];
            g_states[sbase + (size_t)p1 * 128 + n0 + 1] = acc[in][3];
        }
    }
    if (tid == 0) g_asum[(b * HN + h) * NC + c] = sAc[63];
}

// ---------------- K5: inter-chunk prefix scan of states (float4) ----------
__global__ void __launch_bounds__(256) k_scan() {
    int bh = blockIdx.x;
    int b = bh >> 5, h = bh & 31;
    int tid = threadIdx.x;
    float4 S[8];
    #pragma unroll
    for (int j = 0; j < 8; j++) S[j] = make_float4(0.f, 0.f, 0.f, 0.f);
    for (int c = 0; c < NC; c++) {
        size_t base4 = ((size_t)((b * NC + c) * HN + h)) * 2048;
        float dec = expf(g_asum[(b * HN + h) * NC + c]);
        #pragma unroll
        for (int j = 0; j < 8; j++) {
            int e = tid + j * 256;
            ((float4*)g_sin)[base4 + e] = S[j];
            float4 st = ((const float4*)g_states)[base4 + e];
            S[j].x = S[j].x * dec + st.x;
            S[j].y = S[j].y * dec + st.y;
            S[j].z = S[j].z * dec + st.z;
            S[j].w = S[j].w * dec + st.w;
        }
    }
}

// ---------------- K6: Yo = exp(Ac) * C * S^T via mma; Y += Yo + xs*D -------
#define SMEM_K6 (8448 * 2 * 4)   // 67584 bytes
__global__ void __launch_bounds__(256) k_inter(const float* __restrict__ A_log,
                                               const float* __restrict__ Dp) {
    extern __shared__ float sm[];
    float* sC = sm;
    float* sS = sm + 8448;
    __shared__ float sDt[64], sAc[64];

    int bid = blockIdx.x;
    int h = bid & 31, c = (bid >> 5) & 31, b = bid >> 10;
    int tid = threadIdx.x;
    int w = tid >> 5, lane = tid & 31, gq = lane >> 2, tq = lane & 3;
    float Aval = -expf(A_log[h]);
    float Dv = Dp[h];
    int posBase = b * Lq + c * 64;

    if (tid < 64) sDt[tid] = g_dt[(posBase + tid) * HN + h];
    size_t sbase = ((size_t)((b * NC + c) * HN + h)) * 8192;
    #pragma unroll
    for (int k = 0; k < 8; k++) {
        int e4 = tid + k * 256;
        int row = e4 >> 5, col = (e4 & 31) * 4;
        float4 cv = *(const float4*)&g_xBC[(size_t)(posBase + row) * CDIM + DI + DS + col];
        float4 sv = *(const float4*)&g_sin[sbase + (size_t)row * 128 + col];
        cv.x = f2tf(cv.x); cv.y = f2tf(cv.y); cv.z = f2tf(cv.z); cv.w = f2tf(cv.w);
        sv.x = f2tf(sv.x); sv.y = f2tf(sv.y); sv.z = f2tf(sv.z); sv.w = f2tf(sv.w);
        *(float4*)(sC + row * SBSTR + col) = cv;
        *(float4*)(sS + row * SBSTR + col) = sv;
    }
    __syncthreads();
    if (tid == 0) {
        float acc = 0.f;
        for (int s = 0; s < 64; s++) { acc += sDt[s] * Aval; sAc[s] = acc; }
    }
    __syncthreads();

    int wm = (w >> 1) * 16, wn = (w & 1) * 32;
    float acc[4][4] = {};
    #pragma unroll
    for (int kk = 0; kk < 16; kk++) {
        int k = kk * 8;
        uint32_t af[4];
        int r0 = wm + gq;
        af[0] = __float_as_uint(sC[r0 * SBSTR + k + tq]);
        af[1] = __float_as_uint(sC[(r0 + 8) * SBSTR + k + tq]);
        af[2] = __float_as_uint(sC[r0 * SBSTR + k + tq + 4]);
        af[3] = __float_as_uint(sC[(r0 + 8) * SBSTR + k + tq + 4]);
        #pragma unroll
        for (int in = 0; in < 4; in++) {
            int n0 = wn + in * 8 + gq;
            uint32_t bf[2];
            bf[0] = __float_as_uint(sS[n0 * SBSTR + k + tq]);
            bf[1] = __float_as_uint(sS[n0 * SBSTR + k + tq + 4]);
            mma_tf32(acc[in], af, bf);
        }
    }
    int l0 = wm + gq, l1 = l0 + 8;
    float e0 = expf(sAc[l0]), e1 = expf(sAc[l1]);
    float* y0 = &g_Y[(size_t)(posBase + l0) * DI + h * 64];
    float* y1 = &g_Y[(size_t)(posBase + l1) * DI + h * 64];
    const float* x0 = &g_xBC[(size_t)(posBase + l0) * CDIM + h * 64];
    const float* x1 = &g_xBC[(size_t)(posBase + l1) * CDIM + h * 64];
    #pragma unroll
    for (int in = 0; in < 4; in++) {
        int p0 = wn + in * 8 + 2 * tq;
        y0[p0]     += e0 * acc[in][0] + x0[p0] * Dv;
        y0[p0 + 1] += e0 * acc[in][1] + x0[p0 + 1] * Dv;
        y1[p0]     += e1 * acc[in][2] + x1[p0] * Dv;
        y1[p0 + 1] += e1 * acc[in][3] + x1[p0 + 1] * Dv;
    }
}

// ---------------- K7: gated rmsnorm -> g_yn (tf32-rounded) ----------------
__global__ void __launch_bounds__(256) k_gate(const float* __restrict__ w) {
    __shared__ float sv[DI];
    int row = blockIdx.x;
    int tid = threadIdx.x;
    float s = 0.f;
    for (int i = tid; i < DI; i += 256) {
        float z = g_zx[(size_t)row * PROJ + i];
        float y = g_Y[(size_t)row * DI + i];
        float v = y * z / (1.f + expf(-z));
        sv[i] = v;
        s += v * v;
    }
    float tot = block_sum(s);
    float inv = rsqrtf(tot / DI + 1e-5f);
    for (int i = tid; i < DI; i += 256)
        g_yn[(size_t)row * DI + i] = f2tf(sv[i] * inv * w[i]);
}

// ---------------- launcher ----------------
extern "C" void kernel_launch(void* const* d_in, const int* in_sizes, int n_in,
                              void* d_out, int out_size) {
    const float* x       = (const float*)d_in[0];
    const float* norm_w  = (const float*)d_in[1];
    const float* in_W    = (const float*)d_in[2];
    const float* conv_w  = (const float*)d_in[3];
    const float* conv_b  = (const float*)d_in[4];
    const float* dt_bias = (const float*)d_in[5];
    const float* A_log   = (const float*)d_in[6];
    const float* Dp      = (const float*)d_in[7];
    const float* ni_w    = (const float*)d_in[8];
    const float* out_W   = (const float*)d_in[9];
    float* out = (float*)d_out;

    cudaFuncSetAttribute(k_gemm1, cudaFuncAttributeMaxDynamicSharedMemorySize, SMEM_GEMM);
    cudaFuncSetAttribute(k_gemm2, cudaFuncAttributeMaxDynamicSharedMemorySize, SMEM_GEMM);
    cudaFuncSetAttribute(k_chunk, cudaFuncAttributeMaxDynamicSharedMemorySize, SMEM_K4);
    cudaFuncSetAttribute(k_inter, cudaFuncAttributeMaxDynamicSharedMemorySize, SMEM_K6);

    float* d_Win;  cudaGetSymbolAddress((void**)&d_Win, g_Win);
    float* d_Wout; cudaGetSymbolAddress((void**)&d_Wout, g_Wout);

    k_cvt<<<(PROJ * DM / 4 + 255) / 256, 256>>>(in_W, d_Win, PROJ * DM / 4);
    k_cvt<<<(DM * DI / 4 + 255) / 256, 256>>>(out_W, d_Wout, DM * DI / 4);
    k_rmsnorm<<<BL, 256>>>(x, norm_w);
    k_gemm1<<<dim3((PROJ + 127) / 128, BL / 256), 256, SMEM_GEMM>>>();
    k_conv<<<(BL * CDIM + 255) / 256, 256>>>(conv_w, conv_b);
    k_dt<<<(BL * HN + 255) / 256, 256>>>(dt_bias);
    k_chunk<<<Bq * NC * HN, 256, SMEM_K4>>>(A_log);
    k_scan<<<Bq * HN, 256>>>();
    k_inter<<<Bq * NC * HN, 256, SMEM_K6>>>(A_log, Dp);
    k_gate<<<BL, 256>>>(ni_w);
    k_gemm2<<<dim3(DM / 128, BL / 256), 256, SMEM_GEMM>>>(x, out);
}

// round 6
// speedup vs baseline: 4.4303x; 1.0177x over previous
#include <cuda_runtime.h>
#include <math.h>
#include <stdint.h>

#define Bq 4
#define Lq 2048
#define DM 1024
#define DI 2048
#define HN 32
#define HD 64
#define DS 128
#define CDIM 2304
#define PROJ 4384
#define CH 64
#define NC 32
#define BL 8192

// ---------------- scratch (device globals; no allocations) ----------------
__device__ float g_xn[BL * DM];                 // rmsnorm(x), tf32-rounded
__device__ float g_zx[(size_t)BL * PROJ];       // zxbcdt
__device__ float g_xBC[(size_t)BL * CDIM];      // conv+silu output
__device__ float g_dt[BL * HN];                 // softplus dt
__device__ float g_Y[(size_t)BL * DI];          // SSD output (Yd then +=Yo)
__device__ float g_states[(size_t)Bq * NC * HN * HD * DS];
__device__ float g_sin[(size_t)Bq * NC * HN * HD * DS];
__device__ float g_asum[Bq * HN * NC];
__device__ float g_yn[(size_t)BL * DI];         // gated+normed Y, tf32-rounded
__device__ float g_Win[(size_t)PROJ * DM];      // tf32-rounded in_proj_W
__device__ float g_Wout[(size_t)DM * DI];       // tf32-rounded out_proj_W

// ---------------- helpers ----------------
__device__ __forceinline__ float block_sum(float v) {
    __shared__ float red[8];
    #pragma unroll
    for (int o = 16; o; o >>= 1) v += __shfl_down_sync(0xffffffffu, v, o);
    if ((threadIdx.x & 31) == 0) red[threadIdx.x >> 5] = v;
    __syncthreads();
    if (threadIdx.x < 32) {
        v = (threadIdx.x < 8) ? red[threadIdx.x] : 0.f;
        #pragma unroll
        for (int o = 4; o; o >>= 1) v += __shfl_down_sync(0xffffffffu, v, o);
        if (threadIdx.x == 0) red[0] = v;
    }
    __syncthreads();
    return red[0];
}

__device__ __forceinline__ float f2tf(float x) {
    uint32_t u;
    asm("cvt.rna.tf32.f32 %0, %1;" : "=r"(u) : "f"(x));
    return __uint_as_float(u);
}

__device__ __forceinline__ void mma_tf32(float c[4], const uint32_t a[4], const uint32_t b[2]) {
    asm volatile(
        "mma.sync.aligned.m16n8k8.row.col.f32.tf32.tf32.f32 "
        "{%0,%1,%2,%3}, {%4,%5,%6,%7}, {%8,%9}, {%0,%1,%2,%3};"
        : "+f"(c[0]), "+f"(c[1]), "+f"(c[2]), "+f"(c[3])
        : "r"(a[0]), "r"(a[1]), "r"(a[2]), "r"(a[3]), "r"(b[0]), "r"(b[1]));
}

// ---------------- K0: tf32-round weights into scratch ----------------
__global__ void __launch_bounds__(256) k_cvt(const float* __restrict__ src,
                                             float* __restrict__ dst, int n4) {
    int i = blockIdx.x * 256 + threadIdx.x;
    if (i >= n4) return;
    float4 v = ((const float4*)src)[i];
    v.x = f2tf(v.x); v.y = f2tf(v.y); v.z = f2tf(v.z); v.w = f2tf(v.w);
    ((float4*)dst)[i] = v;
}

// ---------------- K1: rmsnorm(x) -> g_xn (tf32-rounded) ----------------
__global__ void __launch_bounds__(256) k_rmsnorm(const float* __restrict__ x,
                                                 const float* __restrict__ w) {
    int row = blockIdx.x;
    const float* xr = x + (size_t)row * DM;
    float s = 0.f;
    for (int i = threadIdx.x; i < DM; i += 256) { float v = xr[i]; s += v * v; }
    float tot = block_sum(s);
    float inv = rsqrtf(tot / DM + 1e-5f);
    for (int i = threadIdx.x; i < DM; i += 256)
        g_xn[(size_t)row * DM + i] = f2tf(xr[i] * inv * w[i]);
}

// ---------------- TF32 pipelined GEMM: C[M,N] = A[M,K]*B[N,K]^T (+Res) -----
// CTA 128x128, 4 warps (64x64 each), k-step 32, 3-stage cp.async pipeline,
// 110 KB smem -> 2 CTAs/SM for cross-CTA latency hiding.
#define SA_FLOATS (128 * 36)
#define SB_FLOATS (128 * 36)
#define STAGE_FLOATS (SA_FLOATS + SB_FLOATS)
#define NSTAGE 3
#define SMEM_GEMM (STAGE_FLOATS * NSTAGE * 4)   // 110592 bytes

__device__ __forceinline__ void stage_copy(const float* __restrict__ A,
                                           const float* __restrict__ Bw,
                                           float* sA, float* sB,
                                           int bm, int bn, int Nn, int K,
                                           int k0, int tid) {
    #pragma unroll
    for (int i = 0; i < 8; i++) {
        int c = tid + 128 * i;                 // 1024 16B chunks for A
        int row = c >> 3, col4 = (c & 7) * 4;
        uint32_t d = (uint32_t)__cvta_generic_to_shared(sA + row * 36 + col4);
        const float* g = A + (size_t)(bm + row) * K + k0 + col4;
        asm volatile("cp.async.cg.shared.global [%0], [%1], 16;" :: "r"(d), "l"(g));
    }
    #pragma unroll
    for (int i = 0; i < 8; i++) {
        int c = tid + 128 * i;                 // 1024 16B chunks for B
        int row = c >> 3, col4 = (c & 7) * 4;
        uint32_t d = (uint32_t)__cvta_generic_to_shared(sB + row * 36 + col4);
        int n = bn + row;
        int ok = (n < Nn);
        const float* g = Bw + (size_t)(ok ? n : 0) * K + k0 + col4;
        int sz = ok ? 16 : 0;
        asm volatile("cp.async.cg.shared.global [%0], [%1], 16, %2;" :: "r"(d), "l"(g), "r"(sz));
    }
}

__device__ __forceinline__ void stage_compute(const float* sA, const float* sB,
                                              float acc[4][8][4],
                                              int wm, int wn, int g, int t) {
    #pragma unroll
    for (int kk = 0; kk < 4; kk++) {
        int k = kk * 8;
        uint32_t af[4][4];
        #pragma unroll
        for (int im = 0; im < 4; im++) {
            int r0 = wm + im * 16 + g;
            af[im][0] = __float_as_uint(sA[r0 * 36 + k + t]);
            af[im][1] = __float_as_uint(sA[(r0 + 8) * 36 + k + t]);
            af[im][2] = __float_as_uint(sA[r0 * 36 + k + t + 4]);
            af[im][3] = __float_as_uint(sA[(r0 + 8) * 36 + k + t + 4]);
        }
        uint32_t bf[8][2];
        #pragma unroll
        for (int in = 0; in < 8; in++) {
            int n0 = wn + in * 8 + g;
            bf[in][0] = __float_as_uint(sB[n0 * 36 + k + t]);
            bf[in][1] = __float_as_uint(sB[n0 * 36 + k + t + 4]);
        }
        #pragma unroll
        for (int im = 0; im < 4; im++)
            #pragma unroll
            for (int in = 0; in < 8; in++)
                mma_tf32(acc[im][in], af[im], bf[in]);
    }
}

__device__ __forceinline__ void gemm_tf32_body(const float* __restrict__ A,
                                               const float* __restrict__ Bw,
                                               const float* __restrict__ Res,
                                               float* __restrict__ C,
                                               int M, int Nn, int K) {
    extern __shared__ float smp[];
    int bm = blockIdx.y * 128, bn = blockIdx.x * 128;
    int tid = threadIdx.x;
    int w = tid >> 5, lane = tid & 31, g = lane >> 2, t = lane & 3;
    int wm = (w >> 1) * 64, wn = (w & 1) * 64;

    float acc[4][8][4] = {};

    stage_copy(A, Bw, smp, smp + SA_FLOATS, bm, bn, Nn, K, 0, tid);
    asm volatile("cp.async.commit_group;");
    stage_copy(A, Bw, smp + STAGE_FLOATS, smp + STAGE_FLOATS + SA_FLOATS,
               bm, bn, Nn, K, 32, tid);
    asm volatile("cp.async.commit_group;");

    int nk = K / 32;
    for (int kt = 0; kt < nk; kt++) {
        asm volatile("cp.async.wait_group 1;");
        __syncthreads();
        if (kt + 2 < nk) {
            int s = (kt + 2) % NSTAGE;
            stage_copy(A, Bw, smp + s * STAGE_FLOATS, smp + s * STAGE_FLOATS + SA_FLOATS,
                       bm, bn, Nn, K, (kt + 2) * 32, tid);
        }
        asm volatile("cp.async.commit_group;");
        int cur = kt % NSTAGE;
        stage_compute(smp + cur * STAGE_FLOATS, smp + cur * STAGE_FLOATS + SA_FLOATS,
                      acc, wm, wn, g, t);
    }

    #pragma unroll
    for (int im = 0; im < 4; im++) {
        int row = bm + wm + im * 16 + g;
        #pragma unroll
        for (int in = 0; in < 8; in++) {
            int col = bn + wn + in * 8 + 2 * t;
            if (col < Nn) {
                size_t o0 = (size_t)row * Nn + col;
                size_t o1 = (size_t)(row + 8) * Nn + col;
                float v0 = acc[im][in][0], v1 = acc[im][in][1];
                float v2 = acc[im][in][2], v3 = acc[im][in][3];
                if (Res) {
                    v0 += Res[o0]; v1 += Res[o0 + 1];
                    v2 += Res[o1]; v3 += Res[o1 + 1];
                }
                C[o0] = v0; C[o0 + 1] = v1;
                C[o1] = v2; C[o1 + 1] = v3;
            }
        }
    }
}

__global__ void __launch_bounds__(128) k_gemm1() {
    gemm_tf32_body(g_xn, g_Win, nullptr, g_zx, BL, PROJ, DM);
}
__global__ void __launch_bounds__(128) k_gemm2(const float* __restrict__ x,
                                               float* __restrict__ out) {
    gemm_tf32_body(g_yn, g_Wout, x, out, BL, DM, DI);
}

// ---------------- K3: causal depthwise conv (w=4) + silu -> g_xBC ----------
__global__ void __launch_bounds__(256) k_conv(const float* __restrict__ cw,
                                              const float* __restrict__ cb) {
    int idx = blockIdx.x * 256 + threadIdx.x;
    if (idx >= BL * CDIM) return;
    int ch = idx % CDIM;
    int bl = idx / CDIM;
    int l = bl % Lq;
    float acc = cb[ch];
    #pragma unroll
    for (int k = 0; k < 4; k++) {
        int ls = l - 3 + k;
        if (ls >= 0)
            acc += g_zx[(size_t)(bl - l + ls) * PROJ + DI + ch] * cw[k * CDIM + ch];
    }
    acc = acc / (1.f + expf(-acc));
    g_xBC[(size_t)bl * CDIM + ch] = acc;
}

// ---------------- K3b: dt = softplus(raw + bias) ----------------
__global__ void __launch_bounds__(256) k_dt(const float* __restrict__ dt_bias) {
    int idx = blockIdx.x * 256 + threadIdx.x;
    if (idx >= BL * HN) return;
    int h = idx & 31;
    float v = g_zx[(size_t)(idx >> 5) * PROJ + DI + CDIM + h] + dt_bias[h];
    g_dt[idx] = (v > 20.f) ? v : log1pf(expf(v));
}

// ---------------- K4: intra-chunk via TF32 mma ----------------
#define SBSTR 132
#define SXSTR 68
#define OFF_C  0
#define OFF_B  8448
#define OFF_XT 16896
#define OFF_XD 21248
#define OFF_G  25600
#define OFF_BT 29952
#define SMEM_K4 ((29952 + 128 * 68) * 4)   // 154624 bytes

__global__ void __launch_bounds__(256) k_chunk(const float* __restrict__ A_log) {
    extern __shared__ float sm[];
    float* sC  = sm + OFF_C;
    float* sB  = sm + OFF_B;
    float* sXT = sm + OFF_XT;
    float* sXD = sm + OFF_XD;
    float* sG  = sm + OFF_G;
    float* sBT = sm + OFF_BT;
    __shared__ float sDt[64], sAc[64], sDec[64];

    int bid = blockIdx.x;
    int h = bid & 31, c = (bid >> 5) & 31, b = bid >> 10;
    int tid = threadIdx.x;
    int w = tid >> 5, lane = tid & 31, gq = lane >> 2, tq = lane & 3;
    float Aval = -expf(A_log[h]);
    int posBase = b * Lq + c * 64;

    if (tid < 64) sDt[tid] = g_dt[(posBase + tid) * HN + h];
    #pragma unroll
    for (int k = 0; k < 8; k++) {
        int e4 = tid + k * 256;
        int row = e4 >> 5, col = (e4 & 31) * 4;
        const float* base = &g_xBC[(size_t)(posBase + row) * CDIM + DI];
        float4 bv = *(const float4*)(base + col);
        float4 cv = *(const float4*)(base + DS + col);
        bv.x = f2tf(bv.x); bv.y = f2tf(bv.y); bv.z = f2tf(bv.z); bv.w = f2tf(bv.w);
        cv.x = f2tf(cv.x); cv.y = f2tf(cv.y); cv.z = f2tf(cv.z); cv.w = f2tf(cv.w);
        *(float4*)(sB + row * SBSTR + col) = bv;
        *(float4*)(sC + row * SBSTR + col) = cv;
    }
    __syncthreads();
    if (tid == 0) {
        float acc = 0.f;
        for (int s = 0; s < 64; s++) { acc += sDt[s] * Aval; sAc[s] = acc; }
    }
    #pragma unroll
    for (int k = 0; k < 32; k++) {
        int e = tid + k * 256;
        int n = e & 127, s = e >> 7;
        sBT[n * SXSTR + s] = sB[s * SBSTR + n];
    }
    __syncthreads();
    if (tid < 64) sDec[tid] = expf(sAc[63] - sAc[tid]);
    __syncthreads();
    #pragma unroll
    for (int k = 0; k < 16; k++) {
        int e = tid + k * 256;
        int p = e & 63, s = e >> 6;
        float xv = g_xBC[(size_t)(posBase + s) * CDIM + h * 64 + p] * sDt[s];
        sXT[p * SXSTR + s] = f2tf(xv);
        sXD[p * SXSTR + s] = f2tf(xv * sDec[s]);
    }
    __syncthreads();

    {
        int wm = (w >> 1) * 16, wn = (w & 1) * 32;
        float acc[4][4] = {};
        #pragma unroll
        for (int kk = 0; kk < 16; kk++) {
            int k = kk * 8;
            uint32_t af[4];
            int r0 = wm + gq;
            af[0] = __float_as_uint(sC[r0 * SBSTR + k + tq]);
            af[1] = __float_as_uint(sC[(r0 + 8) * SBSTR + k + tq]);
            af[2] = __float_as_uint(sC[r0 * SBSTR + k + tq + 4]);
            af[3] = __float_as_uint(sC[(r0 + 8) * SBSTR + k + tq + 4]);
            #pragma unroll
            for (int in = 0; in < 4; in++) {
                int n0 = wn + in * 8 + gq;
                uint32_t bf[2];
                bf[0] = __float_as_uint(sB[n0 * SBSTR + k + tq]);
                bf[1] = __float_as_uint(sB[n0 * SBSTR + k + tq + 4]);
                mma_tf32(acc[in], af, bf);
            }
        }
        int l0 = wm + gq, l1 = l0 + 8;
        float a0 = sAc[l0], a1 = sAc[l1];
        #pragma unroll
        for (int in = 0; in < 4; in++) {
            int s0 = wn + in * 8 + 2 * tq, s1 = s0 + 1;
            float as0 = sAc[s0], as1 = sAc[s1];
            sG[l0 * SXSTR + s0] = (l0 >= s0) ? f2tf(expf(a0 - as0) * acc[in][0]) : 0.f;
            sG[l0 * SXSTR + s1] = (l0 >= s1) ? f2tf(expf(a0 - as1) * acc[in][1]) : 0.f;
            sG[l1 * SXSTR + s0] = (l1 >= s0) ? f2tf(expf(a1 - as0) * acc[in][2]) : 0.f;
            sG[l1 * SXSTR + s1] = (l1 >= s1) ? f2tf(expf(a1 - as1) * acc[in][3]) : 0.f;
        }
    }
    __syncthreads();

    {
        int wm = (w >> 1) * 16, wn = (w & 1) * 32;
        float acc[4][4] = {};
        #pragma unroll
        for (int kk = 0; kk < 8; kk++) {
            int k = kk * 8;
            uint32_t af[4];
            int r0 = wm + gq;
            af[0] = __float_as_uint(sG[r0 * SXSTR + k + tq]);
            af[1] = __float_as_uint(sG[(r0 + 8) * SXSTR + k + tq]);
            af[2] = __float_as_uint(sG[r0 * SXSTR + k + tq + 4]);
            af[3] = __float_as_uint(sG[(r0 + 8) * SXSTR + k + tq + 4]);
            #pragma unroll
            for (int in = 0; in < 4; in++) {
                int n0 = wn + in * 8 + gq;
                uint32_t bf[2];
                bf[0] = __float_as_uint(sXT[n0 * SXSTR + k + tq]);
                bf[1] = __float_as_uint(sXT[n0 * SXSTR + k + tq + 4]);
                mma_tf32(acc[in], af, bf);
            }
        }
        int l0 = wm + gq, l1 = l0 + 8;
        float* y0 = &g_Y[(size_t)(posBase + l0) * DI + h * 64];
        float* y1 = &g_Y[(size_t)(posBase + l1) * DI + h * 64];
        #pragma unroll
        for (int in = 0; in < 4; in++) {
            int p0 = wn + in * 8 + 2 * tq;
            y0[p0] = acc[in][0]; y0[p0 + 1] = acc[in][1];
            y1[p0] = acc[in][2]; y1[p0 + 1] = acc[in][3];
        }
    }

    {
        int wm = (w >> 1) * 16, wn = (w & 1) * 64;
        float acc[8][4] = {};
        #pragma unroll
        for (int kk = 0; kk < 8; kk++) {
            int k = kk * 8;
            uint32_t af[4];
            int r0 = wm + gq;
            af[0] = __float_as_uint(sXD[r0 * SXSTR + k + tq]);
            af[1] = __float_as_uint(sXD[(r0 + 8) * SXSTR + k + tq]);
            af[2] = __float_as_uint(sXD[r0 * SXSTR + k + tq + 4]);
            af[3] = __float_as_uint(sXD[(r0 + 8) * SXSTR + k + tq + 4]);
            #pragma unroll
            for (int in = 0; in < 8; in++) {
                int n0 = wn + in * 8 + gq;
                uint32_t bf[2];
                bf[0] = __float_as_uint(sBT[n0 * SXSTR + k + tq]);
                bf[1] = __float_as_uint(sBT[n0 * SXSTR + k + tq + 4]);
                mma_tf32(acc[in], af, bf);
            }
        }
        size_t sbase = ((size_t)((b * NC + c) * HN + h)) * (64 * 128);
        int p0 = wm + gq, p1 = p0 + 8;
        #pragma unroll
        for (int in = 0; in < 8; in++) {
            int n0 = wn + in * 8 + 2 * tq;
            g_states[sbase + (size_t)p0 * 128 + n0]     = acc[in][0];
            g_states[sbase + (size_t)p0 * 128 + n0 + 1] = acc[in][1];
            g_states[sbase + (size_t)p1 * 128 + n0]     = acc[in][2];
            g_states[sbase + (size_t)p1 * 128 + n0 + 1] = acc[in][3];
        }
    }
    if (tid == 0) g_asum[(b * HN + h) * NC + c] = sAc[63];
}

// ---------------- K5: inter-chunk prefix scan of states (float4) ----------
__global__ void __launch_bounds__(256) k_scan() {
    int bh = blockIdx.x;
    int b = bh >> 5, h = bh & 31;
    int tid = threadIdx.x;
    float4 S[8];
    #pragma unroll
    for (int j = 0; j < 8; j++) S[j] = make_float4(0.f, 0.f, 0.f, 0.f);
    for (int c = 0; c < NC; c++) {
        size_t base4 = ((size_t)((b * NC + c) * HN + h)) * 2048;
        float dec = expf(g_asum[(b * HN + h) * NC + c]);
        #pragma unroll
        for (int j = 0; j < 8; j++) {
            int e = tid + j * 256;
            ((float4*)g_sin)[base4 + e] = S[j];
            float4 st = ((const float4*)g_states)[base4 + e];
            S[j].x = S[j].x * dec + st.x;
            S[j].y = S[j].y * dec + st.y;
            S[j].z = S[j].z * dec + st.z;
            S[j].w = S[j].w * dec + st.w;
        }
    }
}

// ---------------- K6: Yo = exp(Ac) * C * S^T via mma; Y += Yo + xs*D -------
#define SMEM_K6 (8448 * 2 * 4)   // 67584 bytes
__global__ void __launch_bounds__(256) k_inter(const float* __restrict__ A_log,
                                               const float* __restrict__ Dp) {
    extern __shared__ float sm[];
    float* sC = sm;
    float* sS = sm + 8448;
    __shared__ float sDt[64], sAc[64];

    int bid = blockIdx.x;
    int h = bid & 31, c = (bid >> 5) & 31, b = bid >> 10;
    int tid = threadIdx.x;
    int w = tid >> 5, lane = tid & 31, gq = lane >> 2, tq = lane & 3;
    float Aval = -expf(A_log[h]);
    float Dv = Dp[h];
    int posBase = b * Lq + c * 64;

    if (tid < 64) sDt[tid] = g_dt[(posBase + tid) * HN + h];
    size_t sbase = ((size_t)((b * NC + c) * HN + h)) * 8192;
    #pragma unroll
    for (int k = 0; k < 8; k++) {
        int e4 = tid + k * 256;
        int row = e4 >> 5, col = (e4 & 31) * 4;
        float4 cv = *(const float4*)&g_xBC[(size_t)(posBase + row) * CDIM + DI + DS + col];
        float4 sv = *(const float4*)&g_sin[sbase + (size_t)row * 128 + col];
        cv.x = f2tf(cv.x); cv.y = f2tf(cv.y); cv.z = f2tf(cv.z); cv.w = f2tf(cv.w);
        sv.x = f2tf(sv.x); sv.y = f2tf(sv.y); sv.z = f2tf(sv.z); sv.w = f2tf(sv.w);
        *(float4*)(sC + row * SBSTR + col) = cv;
        *(float4*)(sS + row * SBSTR + col) = sv;
    }
    __syncthreads();
    if (tid == 0) {
        float acc = 0.f;
        for (int s = 0; s < 64; s++) { acc += sDt[s] * Aval; sAc[s] = acc; }
    }
    __syncthreads();

    int wm = (w >> 1) * 16, wn = (w & 1) * 32;
    float acc[4][4] = {};
    #pragma unroll
    for (int kk = 0; kk < 16; kk++) {
        int k = kk * 8;
        uint32_t af[4];
        int r0 = wm + gq;
        af[0] = __float_as_uint(sC[r0 * SBSTR + k + tq]);
        af[1] = __float_as_uint(sC[(r0 + 8) * SBSTR + k + tq]);
        af[2] = __float_as_uint(sC[r0 * SBSTR + k + tq + 4]);
        af[3] = __float_as_uint(sC[(r0 + 8) * SBSTR + k + tq + 4]);
        #pragma unroll
        for (int in = 0; in < 4; in++) {
            int n0 = wn + in * 8 + gq;
            uint32_t bf[2];
            bf[0] = __float_as_uint(sS[n0 * SBSTR + k + tq]);
            bf[1] = __float_as_uint(sS[n0 * SBSTR + k + tq + 4]);
            mma_tf32(acc[in], af, bf);
        }
    }
    int l0 = wm + gq, l1 = l0 + 8;
    float e0 = expf(sAc[l0]), e1 = expf(sAc[l1]);
    float* y0 = &g_Y[(size_t)(posBase + l0) * DI + h * 64];
    float* y1 = &g_Y[(size_t)(posBase + l1) * DI + h * 64];
    const float* x0 = &g_xBC[(size_t)(posBase + l0) * CDIM + h * 64];
    const float* x1 = &g_xBC[(size_t)(posBase + l1) * CDIM + h * 64];
    #pragma unroll
    for (int in = 0; in < 4; in++) {
        int p0 = wn + in * 8 + 2 * tq;
        y0[p0]     += e0 * acc[in][0] + x0[p0] * Dv;
        y0[p0 + 1] += e0 * acc[in][1] + x0[p0 + 1] * Dv;
        y1[p0]     += e1 * acc[in][2] + x1[p0] * Dv;
        y1[p0 + 1] += e1 * acc[in][3] + x1[p0 + 1] * Dv;
    }
}

// ---------------- K7: gated rmsnorm -> g_yn (tf32-rounded) ----------------
__global__ void __launch_bounds__(256) k_gate(const float* __restrict__ w) {
    __shared__ float sv[DI];
    int row = blockIdx.x;
    int tid = threadIdx.x;
    float s = 0.f;
    for (int i = tid; i < DI; i += 256) {
        float z = g_zx[(size_t)row * PROJ + i];
        float y = g_Y[(size_t)row * DI + i];
        float v = y * z / (1.f + expf(-z));
        sv[i] = v;
        s += v * v;
    }
    float tot = block_sum(s);
    float inv = rsqrtf(tot / DI + 1e-5f);
    for (int i = tid; i < DI; i += 256)
        g_yn[(size_t)row * DI + i] = f2tf(sv[i] * inv * w[i]);
}

// ---------------- launcher ----------------
extern "C" void kernel_launch(void* const* d_in, const int* in_sizes, int n_in,
                              void* d_out, int out_size) {
    const float* x       = (const float*)d_in[0];
    const float* norm_w  = (const float*)d_in[1];
    const float* in_W    = (const float*)d_in[2];
    const float* conv_w  = (const float*)d_in[3];
    const float* conv_b  = (const float*)d_in[4];
    const float* dt_bias = (const float*)d_in[5];
    const float* A_log   = (const float*)d_in[6];
    const float* Dp      = (const float*)d_in[7];
    const float* ni_w    = (const float*)d_in[8];
    const float* out_W   = (const float*)d_in[9];
    float* out = (float*)d_out;

    cudaFuncSetAttribute(k_gemm1, cudaFuncAttributeMaxDynamicSharedMemorySize, SMEM_GEMM);
    cudaFuncSetAttribute(k_gemm2, cudaFuncAttributeMaxDynamicSharedMemorySize, SMEM_GEMM);
    cudaFuncSetAttribute(k_chunk, cudaFuncAttributeMaxDynamicSharedMemorySize, SMEM_K4);
    cudaFuncSetAttribute(k_inter, cudaFuncAttributeMaxDynamicSharedMemorySize, SMEM_K6);

    float* d_Win;  cudaGetSymbolAddress((void**)&d_Win, g_Win);
    float* d_Wout; cudaGetSymbolAddress((void**)&d_Wout, g_Wout);

    k_cvt<<<(PROJ * DM / 4 + 255) / 256, 256>>>(in_W, d_Win, PROJ * DM / 4);
    k_cvt<<<(DM * DI / 4 + 255) / 256, 256>>>(out_W, d_Wout, DM * DI / 4);
    k_rmsnorm<<<BL, 256>>>(x, norm_w);
    k_gemm1<<<dim3((PROJ + 127) / 128, BL / 128), 128, SMEM_GEMM>>>();
    k_conv<<<(BL * CDIM + 255) / 256, 256>>>(conv_w, conv_b);
    k_dt<<<(BL * HN + 255) / 256, 256>>>(dt_bias);
    k_chunk<<<Bq * NC * HN, 256, SMEM_K4>>>(A_log);
    k_scan<<<Bq * HN, 256>>>();
    k_inter<<<Bq * NC * HN, 256, SMEM_K6>>>(A_log, Dp);
    k_gate<<<BL, 256>>>(ni_w);
    k_gemm2<<<dim3(DM / 128, BL / 128), 128, SMEM_GEMM>>>(x, out);
}

// round 7
// speedup vs baseline: 4.5002x; 1.0158x over previous
#include <cuda_runtime.h>
#include <math.h>
#include <stdint.h>

#define Bq 4
#define Lq 2048
#define DM 1024
#define DI 2048
#define HN 32
#define HD 64
#define DS 128
#define CDIM 2304
#define PROJ 4384
#define CH 64
#define NC 32
#define BL 8192

// ---------------- scratch (device globals; no allocations) ----------------
__device__ float g_xn[BL * DM];                 // rmsnorm(x), tf32-rounded
__device__ float g_zx[(size_t)BL * PROJ];       // zxbcdt
__device__ float g_xBC[(size_t)BL * CDIM];      // conv+silu output
__device__ float g_dt[BL * HN];                 // softplus dt
__device__ float g_Y[(size_t)BL * DI];          // SSD output (Yd then +=Yo)
__device__ float g_states[(size_t)Bq * NC * HN * HD * DS];
__device__ float g_sin[(size_t)Bq * NC * HN * HD * DS];
__device__ float g_asum[Bq * HN * NC];
__device__ float g_yn[(size_t)BL * DI];         // gated+normed Y, tf32-rounded
__device__ float g_Win[(size_t)PROJ * DM];      // tf32-rounded in_proj_W
__device__ float g_Wout[(size_t)DM * DI];       // tf32-rounded out_proj_W

// ---------------- helpers ----------------
__device__ __forceinline__ float block_sum(float v) {
    __shared__ float red[8];
    #pragma unroll
    for (int o = 16; o; o >>= 1) v += __shfl_down_sync(0xffffffffu, v, o);
    if ((threadIdx.x & 31) == 0) red[threadIdx.x >> 5] = v;
    __syncthreads();
    if (threadIdx.x < 32) {
        v = (threadIdx.x < 8) ? red[threadIdx.x] : 0.f;
        #pragma unroll
        for (int o = 4; o; o >>= 1) v += __shfl_down_sync(0xffffffffu, v, o);
        if (threadIdx.x == 0) red[0] = v;
    }
    __syncthreads();
    return red[0];
}

__device__ __forceinline__ float f2tf(float x) {
    uint32_t u;
    asm("cvt.rna.tf32.f32 %0, %1;" : "=r"(u) : "f"(x));
    return __uint_as_float(u);
}

__device__ __forceinline__ void mma_tf32(float c[4], const uint32_t a[4], const uint32_t b[2]) {
    asm volatile(
        "mma.sync.aligned.m16n8k8.row.col.f32.tf32.tf32.f32 "
        "{%0,%1,%2,%3}, {%4,%5,%6,%7}, {%8,%9}, {%0,%1,%2,%3};"
        : "+f"(c[0]), "+f"(c[1]), "+f"(c[2]), "+f"(c[3])
        : "r"(a[0]), "r"(a[1]), "r"(a[2]), "r"(a[3]), "r"(b[0]), "r"(b[1]));
}

// ---------------- K0: tf32-round weights into scratch ----------------
__global__ void __launch_bounds__(256) k_cvt(const float* __restrict__ src,
                                             float* __restrict__ dst, int n4) {
    int i = blockIdx.x * 256 + threadIdx.x;
    if (i >= n4) return;
    float4 v = ((const float4*)src)[i];
    v.x = f2tf(v.x); v.y = f2tf(v.y); v.z = f2tf(v.z); v.w = f2tf(v.w);
    ((float4*)dst)[i] = v;
}

// ---------------- K1: rmsnorm(x) -> g_xn (tf32-rounded) ----------------
__global__ void __launch_bounds__(256) k_rmsnorm(const float* __restrict__ x,
                                                 const float* __restrict__ w) {
    int row = blockIdx.x;
    const float* xr = x + (size_t)row * DM;
    float s = 0.f;
    for (int i = threadIdx.x; i < DM; i += 256) { float v = xr[i]; s += v * v; }
    float tot = block_sum(s);
    float inv = rsqrtf(tot / DM + 1e-5f);
    for (int i = threadIdx.x; i < DM; i += 256)
        g_xn[(size_t)row * DM + i] = f2tf(xr[i] * inv * w[i]);
}

// ---------------- TF32 pipelined GEMM: C[M,N] = A[M,K]*B[N,K]^T (+Res) -----
// CTA 128x128, 4 warps (64x64 each), k-step 32, 2-stage cp.async pipeline,
// register double-buffered fragments to hide LDS latency behind mma issue.
#define SA_FLOATS (128 * 36)
#define SB_FLOATS (128 * 36)
#define STAGE_FLOATS (SA_FLOATS + SB_FLOATS)
#define NSTAGE 2
#define SMEM_GEMM (STAGE_FLOATS * NSTAGE * 4)   // 73728 bytes

__device__ __forceinline__ void stage_copy(const float* __restrict__ A,
                                           const float* __restrict__ Bw,
                                           float* sA, float* sB,
                                           int bm, int bn, int Nn, int K,
                                           int k0, int tid) {
    #pragma unroll
    for (int i = 0; i < 8; i++) {
        int c = tid + 128 * i;                 // 1024 16B chunks for A
        int row = c >> 3, col4 = (c & 7) * 4;
        uint32_t d = (uint32_t)__cvta_generic_to_shared(sA + row * 36 + col4);
        const float* g = A + (size_t)(bm + row) * K + k0 + col4;
        asm volatile("cp.async.cg.shared.global [%0], [%1], 16;" :: "r"(d), "l"(g));
    }
    #pragma unroll
    for (int i = 0; i < 8; i++) {
        int c = tid + 128 * i;                 // 1024 16B chunks for B
        int row = c >> 3, col4 = (c & 7) * 4;
        uint32_t d = (uint32_t)__cvta_generic_to_shared(sB + row * 36 + col4);
        int n = bn + row;
        int ok = (n < Nn);
        const float* g = Bw + (size_t)(ok ? n : 0) * K + k0 + col4;
        int sz = ok ? 16 : 0;
        asm volatile("cp.async.cg.shared.global [%0], [%1], 16, %2;" :: "r"(d), "l"(g), "r"(sz));
    }
}

__device__ __forceinline__ void load_frag(const float* sA, const float* sB,
                                          int kk, uint32_t af[4][4], uint32_t bf[8][2],
                                          int wm, int wn, int g, int t) {
    int k = kk * 8;
    #pragma unroll
    for (int im = 0; im < 4; im++) {
        int r0 = wm + im * 16 + g;
        af[im][0] = __float_as_uint(sA[r0 * 36 + k + t]);
        af[im][1] = __float_as_uint(sA[(r0 + 8) * 36 + k + t]);
        af[im][2] = __float_as_uint(sA[r0 * 36 + k + t + 4]);
        af[im][3] = __float_as_uint(sA[(r0 + 8) * 36 + k + t + 4]);
    }
    #pragma unroll
    for (int in = 0; in < 8; in++) {
        int n0 = wn + in * 8 + g;
        bf[in][0] = __float_as_uint(sB[n0 * 36 + k + t]);
        bf[in][1] = __float_as_uint(sB[n0 * 36 + k + t + 4]);
    }
}

__device__ __forceinline__ void stage_compute(const float* sA, const float* sB,
                                              float acc[4][8][4],
                                              int wm, int wn, int g, int t) {
    uint32_t af[2][4][4], bf[2][8][2];
    load_frag(sA, sB, 0, af[0], bf[0], wm, wn, g, t);
    #pragma unroll
    for (int kk = 0; kk < 4; kk++) {
        int cur = kk & 1;
        if (kk < 3)
            load_frag(sA, sB, kk + 1, af[cur ^ 1], bf[cur ^ 1], wm, wn, g, t);
        #pragma unroll
        for (int im = 0; im < 4; im++)
            #pragma unroll
            for (int in = 0; in < 8; in++)
                mma_tf32(acc[im][in], af[cur][im], bf[cur][in]);
    }
}

__device__ __forceinline__ void gemm_tf32_body(const float* __restrict__ A,
                                               const float* __restrict__ Bw,
                                               const float* __restrict__ Res,
                                               float* __restrict__ C,
                                               int M, int Nn, int K) {
    extern __shared__ float smp[];
    int bm = blockIdx.y * 128, bn = blockIdx.x * 128;
    int tid = threadIdx.x;
    int w = tid >> 5, lane = tid & 31, g = lane >> 2, t = lane & 3;
    int wm = (w >> 1) * 64, wn = (w & 1) * 64;

    float acc[4][8][4] = {};

    stage_copy(A, Bw, smp, smp + SA_FLOATS, bm, bn, Nn, K, 0, tid);
    asm volatile("cp.async.commit_group;");

    int nk = K / 32;
    for (int kt = 0; kt < nk; kt++) {
        asm volatile("cp.async.wait_group 0;");
        __syncthreads();
        if (kt + 1 < nk) {
            int s = (kt + 1) & 1;
            stage_copy(A, Bw, smp + s * STAGE_FLOATS, smp + s * STAGE_FLOATS + SA_FLOATS,
                       bm, bn, Nn, K, (kt + 1) * 32, tid);
            asm volatile("cp.async.commit_group;");
        }
        int cur = kt & 1;
        stage_compute(smp + cur * STAGE_FLOATS, smp + cur * STAGE_FLOATS + SA_FLOATS,
                      acc, wm, wn, g, t);
    }

    #pragma unroll
    for (int im = 0; im < 4; im++) {
        int row = bm + wm + im * 16 + g;
        #pragma unroll
        for (int in = 0; in < 8; in++) {
            int col = bn + wn + in * 8 + 2 * t;
            if (col < Nn) {
                size_t o0 = (size_t)row * Nn + col;
                size_t o1 = (size_t)(row + 8) * Nn + col;
                float v0 = acc[im][in][0], v1 = acc[im][in][1];
                float v2 = acc[im][in][2], v3 = acc[im][in][3];
                if (Res) {
                    v0 += Res[o0]; v1 += Res[o0 + 1];
                    v2 += Res[o1]; v3 += Res[o1 + 1];
                }
                C[o0] = v0; C[o0 + 1] = v1;
                C[o1] = v2; C[o1 + 1] = v3;
            }
        }
    }
}

__global__ void __launch_bounds__(128) k_gemm1() {
    gemm_tf32_body(g_xn, g_Win, nullptr, g_zx, BL, PROJ, DM);
}
__global__ void __launch_bounds__(128) k_gemm2(const float* __restrict__ x,
                                               float* __restrict__ out) {
    gemm_tf32_body(g_yn, g_Wout, x, out, BL, DM, DI);
}

// ---------------- K3: causal depthwise conv (w=4) + silu -> g_xBC ----------
__global__ void __launch_bounds__(256) k_conv(const float* __restrict__ cw,
                                              const float* __restrict__ cb) {
    int idx = blockIdx.x * 256 + threadIdx.x;
    if (idx >= BL * CDIM) return;
    int ch = idx % CDIM;
    int bl = idx / CDIM;
    int l = bl % Lq;
    float acc = cb[ch];
    #pragma unroll
    for (int k = 0; k < 4; k++) {
        int ls = l - 3 + k;
        if (ls >= 0)
            acc += g_zx[(size_t)(bl - l + ls) * PROJ + DI + ch] * cw[k * CDIM + ch];
    }
    acc = acc / (1.f + expf(-acc));
    g_xBC[(size_t)bl * CDIM + ch] = acc;
}

// ---------------- K3b: dt = softplus(raw + bias) ----------------
__global__ void __launch_bounds__(256) k_dt(const float* __restrict__ dt_bias) {
    int idx = blockIdx.x * 256 + threadIdx.x;
    if (idx >= BL * HN) return;
    int h = idx & 31;
    float v = g_zx[(size_t)(idx >> 5) * PROJ + DI + CDIM + h] + dt_bias[h];
    g_dt[idx] = (v > 20.f) ? v : log1pf(expf(v));
}

// ---------------- K4: intra-chunk via TF32 mma ----------------
#define SBSTR 132
#define SXSTR 68
#define OFF_C  0
#define OFF_B  8448
#define OFF_XT 16896
#define OFF_XD 21248
#define OFF_G  25600
#define OFF_BT 29952
#define SMEM_K4 ((29952 + 128 * 68) * 4)   // 154624 bytes

__global__ void __launch_bounds__(256) k_chunk(const float* __restrict__ A_log) {
    extern __shared__ float sm[];
    float* sC  = sm + OFF_C;
    float* sB  = sm + OFF_B;
    float* sXT = sm + OFF_XT;
    float* sXD = sm + OFF_XD;
    float* sG  = sm + OFF_G;
    float* sBT = sm + OFF_BT;
    __shared__ float sDt[64], sAc[64], sDec[64];

    int bid = blockIdx.x;
    int h = bid & 31, c = (bid >> 5) & 31, b = bid >> 10;
    int tid = threadIdx.x;
    int w = tid >> 5, lane = tid & 31, gq = lane >> 2, tq = lane & 3;
    float Aval = -expf(A_log[h]);
    int posBase = b * Lq + c * 64;

    if (tid < 64) sDt[tid] = g_dt[(posBase + tid) * HN + h];
    #pragma unroll
    for (int k = 0; k < 8; k++) {
        int e4 = tid + k * 256;
        int row = e4 >> 5, col = (e4 & 31) * 4;
        const float* base = &g_xBC[(size_t)(posBase + row) * CDIM + DI];
        float4 bv = *(const float4*)(base + col);
        float4 cv = *(const float4*)(base + DS + col);
        bv.x = f2tf(bv.x); bv.y = f2tf(bv.y); bv.z = f2tf(bv.z); bv.w = f2tf(bv.w);
        cv.x = f2tf(cv.x); cv.y = f2tf(cv.y); cv.z = f2tf(cv.z); cv.w = f2tf(cv.w);
        *(float4*)(sB + row * SBSTR + col) = bv;
        *(float4*)(sC + row * SBSTR + col) = cv;
    }
    __syncthreads();
    if (tid == 0) {
        float acc = 0.f;
        for (int s = 0; s < 64; s++) { acc += sDt[s] * Aval; sAc[s] = acc; }
    }
    #pragma unroll
    for (int k = 0; k < 32; k++) {
        int e = tid + k * 256;
        int n = e & 127, s = e >> 7;
        sBT[n * SXSTR + s] = sB[s * SBSTR + n];
    }
    __syncthreads();
    if (tid < 64) sDec[tid] = expf(sAc[63] - sAc[tid]);
    __syncthreads();
    #pragma unroll
    for (int k = 0; k < 16; k++) {
        int e = tid + k * 256;
        int p = e & 63, s = e >> 6;
        float xv = g_xBC[(size_t)(posBase + s) * CDIM + h * 64 + p] * sDt[s];
        sXT[p * SXSTR + s] = f2tf(xv);
        sXD[p * SXSTR + s] = f2tf(xv * sDec[s]);
    }
    __syncthreads();

    {
        int wm = (w >> 1) * 16, wn = (w & 1) * 32;
        float acc[4][4] = {};
        #pragma unroll
        for (int kk = 0; kk < 16; kk++) {
            int k = kk * 8;
            uint32_t af[4];
            int r0 = wm + gq;
            af[0] = __float_as_uint(sC[r0 * SBSTR + k + tq]);
            af[1] = __float_as_uint(sC[(r0 + 8) * SBSTR + k + tq]);
            af[2] = __float_as_uint(sC[r0 * SBSTR + k + tq + 4]);
            af[3] = __float_as_uint(sC[(r0 + 8) * SBSTR + k + tq + 4]);
            #pragma unroll
            for (int in = 0; in < 4; in++) {
                int n0 = wn + in * 8 + gq;
                uint32_t bf[2];
                bf[0] = __float_as_uint(sB[n0 * SBSTR + k + tq]);
                bf[1] = __float_as_uint(sB[n0 * SBSTR + k + tq + 4]);
                mma_tf32(acc[in], af, bf);
            }
        }
        int l0 = wm + gq, l1 = l0 + 8;
        float a0 = sAc[l0], a1 = sAc[l1];
        #pragma unroll
        for (int in = 0; in < 4; in++) {
            int s0 = wn + in * 8 + 2 * tq, s1 = s0 + 1;
            float as0 = sAc[s0], as1 = sAc[s1];
            sG[l0 * SXSTR + s0] = (l0 >= s0) ? f2tf(expf(a0 - as0) * acc[in][0]) : 0.f;
            sG[l0 * SXSTR + s1] = (l0 >= s1) ? f2tf(expf(a0 - as1) * acc[in][1]) : 0.f;
            sG[l1 * SXSTR + s0] = (l1 >= s0) ? f2tf(expf(a1 - as0) * acc[in][2]) : 0.f;
            sG[l1 * SXSTR + s1] = (l1 >= s1) ? f2tf(expf(a1 - as1) * acc[in][3]) : 0.f;
        }
    }
    __syncthreads();

    {
        int wm = (w >> 1) * 16, wn = (w & 1) * 32;
        float acc[4][4] = {};
        #pragma unroll
        for (int kk = 0; kk < 8; kk++) {
            int k = kk * 8;
            uint32_t af[4];
            int r0 = wm + gq;
            af[0] = __float_as_uint(sG[r0 * SXSTR + k + tq]);
            af[1] = __float_as_uint(sG[(r0 + 8) * SXSTR + k + tq]);
            af[2] = __float_as_uint(sG[r0 * SXSTR + k + tq + 4]);
            af[3] = __float_as_uint(sG[(r0 + 8) * SXSTR + k + tq + 4]);
            #pragma unroll
            for (int in = 0; in < 4; in++) {
                int n0 = wn + in * 8 + gq;
                uint32_t bf[2];
                bf[0] = __float_as_uint(sXT[n0 * SXSTR + k + tq]);
                bf[1] = __float_as_uint(sXT[n0 * SXSTR + k + tq + 4]);
                mma_tf32(acc[in], af, bf);
            }
        }
        int l0 = wm + gq, l1 = l0 + 8;
        float* y0 = &g_Y[(size_t)(posBase + l0) * DI + h * 64];
        float* y1 = &g_Y[(size_t)(posBase + l1) * DI + h * 64];
        #pragma unroll
        for (int in = 0; in < 4; in++) {
            int p0 = wn + in * 8 + 2 * tq;
            y0[p0] = acc[in][0]; y0[p0 + 1] = acc[in][1];
            y1[p0] = acc[in][2]; y1[p0 + 1] = acc[in][3];
        }
    }

    {
        int wm = (w >> 1) * 16, wn = (w & 1) * 64;
        float acc[8][4] = {};
        #pragma unroll
        for (int kk = 0; kk < 8; kk++) {
            int k = kk * 8;
            uint32_t af[4];
            int r0 = wm + gq;
            af[0] = __float_as_uint(sXD[r0 * SXSTR + k + tq]);
            af[1] = __float_as_uint(sXD[(r0 + 8) * SXSTR + k + tq]);
            af[2] = __float_as_uint(sXD[r0 * SXSTR + k + tq + 4]);
            af[3] = __float_as_uint(sXD[(r0 + 8) * SXSTR + k + tq + 4]);
            #pragma unroll
            for (int in = 0; in < 8; in++) {
                int n0 = wn + in * 8 + gq;
                uint32_t bf[2];
                bf[0] = __float_as_uint(sBT[n0 * SXSTR + k + tq]);
                bf[1] = __float_as_uint(sBT[n0 * SXSTR + k + tq + 4]);
                mma_tf32(acc[in], af, bf);
            }
        }
        size_t sbase = ((size_t)((b * NC + c) * HN + h)) * (64 * 128);
        int p0 = wm + gq, p1 = p0 + 8;
        #pragma unroll
        for (int in = 0; in < 8; in++) {
            int n0 = wn + in * 8 + 2 * tq;
            g_states[sbase + (size_t)p0 * 128 + n0]     = acc[in][0];
            g_states[sbase + (size_t)p0 * 128 + n0 + 1] = acc[in][1];
            g_states[sbase + (size_t)p1 * 128 + n0]     = acc[in][2];
            g_states[sbase + (size_t)p1 * 128 + n0 + 1] = acc[in][3];
        }
    }
    if (tid == 0) g_asum[(b * HN + h) * NC + c] = sAc[63];
}

// ---------------- K5: inter-chunk prefix scan of states (float4) ----------
__global__ void __launch_bounds__(256) k_scan() {
    int bh = blockIdx.x;
    int b = bh >> 5, h = bh & 31;
    int tid = threadIdx.x;
    float4 S[8];
    #pragma unroll
    for (int j = 0; j < 8; j++) S[j] = make_float4(0.f, 0.f, 0.f, 0.f);
    for (int c = 0; c < NC; c++) {
        size_t base4 = ((size_t)((b * NC + c) * HN + h)) * 2048;
        float dec = expf(g_asum[(b * HN + h) * NC + c]);
        #pragma unroll
        for (int j = 0; j < 8; j++) {
            int e = tid + j * 256;
            ((float4*)g_sin)[base4 + e] = S[j];
            float4 st = ((const float4*)g_states)[base4 + e];
            S[j].x = S[j].x * dec + st.x;
            S[j].y = S[j].y * dec + st.y;
            S[j].z = S[j].z * dec + st.z;
            S[j].w = S[j].w * dec + st.w;
        }
    }
}

// ---------------- K6: Yo = exp(Ac) * C * S^T via mma; Y += Yo + xs*D -------
#define SMEM_K6 (8448 * 2 * 4)   // 67584 bytes
__global__ void __launch_bounds__(256) k_inter(const float* __restrict__ A_log,
                                               const float* __restrict__ Dp) {
    extern __shared__ float sm[];
    float* sC = sm;
    float* sS = sm + 8448;
    __shared__ float sDt[64], sAc[64];

    int bid = blockIdx.x;
    int h = bid & 31, c = (bid >> 5) & 31, b = bid >> 10;
    int tid = threadIdx.x;
    int w = tid >> 5, lane = tid & 31, gq = lane >> 2, tq = lane & 3;
    float Aval = -expf(A_log[h]);
    float Dv = Dp[h];
    int posBase = b * Lq + c * 64;

    if (tid < 64) sDt[tid] = g_dt[(posBase + tid) * HN + h];
    size_t sbase = ((size_t)((b * NC + c) * HN + h)) * 8192;
    #pragma unroll
    for (int k = 0; k < 8; k++) {
        int e4 = tid + k * 256;
        int row = e4 >> 5, col = (e4 & 31) * 4;
        float4 cv = *(const float4*)&g_xBC[(size_t)(posBase + row) * CDIM + DI + DS + col];
        float4 sv = *(const float4*)&g_sin[sbase + (size_t)row * 128 + col];
        cv.x = f2tf(cv.x); cv.y = f2tf(cv.y); cv.z = f2tf(cv.z); cv.w = f2tf(cv.w);
        sv.x = f2tf(sv.x); sv.y = f2tf(sv.y); sv.z = f2tf(sv.z); sv.w = f2tf(sv.w);
        *(float4*)(sC + row * SBSTR + col) = cv;
        *(float4*)(sS + row * SBSTR + col) = sv;
    }
    __syncthreads();
    if (tid == 0) {
        float acc = 0.f;
        for (int s = 0; s < 64; s++) { acc += sDt[s] * Aval; sAc[s] = acc; }
    }
    __syncthreads();

    int wm = (w >> 1) * 16, wn = (w & 1) * 32;
    float acc[4][4] = {};
    #pragma unroll
    for (int kk = 0; kk < 16; kk++) {
        int k = kk * 8;
        uint32_t af[4];
        int r0 = wm + gq;
        af[0] = __float_as_uint(sC[r0 * SBSTR + k + tq]);
        af[1] = __float_as_uint(sC[(r0 + 8) * SBSTR + k + tq]);
        af[2] = __float_as_uint(sC[r0 * SBSTR + k + tq + 4]);
        af[3] = __float_as_uint(sC[(r0 + 8) * SBSTR + k + tq + 4]);
        #pragma unroll
        for (int in = 0; in < 4; in++) {
            int n0 = wn + in * 8 + gq;
            uint32_t bf[2];
            bf[0] = __float_as_uint(sS[n0 * SBSTR + k + tq]);
            bf[1] = __float_as_uint(sS[n0 * SBSTR + k + tq + 4]);
            mma_tf32(acc[in], af, bf);
        }
    }
    int l0 = wm + gq, l1 = l0 + 8;
    float e0 = expf(sAc[l0]), e1 = expf(sAc[l1]);
    float* y0 = &g_Y[(size_t)(posBase + l0) * DI + h * 64];
    float* y1 = &g_Y[(size_t)(posBase + l1) * DI + h * 64];
    const float* x0 = &g_xBC[(size_t)(posBase + l0) * CDIM + h * 64];
    const float* x1 = &g_xBC[(size_t)(posBase + l1) * CDIM + h * 64];
    #pragma unroll
    for (int in = 0; in < 4; in++) {
        int p0 = wn + in * 8 + 2 * tq;
        y0[p0]     += e0 * acc[in][0] + x0[p0] * Dv;
        y0[p0 + 1] += e0 * acc[in][1] + x0[p0 + 1] * Dv;
        y1[p0]     += e1 * acc[in][2] + x1[p0] * Dv;
        y1[p0 + 1] += e1 * acc[in][3] + x1[p0 + 1] * Dv;
    }
}

// ---------------- K7: gated rmsnorm -> g_yn (tf32-rounded) ----------------
__global__ void __launch_bounds__(256) k_gate(const float* __restrict__ w) {
    __shared__ float sv[DI];
    int row = blockIdx.x;
    int tid = threadIdx.x;
    float s = 0.f;
    for (int i = tid; i < DI; i += 256) {
        float z = g_zx[(size_t)row * PROJ + i];
        float y = g_Y[(size_t)row * DI + i];
        float v = y * z / (1.f + expf(-z));
        sv[i] = v;
        s += v * v;
    }
    float tot = block_sum(s);
    float inv = rsqrtf(tot / DI + 1e-5f);
    for (int i = tid; i < DI; i += 256)
        g_yn[(size_t)row * DI + i] = f2tf(sv[i] * inv * w[i]);
}

// ---------------- launcher ----------------
extern "C" void kernel_launch(void* const* d_in, const int* in_sizes, int n_in,
                              void* d_out, int out_size) {
    const float* x       = (const float*)d_in[0];
    const float* norm_w  = (const float*)d_in[1];
    const float* in_W    = (const float*)d_in[2];
    const float* conv_w  = (const float*)d_in[3];
    const float* conv_b  = (const float*)d_in[4];
    const float* dt_bias = (const float*)d_in[5];
    const float* A_log   = (const float*)d_in[6];
    const float* Dp      = (const float*)d_in[7];
    const float* ni_w    = (const float*)d_in[8];
    const float* out_W   = (const float*)d_in[9];
    float* out = (float*)d_out;

    cudaFuncSetAttribute(k_gemm1, cudaFuncAttributeMaxDynamicSharedMemorySize, SMEM_GEMM);
    cudaFuncSetAttribute(k_gemm2, cudaFuncAttributeMaxDynamicSharedMemorySize, SMEM_GEMM);
    cudaFuncSetAttribute(k_chunk, cudaFuncAttributeMaxDynamicSharedMemorySize, SMEM_K4);
    cudaFuncSetAttribute(k_inter, cudaFuncAttributeMaxDynamicSharedMemorySize, SMEM_K6);

    float* d_Win;  cudaGetSymbolAddress((void**)&d_Win, g_Win);
    float* d_Wout; cudaGetSymbolAddress((void**)&d_Wout, g_Wout);

    k_cvt<<<(PROJ * DM / 4 + 255) / 256, 256>>>(in_W, d_Win, PROJ * DM / 4);
    k_cvt<<<(DM * DI / 4 + 255) / 256, 256>>>(out_W, d_Wout, DM * DI / 4);
    k_rmsnorm<<<BL, 256>>>(x, norm_w);
    k_gemm1<<<dim3((PROJ + 127) / 128, BL / 128), 128, SMEM_GEMM>>>();
    k_conv<<<(BL * CDIM + 255) / 256, 256>>>(conv_w, conv_b);
    k_dt<<<(BL * HN + 255) / 256, 256>>>(dt_bias);
    k_chunk<<<Bq * NC * HN, 256, SMEM_K4>>>(A_log);
    k_scan<<<Bq * HN, 256>>>();
    k_inter<<<Bq * NC * HN, 256, SMEM_K6>>>(A_log, Dp);
    k_gate<<<BL, 256>>>(ni_w);
    k_gemm2<<<dim3(DM / 128, BL / 128), 128, SMEM_GEMM>>>(x, out);
}

// round 10
// speedup vs baseline: 4.5445x; 1.0098x over previous
#include <cuda_runtime.h>
#include <math.h>
#include <stdint.h>

#define Bq 4
#define Lq 2048
#define DM 1024
#define DI 2048
#define HN 32
#define HD 64
#define DS 128
#define CDIM 2304
#define PROJ 4384
#define CH 64
#define NC 32
#define BL 8192

// ---------------- scratch (device globals; no allocations) ----------------
__device__ float g_xn[BL * DM];                 // rmsnorm(x), tf32-rounded
__device__ float g_zx[(size_t)BL * PROJ];       // zxbcdt
__device__ float g_xBC[(size_t)BL * CDIM];      // conv+silu output
__device__ float g_dt[BL * HN];                 // softplus dt
__device__ float g_Y[(size_t)BL * DI];          // SSD output (Yd then +=Yo)
__device__ float g_states[(size_t)Bq * NC * HN * HD * DS];
__device__ float g_sin[(size_t)Bq * NC * HN * HD * DS];
__device__ float g_asum[Bq * HN * NC];
__device__ float g_yn[(size_t)BL * DI];         // gated+normed Y, tf32-rounded
__device__ float g_Win[(size_t)PROJ * DM];      // tf32-rounded in_proj_W
__device__ float g_Wout[(size_t)DM * DI];       // tf32-rounded out_proj_W

// ---------------- helpers ----------------
__device__ __forceinline__ float block_sum(float v) {
    __shared__ float red[8];
    #pragma unroll
    for (int o = 16; o; o >>= 1) v += __shfl_down_sync(0xffffffffu, v, o);
    if ((threadIdx.x & 31) == 0) red[threadIdx.x >> 5] = v;
    __syncthreads();
    if (threadIdx.x < 32) {
        v = (threadIdx.x < 8) ? red[threadIdx.x] : 0.f;
        #pragma unroll
        for (int o = 4; o; o >>= 1) v += __shfl_down_sync(0xffffffffu, v, o);
        if (threadIdx.x == 0) red[0] = v;
    }
    __syncthreads();
    return red[0];
}

__device__ __forceinline__ float f2tf(float x) {
    uint32_t u;
    asm("cvt.rna.tf32.f32 %0, %1;" : "=r"(u) : "f"(x));
    return __uint_as_float(u);
}

__device__ __forceinline__ void mma_tf32(float c[4], const uint32_t a[4], const uint32_t b[2]) {
    asm volatile(
        "mma.sync.aligned.m16n8k8.row.col.f32.tf32.tf32.f32 "
        "{%0,%1,%2,%3}, {%4,%5,%6,%7}, {%8,%9}, {%0,%1,%2,%3};"
        : "+f"(c[0]), "+f"(c[1]), "+f"(c[2]), "+f"(c[3])
        : "r"(a[0]), "r"(a[1]), "r"(a[2]), "r"(a[3]), "r"(b[0]), "r"(b[1]));
}

// ---------------- K0: tf32-round weights into scratch ----------------
__global__ void __launch_bounds__(256) k_cvt(const float* __restrict__ src,
                                             float* __restrict__ dst, int n4) {
    int i = blockIdx.x * 256 + threadIdx.x;
    if (i >= n4) return;
    float4 v = ((const float4*)src)[i];
    v.x = f2tf(v.x); v.y = f2tf(v.y); v.z = f2tf(v.z); v.w = f2tf(v.w);
    ((float4*)dst)[i] = v;
}

// ---------------- K1: rmsnorm(x) -> g_xn (tf32-rounded) ----------------
__global__ void __launch_bounds__(256) k_rmsnorm(const float* __restrict__ x,
                                                 const float* __restrict__ w) {
    int row = blockIdx.x;
    const float* xr = x + (size_t)row * DM;
    float s = 0.f;
    for (int i = threadIdx.x; i < DM; i += 256) { float v = xr[i]; s += v * v; }
    float tot = block_sum(s);
    float inv = rsqrtf(tot / DM + 1e-5f);
    for (int i = threadIdx.x; i < DM; i += 256)
        g_xn[(size_t)row * DM + i] = f2tf(xr[i] * inv * w[i]);
}

// ---------------- TF32 pipelined GEMM: C[M,N] = A[M,K]*B[N,K]^T (+Res) -----
// CTA 128x128, 4 warps (64x64 each), k-step 32, 2-stage cp.async pipeline,
// register double-buffered fragments to hide LDS latency behind mma issue.
#define SA_FLOATS (128 * 36)
#define SB_FLOATS (128 * 36)
#define STAGE_FLOATS (SA_FLOATS + SB_FLOATS)
#define NSTAGE 2
#define SMEM_GEMM (STAGE_FLOATS * NSTAGE * 4)   // 73728 bytes

__device__ __forceinline__ void stage_copy(const float* __restrict__ A,
                                           const float* __restrict__ Bw,
                                           float* sA, float* sB,
                                           int bm, int bn, int Nn, int K,
                                           int k0, int tid) {
    #pragma unroll
    for (int i = 0; i < 8; i++) {
        int c = tid + 128 * i;                 // 1024 16B chunks for A
        int row = c >> 3, col4 = (c & 7) * 4;
        uint32_t d = (uint32_t)__cvta_generic_to_shared(sA + row * 36 + col4);
        const float* g = A + (size_t)(bm + row) * K + k0 + col4;
        asm volatile("cp.async.cg.shared.global [%0], [%1], 16;" :: "r"(d), "l"(g));
    }
    #pragma unroll
    for (int i = 0; i < 8; i++) {
        int c = tid + 128 * i;                 // 1024 16B chunks for B
        int row = c >> 3, col4 = (c & 7) * 4;
        uint32_t d = (uint32_t)__cvta_generic_to_shared(sB + row * 36 + col4);
        int n = bn + row;
        int ok = (n < Nn);
        const float* g = Bw + (size_t)(ok ? n : 0) * K + k0 + col4;
        int sz = ok ? 16 : 0;
        asm volatile("cp.async.cg.shared.global [%0], [%1], 16, %2;" :: "r"(d), "l"(g), "r"(sz));
    }
}

__device__ __forceinline__ void load_frag(const float* sA, const float* sB,
                                          int kk, uint32_t af[4][4], uint32_t bf[8][2],
                                          int wm, int wn, int g, int t) {
    int k = kk * 8;
    #pragma unroll
    for (int im = 0; im < 4; im++) {
        int r0 = wm + im * 16 + g;
        af[im][0] = __float_as_uint(sA[r0 * 36 + k + t]);
        af[im][1] = __float_as_uint(sA[(r0 + 8) * 36 + k + t]);
        af[im][2] = __float_as_uint(sA[r0 * 36 + k + t + 4]);
        af[im][3] = __float_as_uint(sA[(r0 + 8) * 36 + k + t + 4]);
    }
    #pragma unroll
    for (int in = 0; in < 8; in++) {
        int n0 = wn + in * 8 + g;
        bf[in][0] = __float_as_uint(sB[n0 * 36 + k + t]);
        bf[in][1] = __float_as_uint(sB[n0 * 36 + k + t + 4]);
    }
}

__device__ __forceinline__ void stage_compute(const float* sA, const float* sB,
                                              float acc[4][8][4],
                                              int wm, int wn, int g, int t) {
    uint32_t af[2][4][4], bf[2][8][2];
    load_frag(sA, sB, 0, af[0], bf[0], wm, wn, g, t);
    #pragma unroll
    for (int kk = 0; kk < 4; kk++) {
        int cur = kk & 1;
        if (kk < 3)
            load_frag(sA, sB, kk + 1, af[cur ^ 1], bf[cur ^ 1], wm, wn, g, t);
        #pragma unroll
        for (int im = 0; im < 4; im++)
            #pragma unroll
            for (int in = 0; in < 8; in++)
                mma_tf32(acc[im][in], af[cur][im], bf[cur][in]);
    }
}

__device__ __forceinline__ void gemm_tf32_body(const float* __restrict__ A,
                                               const float* __restrict__ Bw,
                                               const float* __restrict__ Res,
                                               float* __restrict__ C,
                                               int M, int Nn, int K) {
    extern __shared__ float smp[];
    int bm = blockIdx.y * 128, bn = blockIdx.x * 128;
    int tid = threadIdx.x;
    int w = tid >> 5, lane = tid & 31, g = lane >> 2, t = lane & 3;
    int wm = (w >> 1) * 64, wn = (w & 1) * 64;

    float acc[4][8][4] = {};

    stage_copy(A, Bw, smp, smp + SA_FLOATS, bm, bn, Nn, K, 0, tid);
    asm volatile("cp.async.commit_group;");

    int nk = K / 32;
    for (int kt = 0; kt < nk; kt++) {
        asm volatile("cp.async.wait_group 0;");
        __syncthreads();
        if (kt + 1 < nk) {
            int s = (kt + 1) & 1;
            stage_copy(A, Bw, smp + s * STAGE_FLOATS, smp + s * STAGE_FLOATS + SA_FLOATS,
                       bm, bn, Nn, K, (kt + 1) * 32, tid);
            asm volatile("cp.async.commit_group;");
        }
        int cur = kt & 1;
        stage_compute(smp + cur * STAGE_FLOATS, smp + cur * STAGE_FLOATS + SA_FLOATS,
                      acc, wm, wn, g, t);
    }

    #pragma unroll
    for (int im = 0; im < 4; im++) {
        int row = bm + wm + im * 16 + g;
        #pragma unroll
        for (int in = 0; in < 8; in++) {
            int col = bn + wn + in * 8 + 2 * t;
            if (col < Nn) {
                size_t o0 = (size_t)row * Nn + col;
                size_t o1 = (size_t)(row + 8) * Nn + col;
                float v0 = acc[im][in][0], v1 = acc[im][in][1];
                float v2 = acc[im][in][2], v3 = acc[im][in][3];
                if (Res) {
                    v0 += Res[o0]; v1 += Res[o0 + 1];
                    v2 += Res[o1]; v3 += Res[o1 + 1];
                }
                C[o0] = v0; C[o0 + 1] = v1;
                C[o1] = v2; C[o1 + 1] = v3;
            }
        }
    }
}

__global__ void __launch_bounds__(128) k_gemm1() {
    gemm_tf32_body(g_xn, g_Win, nullptr, g_zx, BL, PROJ, DM);
}
__global__ void __launch_bounds__(128) k_gemm2(const float* __restrict__ x,
                                               float* __restrict__ out) {
    gemm_tf32_body(g_yn, g_Wout, x, out, BL, DM, DI);
}

// ---------------- K3: causal depthwise conv (w=4) + silu -> g_xBC ----------
__global__ void __launch_bounds__(256) k_conv(const float* __restrict__ cw,
                                              const float* __restrict__ cb) {
    int idx = blockIdx.x * 256 + threadIdx.x;
    if (idx >= BL * CDIM) return;
    int ch = idx % CDIM;
    int bl = idx / CDIM;
    int l = bl % Lq;
    float acc = cb[ch];
    #pragma unroll
    for (int k = 0; k < 4; k++) {
        int ls = l - 3 + k;
        if (ls >= 0)
            acc += g_zx[(size_t)(bl - l + ls) * PROJ + DI + ch] * cw[k * CDIM + ch];
    }
    acc = acc / (1.f + expf(-acc));
    g_xBC[(size_t)bl * CDIM + ch] = acc;
}

// ---------------- K3b: dt = softplus(raw + bias) ----------------
__global__ void __launch_bounds__(256) k_dt(const float* __restrict__ dt_bias) {
    int idx = blockIdx.x * 256 + threadIdx.x;
    if (idx >= BL * HN) return;
    int h = idx & 31;
    float v = g_zx[(size_t)(idx >> 5) * PROJ + DI + CDIM + h] + dt_bias[h];
    g_dt[idx] = (v > 20.f) ? v : log1pf(expf(v));
}

// ---------------- K4: intra-chunk via TF32 mma ----------------
#define SBSTR 132
#define SXSTR 68
#define OFF_C  0
#define OFF_B  8448
#define OFF_XT 16896
#define OFF_XD 21248
#define OFF_G  25600
#define OFF_BT 29952
#define SMEM_K4 ((29952 + 128 * 68) * 4)   // 154624 bytes

__global__ void __launch_bounds__(256) k_chunk(const float* __restrict__ A_log) {
    extern __shared__ float sm[];
    float* sC  = sm + OFF_C;
    float* sB  = sm + OFF_B;
    float* sXT = sm + OFF_XT;
    float* sXD = sm + OFF_XD;
    float* sG  = sm + OFF_G;
    float* sBT = sm + OFF_BT;
    __shared__ float sDt[64], sAc[64], sDec[64];

    int bid = blockIdx.x;
    int h = bid & 31, c = (bid >> 5) & 31, b = bid >> 10;
    int tid = threadIdx.x;
    int w = tid >> 5, lane = tid & 31, gq = lane >> 2, tq = lane & 3;
    float Aval = -expf(A_log[h]);
    int posBase = b * Lq + c * 64;

    if (tid < 64) sDt[tid] = g_dt[(posBase + tid) * HN + h];
    #pragma unroll
    for (int k = 0; k < 8; k++) {
        int e4 = tid + k * 256;
        int row = e4 >> 5, col = (e4 & 31) * 4;
        const float* base = &g_xBC[(size_t)(posBase + row) * CDIM + DI];
        float4 bv = *(const float4*)(base + col);
        float4 cv = *(const float4*)(base + DS + col);
        bv.x = f2tf(bv.x); bv.y = f2tf(bv.y); bv.z = f2tf(bv.z); bv.w = f2tf(bv.w);
        cv.x = f2tf(cv.x); cv.y = f2tf(cv.y); cv.z = f2tf(cv.z); cv.w = f2tf(cv.w);
        *(float4*)(sB + row * SBSTR + col) = bv;
        *(float4*)(sC + row * SBSTR + col) = cv;
    }
    __syncthreads();
    if (tid == 0) {
        float acc = 0.f;
        for (int s = 0; s < 64; s++) { acc += sDt[s] * Aval; sAc[s] = acc; }
    }
    #pragma unroll
    for (int k = 0; k < 32; k++) {
        int e = tid + k * 256;
        int n = e & 127, s = e >> 7;
        sBT[n * SXSTR + s] = sB[s * SBSTR + n];
    }
    __syncthreads();
    if (tid < 64) sDec[tid] = expf(sAc[63] - sAc[tid]);
    __syncthreads();
    #pragma unroll
    for (int k = 0; k < 16; k++) {
        int e = tid + k * 256;
        int p = e & 63, s = e >> 6;
        float xv = g_xBC[(size_t)(posBase + s) * CDIM + h * 64 + p] * sDt[s];
        sXT[p * SXSTR + s] = f2tf(xv);
        sXD[p * SXSTR + s] = f2tf(xv * sDec[s]);
    }
    __syncthreads();

    {
        int wm = (w >> 1) * 16, wn = (w & 1) * 32;
        float acc[4][4] = {};
        #pragma unroll
        for (int kk = 0; kk < 16; kk++) {
            int k = kk * 8;
            uint32_t af[4];
            int r0 = wm + gq;
            af[0] = __float_as_uint(sC[r0 * SBSTR + k + tq]);
            af[1] = __float_as_uint(sC[(r0 + 8) * SBSTR + k + tq]);
            af[2] = __float_as_uint(sC[r0 * SBSTR + k + tq + 4]);
            af[3] = __float_as_uint(sC[(r0 + 8) * SBSTR + k + tq + 4]);
            #pragma unroll
            for (int in = 0; in < 4; in++) {
                int n0 = wn + in * 8 + gq;
                uint32_t bf[2];
                bf[0] = __float_as_uint(sB[n0 * SBSTR + k + tq]);
                bf[1] = __float_as_uint(sB[n0 * SBSTR + k + tq + 4]);
                mma_tf32(acc[in], af, bf);
            }
        }
        int l0 = wm + gq, l1 = l0 + 8;
        float a0 = sAc[l0], a1 = sAc[l1];
        #pragma unroll
        for (int in = 0; in < 4; in++) {
            int s0 = wn + in * 8 + 2 * tq, s1 = s0 + 1;
            float as0 = sAc[s0], as1 = sAc[s1];
            sG[l0 * SXSTR + s0] = (l0 >= s0) ? f2tf(expf(a0 - as0) * acc[in][0]) : 0.f;
            sG[l0 * SXSTR + s1] = (l0 >= s1) ? f2tf(expf(a0 - as1) * acc[in][1]) : 0.f;
            sG[l1 * SXSTR + s0] = (l1 >= s0) ? f2tf(expf(a1 - as0) * acc[in][2]) : 0.f;
            sG[l1 * SXSTR + s1] = (l1 >= s1) ? f2tf(expf(a1 - as1) * acc[in][3]) : 0.f;
        }
    }
    __syncthreads();

    {
        int wm = (w >> 1) * 16, wn = (w & 1) * 32;
        float acc[4][4] = {};
        #pragma unroll
        for (int kk = 0; kk < 8; kk++) {
            int k = kk * 8;
            uint32_t af[4];
            int r0 = wm + gq;
            af[0] = __float_as_uint(sG[r0 * SXSTR + k + tq]);
            af[1] = __float_as_uint(sG[(r0 + 8) * SXSTR + k + tq]);
            af[2] = __float_as_uint(sG[r0 * SXSTR + k + tq + 4]);
            af[3] = __float_as_uint(sG[(r0 + 8) * SXSTR + k + tq + 4]);
            #pragma unroll
            for (int in = 0; in < 4; in++) {
                int n0 = wn + in * 8 + gq;
                uint32_t bf[2];
                bf[0] = __float_as_uint(sXT[n0 * SXSTR + k + tq]);
                bf[1] = __float_as_uint(sXT[n0 * SXSTR + k + tq + 4]);
                mma_tf32(acc[in], af, bf);
            }
        }
        int l0 = wm + gq, l1 = l0 + 8;
        float* y0 = &g_Y[(size_t)(posBase + l0) * DI + h * 64];
        float* y1 = &g_Y[(size_t)(posBase + l1) * DI + h * 64];
        #pragma unroll
        for (int in = 0; in < 4; in++) {
            int p0 = wn + in * 8 + 2 * tq;
            y0[p0] = acc[in][0]; y0[p0 + 1] = acc[in][1];
            y1[p0] = acc[in][2]; y1[p0 + 1] = acc[in][3];
        }
    }

    {
        int wm = (w >> 1) * 16, wn = (w & 1) * 64;
        float acc[8][4] = {};
        #pragma unroll
        for (int kk = 0; kk < 8; kk++) {
            int k = kk * 8;
            uint32_t af[4];
            int r0 = wm + gq;
            af[0] = __float_as_uint(sXD[r0 * SXSTR + k + tq]);
            af[1] = __float_as_uint(sXD[(r0 + 8) * SXSTR + k + tq]);
            af[2] = __float_as_uint(sXD[r0 * SXSTR + k + tq + 4]);
            af[3] = __float_as_uint(sXD[(r0 + 8) * SXSTR + k + tq + 4]);
            #pragma unroll
            for (int in = 0; in < 8; in++) {
                int n0 = wn + in * 8 + gq;
                uint32_t bf[2];
                bf[0] = __float_as_uint(sBT[n0 * SXSTR + k + tq]);
                bf[1] = __float_as_uint(sBT[n0 * SXSTR + k + tq + 4]);
                mma_tf32(acc[in], af, bf);
            }
        }
        size_t sbase = ((size_t)((b * NC + c) * HN + h)) * (64 * 128);
        int p0 = wm + gq, p1 = p0 + 8;
        #pragma unroll
        for (int in = 0; in < 8; in++) {
            int n0 = wn + in * 8 + 2 * tq;
            g_states[sbase + (size_t)p0 * 128 + n0]     = acc[in][0];
            g_states[sbase + (size_t)p0 * 128 + n0 + 1] = acc[in][1];
            g_states[sbase + (size_t)p1 * 128 + n0]     = acc[in][2];
            g_states[sbase + (size_t)p1 * 128 + n0 + 1] = acc[in][3];
        }
    }
    if (tid == 0) g_asum[(b * HN + h) * NC + c] = sAc[63];
}

// ---------------- K5: inter-chunk prefix scan (parallel: 1 float4/thread) --
// grid = Bq*HN*8 blocks of 256 threads; block j of a (b,h) pair owns float4
// elements [j*256, (j+1)*256) of the 2048-float4 state, scanning 32 chunks.
__global__ void __launch_bounds__(256) k_scan() {
    int bid = blockIdx.x;
    int seg = bid & 7;                  // 8 segments per (b,h)
    int bh = bid >> 3;
    int b = bh >> 5, h = bh & 31;
    int e = seg * 256 + threadIdx.x;    // float4 index within state
    const float* asum = &g_asum[(b * HN + h) * NC];
    float4 S = make_float4(0.f, 0.f, 0.f, 0.f);
    #pragma unroll 4
    for (int c = 0; c < NC; c++) {
        size_t base4 = ((size_t)((b * NC + c) * HN + h)) * 2048;
        float dec = expf(asum[c]);
        ((float4*)g_sin)[base4 + e] = S;
        float4 st = ((const float4*)g_states)[base4 + e];
        S.x = S.x * dec + st.x;
        S.y = S.y * dec + st.y;
        S.z = S.z * dec + st.z;
        S.w = S.w * dec + st.w;
    }
}

// ---------------- K6: Yo = exp(Ac) * C * S^T via mma; Y += Yo + xs*D -------
#define SMEM_K6 (8448 * 2 * 4)   // 67584 bytes
__global__ void __launch_bounds__(256) k_inter(const float* __restrict__ A_log,
                                               const float* __restrict__ Dp) {
    extern __shared__ float sm[];
    float* sC = sm;
    float* sS = sm + 8448;
    __shared__ float sDt[64], sAc[64];

    int bid = blockIdx.x;
    int h = bid & 31, c = (bid >> 5) & 31, b = bid >> 10;
    int tid = threadIdx.x;
    int w = tid >> 5, lane = tid & 31, gq = lane >> 2, tq = lane & 3;
    float Aval = -expf(A_log[h]);
    float Dv = Dp[h];
    int posBase = b * Lq + c * 64;

    if (tid < 64) sDt[tid] = g_dt[(posBase + tid) * HN + h];
    size_t sbase = ((size_t)((b * NC + c) * HN + h)) * 8192;
    #pragma unroll
    for (int k = 0; k < 8; k++) {
        int e4 = tid + k * 256;
        int row = e4 >> 5, col = (e4 & 31) * 4;
        float4 cv = *(const float4*)&g_xBC[(size_t)(posBase + row) * CDIM + DI + DS + col];
        float4 sv = *(const float4*)&g_sin[sbase + (size_t)row * 128 + col];
        cv.x = f2tf(cv.x); cv.y = f2tf(cv.y); cv.z = f2tf(cv.z); cv.w = f2tf(cv.w);
        sv.x = f2tf(sv.x); sv.y = f2tf(sv.y); sv.z = f2tf(sv.z); sv.w = f2tf(sv.w);
        *(float4*)(sC + row * SBSTR + col) = cv;
        *(float4*)(sS + row * SBSTR + col) = sv;
    }
    __syncthreads();
    if (tid == 0) {
        float acc = 0.f;
        for (int s = 0; s < 64; s++) { acc += sDt[s] * Aval; sAc[s] = acc; }
    }
    __syncthreads();

    int wm = (w >> 1) * 16, wn = (w & 1) * 32;
    float acc[4][4] = {};
    #pragma unroll
    for (int kk = 0; kk < 16; kk++) {
        int k = kk * 8;
        uint32_t af[4];
        int r0 = wm + gq;
        af[0] = __float_as_uint(sC[r0 * SBSTR + k + tq]);
        af[1] = __float_as_uint(sC[(r0 + 8) * SBSTR + k + tq]);
        af[2] = __float_as_uint(sC[r0 * SBSTR + k + tq + 4]);
        af[3] = __float_as_uint(sC[(r0 + 8) * SBSTR + k + tq + 4]);
        #pragma unroll
        for (int in = 0; in < 4; in++) {
            int n0 = wn + in * 8 + gq;
            uint32_t bf[2];
            bf[0] = __float_as_uint(sS[n0 * SBSTR + k + tq]);
            bf[1] = __float_as_uint(sS[n0 * SBSTR + k + tq + 4]);
            mma_tf32(acc[in], af, bf);
        }
    }
    int l0 = wm + gq, l1 = l0 + 8;
    float e0 = expf(sAc[l0]), e1 = expf(sAc[l1]);
    float* y0 = &g_Y[(size_t)(posBase + l0) * DI + h * 64];
    float* y1 = &g_Y[(size_t)(posBase + l1) * DI + h * 64];
    const float* x0 = &g_xBC[(size_t)(posBase + l0) * CDIM + h * 64];
    const float* x1 = &g_xBC[(size_t)(posBase + l1) * CDIM + h * 64];
    #pragma unroll
    for (int in = 0; in < 4; in++) {
        int p0 = wn + in * 8 + 2 * tq;
        y0[p0]     += e0 * acc[in][0] + x0[p0] * Dv;
        y0[p0 + 1] += e0 * acc[in][1] + x0[p0 + 1] * Dv;
        y1[p0]     += e1 * acc[in][2] + x1[p0] * Dv;
        y1[p0 + 1] += e1 * acc[in][3] + x1[p0 + 1] * Dv;
    }
}

// ---------------- K7: gated rmsnorm -> g_yn (tf32-rounded) ----------------
__global__ void __launch_bounds__(256) k_gate(const float* __restrict__ w) {
    __shared__ float sv[DI];
    int row = blockIdx.x;
    int tid = threadIdx.x;
    float s = 0.f;
    for (int i = tid; i < DI; i += 256) {
        float z = g_zx[(size_t)row * PROJ + i];
        float y = g_Y[(size_t)row * DI + i];
        float v = y * z / (1.f + expf(-z));
        sv[i] = v;
        s += v * v;
    }
    float tot = block_sum(s);
    float inv = rsqrtf(tot / DI + 1e-5f);
    for (int i = tid; i < DI; i += 256)
        g_yn[(size_t)row * DI + i] = f2tf(sv[i] * inv * w[i]);
}

// ---------------- launcher ----------------
extern "C" void kernel_launch(void* const* d_in, const int* in_sizes, int n_in,
                              void* d_out, int out_size) {
    const float* x       = (const float*)d_in[0];
    const float* norm_w  = (const float*)d_in[1];
    const float* in_W    = (const float*)d_in[2];
    const float* conv_w  = (const float*)d_in[3];
    const float* conv_b  = (const float*)d_in[4];
    const float* dt_bias = (const float*)d_in[5];
    const float* A_log   = (const float*)d_in[6];
    const float* Dp      = (const float*)d_in[7];
    const float* ni_w    = (const float*)d_in[8];
    const float* out_W   = (const float*)d_in[9];
    float* out = (float*)d_out;

    cudaFuncSetAttribute(k_gemm1, cudaFuncAttributeMaxDynamicSharedMemorySize, SMEM_GEMM);
    cudaFuncSetAttribute(k_gemm2, cudaFuncAttributeMaxDynamicSharedMemorySize, SMEM_GEMM);
    cudaFuncSetAttribute(k_chunk, cudaFuncAttributeMaxDynamicSharedMemorySize, SMEM_K4);
    cudaFuncSetAttribute(k_inter, cudaFuncAttributeMaxDynamicSharedMemorySize, SMEM_K6);

    float* d_Win;  cudaGetSymbolAddress((void**)&d_Win, g_Win);
    float* d_Wout; cudaGetSymbolAddress((void**)&d_Wout, g_Wout);

    k_cvt<<<(PROJ * DM / 4 + 255) / 256, 256>>>(in_W, d_Win, PROJ * DM / 4);
    k_cvt<<<(DM * DI / 4 + 255) / 256, 256>>>(out_W, d_Wout, DM * DI / 4);
    k_rmsnorm<<<BL, 256>>>(x, norm_w);
    k_gemm1<<<dim3((PROJ + 127) / 128, BL / 128), 128, SMEM_GEMM>>>();
    k_conv<<<(BL * CDIM + 255) / 256, 256>>>(conv_w, conv_b);
    k_dt<<<(BL * HN + 255) / 256, 256>>>(dt_bias);
    k_chunk<<<Bq * NC * HN, 256, SMEM_K4>>>(A_log);
    k_scan<<<Bq * HN * 8, 256>>>();
    k_inter<<<Bq * NC * HN, 256, SMEM_K6>>>(A_log, Dp);
    k_gate<<<BL, 256>>>(ni_w);
    k_gemm2<<<dim3(DM / 128, BL / 128), 128, SMEM_GEMM>>>(x, out);
}

// round 11
// speedup vs baseline: 4.5840x; 1.0087x over previous
#include <cuda_runtime.h>
#include <math.h>
#include <stdint.h>

#define Bq 4
#define Lq 2048
#define DM 1024
#define DI 2048
#define HN 32
#define HD 64
#define DS 128
#define CDIM 2304
#define PROJ 4384
#define CH 64
#define NC 32
#define BL 8192

// ---------------- scratch (device globals; no allocations) ----------------
__device__ float g_xn[BL * DM];                 // rmsnorm(x), tf32-rounded
__device__ float g_zx[(size_t)BL * PROJ];       // zxbcdt
__device__ float g_xBC[(size_t)BL * CDIM];      // conv+silu output
__device__ float g_dt[BL * HN];                 // softplus dt
__device__ float g_Y[(size_t)BL * DI];          // SSD output (Yd then +=Yo)
__device__ float g_states[(size_t)Bq * NC * HN * HD * DS];
__device__ float g_sin[(size_t)Bq * NC * HN * HD * DS];
__device__ float g_asum[Bq * HN * NC];
__device__ float g_yn[(size_t)BL * DI];         // gated+normed Y, tf32-rounded
__device__ float g_Win[(size_t)PROJ * DM];      // tf32-rounded in_proj_W
__device__ float g_Wout[(size_t)DM * DI];       // tf32-rounded out_proj_W

// ---------------- helpers ----------------
__device__ __forceinline__ float block_sum(float v) {
    __shared__ float red[8];
    #pragma unroll
    for (int o = 16; o; o >>= 1) v += __shfl_down_sync(0xffffffffu, v, o);
    if ((threadIdx.x & 31) == 0) red[threadIdx.x >> 5] = v;
    __syncthreads();
    if (threadIdx.x < 32) {
        v = (threadIdx.x < 8) ? red[threadIdx.x] : 0.f;
        #pragma unroll
        for (int o = 4; o; o >>= 1) v += __shfl_down_sync(0xffffffffu, v, o);
        if (threadIdx.x == 0) red[0] = v;
    }
    __syncthreads();
    return red[0];
}

__device__ __forceinline__ float f2tf(float x) {
    uint32_t u;
    asm("cvt.rna.tf32.f32 %0, %1;" : "=r"(u) : "f"(x));
    return __uint_as_float(u);
}

__device__ __forceinline__ void mma_tf32(float c[4], const uint32_t a[4], const uint32_t b[2]) {
    asm volatile(
        "mma.sync.aligned.m16n8k8.row.col.f32.tf32.tf32.f32 "
        "{%0,%1,%2,%3}, {%4,%5,%6,%7}, {%8,%9}, {%0,%1,%2,%3};"
        : "+f"(c[0]), "+f"(c[1]), "+f"(c[2]), "+f"(c[3])
        : "r"(a[0]), "r"(a[1]), "r"(a[2]), "r"(a[3]), "r"(b[0]), "r"(b[1]));
}

// ---------------- K0: tf32-round weights into scratch ----------------
__global__ void __launch_bounds__(256) k_cvt(const float* __restrict__ src,
                                             float* __restrict__ dst, int n4) {
    int i = blockIdx.x * 256 + threadIdx.x;
    if (i >= n4) return;
    float4 v = ((const float4*)src)[i];
    v.x = f2tf(v.x); v.y = f2tf(v.y); v.z = f2tf(v.z); v.w = f2tf(v.w);
    ((float4*)dst)[i] = v;
}

// ---------------- K1: rmsnorm(x) -> g_xn (tf32-rounded) ----------------
__global__ void __launch_bounds__(256) k_rmsnorm(const float* __restrict__ x,
                                                 const float* __restrict__ w) {
    int row = blockIdx.x;
    const float* xr = x + (size_t)row * DM;
    float s = 0.f;
    for (int i = threadIdx.x; i < DM; i += 256) { float v = xr[i]; s += v * v; }
    float tot = block_sum(s);
    float inv = rsqrtf(tot / DM + 1e-5f);
    for (int i = threadIdx.x; i < DM; i += 256)
        g_xn[(size_t)row * DM + i] = f2tf(xr[i] * inv * w[i]);
}

// ---------------- TF32 pipelined GEMM: C[M,N] = A[M,K]*B[N,K]^T (+Res) -----
#define SA_FLOATS (128 * 36)
#define SB_FLOATS (128 * 36)
#define STAGE_FLOATS (SA_FLOATS + SB_FLOATS)
#define NSTAGE 2
#define SMEM_GEMM (STAGE_FLOATS * NSTAGE * 4)   // 73728 bytes

__device__ __forceinline__ void stage_copy(const float* __restrict__ A,
                                           const float* __restrict__ Bw,
                                           float* sA, float* sB,
                                           int bm, int bn, int Nn, int K,
                                           int k0, int tid) {
    #pragma unroll
    for (int i = 0; i < 8; i++) {
        int c = tid + 128 * i;
        int row = c >> 3, col4 = (c & 7) * 4;
        uint32_t d = (uint32_t)__cvta_generic_to_shared(sA + row * 36 + col4);
        const float* g = A + (size_t)(bm + row) * K + k0 + col4;
        asm volatile("cp.async.cg.shared.global [%0], [%1], 16;" :: "r"(d), "l"(g));
    }
    #pragma unroll
    for (int i = 0; i < 8; i++) {
        int c = tid + 128 * i;
        int row = c >> 3, col4 = (c & 7) * 4;
        uint32_t d = (uint32_t)__cvta_generic_to_shared(sB + row * 36 + col4);
        int n = bn + row;
        int ok = (n < Nn);
        const float* g = Bw + (size_t)(ok ? n : 0) * K + k0 + col4;
        int sz = ok ? 16 : 0;
        asm volatile("cp.async.cg.shared.global [%0], [%1], 16, %2;" :: "r"(d), "l"(g), "r"(sz));
    }
}

__device__ __forceinline__ void load_frag(const float* sA, const float* sB,
                                          int kk, uint32_t af[4][4], uint32_t bf[8][2],
                                          int wm, int wn, int g, int t) {
    int k = kk * 8;
    #pragma unroll
    for (int im = 0; im < 4; im++) {
        int r0 = wm + im * 16 + g;
        af[im][0] = __float_as_uint(sA[r0 * 36 + k + t]);
        af[im][1] = __float_as_uint(sA[(r0 + 8) * 36 + k + t]);
        af[im][2] = __float_as_uint(sA[r0 * 36 + k + t + 4]);
        af[im][3] = __float_as_uint(sA[(r0 + 8) * 36 + k + t + 4]);
    }
    #pragma unroll
    for (int in = 0; in < 8; in++) {
        int n0 = wn + in * 8 + g;
        bf[in][0] = __float_as_uint(sB[n0 * 36 + k + t]);
        bf[in][1] = __float_as_uint(sB[n0 * 36 + k + t + 4]);
    }
}

__device__ __forceinline__ void stage_compute(const float* sA, const float* sB,
                                              float acc[4][8][4],
                                              int wm, int wn, int g, int t) {
    uint32_t af[2][4][4], bf[2][8][2];
    load_frag(sA, sB, 0, af[0], bf[0], wm, wn, g, t);
    #pragma unroll
    for (int kk = 0; kk < 4; kk++) {
        int cur = kk & 1;
        if (kk < 3)
            load_frag(sA, sB, kk + 1, af[cur ^ 1], bf[cur ^ 1], wm, wn, g, t);
        #pragma unroll
        for (int im = 0; im < 4; im++)
            #pragma unroll
            for (int in = 0; in < 8; in++)
                mma_tf32(acc[im][in], af[cur][im], bf[cur][in]);
    }
}

__device__ __forceinline__ void gemm_tf32_body(const float* __restrict__ A,
                                               const float* __restrict__ Bw,
                                               const float* __restrict__ Res,
                                               float* __restrict__ C,
                                               int M, int Nn, int K) {
    extern __shared__ float smp[];
    int bm = blockIdx.y * 128, bn = blockIdx.x * 128;
    int tid = threadIdx.x;
    int w = tid >> 5, lane = tid & 31, g = lane >> 2, t = lane & 3;
    int wm = (w >> 1) * 64, wn = (w & 1) * 64;

    float acc[4][8][4] = {};

    stage_copy(A, Bw, smp, smp + SA_FLOATS, bm, bn, Nn, K, 0, tid);
    asm volatile("cp.async.commit_group;");

    int nk = K / 32;
    for (int kt = 0; kt < nk; kt++) {
        asm volatile("cp.async.wait_group 0;");
        __syncthreads();
        if (kt + 1 < nk) {
            int s = (kt + 1) & 1;
            stage_copy(A, Bw, smp + s * STAGE_FLOATS, smp + s * STAGE_FLOATS + SA_FLOATS,
                       bm, bn, Nn, K, (kt + 1) * 32, tid);
            asm volatile("cp.async.commit_group;");
        }
        int cur = kt & 1;
        stage_compute(smp + cur * STAGE_FLOATS, smp + cur * STAGE_FLOATS + SA_FLOATS,
                      acc, wm, wn, g, t);
    }

    #pragma unroll
    for (int im = 0; im < 4; im++) {
        int row = bm + wm + im * 16 + g;
        #pragma unroll
        for (int in = 0; in < 8; in++) {
            int col = bn + wn + in * 8 + 2 * t;
            if (col < Nn) {
                size_t o0 = (size_t)row * Nn + col;
                size_t o1 = (size_t)(row + 8) * Nn + col;
                float v0 = acc[im][in][0], v1 = acc[im][in][1];
                float v2 = acc[im][in][2], v3 = acc[im][in][3];
                if (Res) {
                    v0 += Res[o0]; v1 += Res[o0 + 1];
                    v2 += Res[o1]; v3 += Res[o1 + 1];
                }
                C[o0] = v0; C[o0 + 1] = v1;
                C[o1] = v2; C[o1 + 1] = v3;
            }
        }
    }
}

__global__ void __launch_bounds__(128) k_gemm1() {
    gemm_tf32_body(g_xn, g_Win, nullptr, g_zx, BL, PROJ, DM);
}
__global__ void __launch_bounds__(128) k_gemm2(const float* __restrict__ x,
                                               float* __restrict__ out) {
    gemm_tf32_body(g_yn, g_Wout, x, out, BL, DM, DI);
}

// ---------------- K3: tiled causal depthwise conv (w=4) + silu -> g_xBC ----
// Block: 32 l-positions x 128 channels. Stage (32+3)x128 floats in smem once.
#define CTL 32
#define CTC 128
__global__ void __launch_bounds__(256) k_conv(const float* __restrict__ cw,
                                              const float* __restrict__ cb) {
    __shared__ float s[(CTL + 3) * CTC];
    int ct = blockIdx.x * CTC;          // channel tile base
    int blt = blockIdx.y * CTL;         // global (b*Lq + l) base, tile-aligned
    int l0 = blt & (Lq - 1);            // l within batch (Lq pow2)
    int tid = threadIdx.x;

    // stage rows l0-3 .. l0+31 (zeros before batch start)
    for (int idx = tid; idx < (CTL + 3) * CTC; idx += 256) {
        int r = (idx >> 7) - 3;         // -3..31
        int ch = idx & 127;
        float v = 0.f;
        if (l0 + r >= 0)
            v = g_zx[(size_t)(blt + r) * PROJ + DI + ct + ch];
        s[idx] = v;
    }
    __syncthreads();

    int ch = tid & 127;
    int li0 = (tid >> 7) * 16;          // 0 or 16
    float w0 = cw[0 * CDIM + ct + ch];
    float w1 = cw[1 * CDIM + ct + ch];
    float w2 = cw[2 * CDIM + ct + ch];
    float w3 = cw[3 * CDIM + ct + ch];
    float bias = cb[ct + ch];

    #pragma unroll
    for (int i = 0; i < 16; i++) {
        int li = li0 + i;
        float acc = bias
                  + w0 * s[li * CTC + ch]
                  + w1 * s[(li + 1) * CTC + ch]
                  + w2 * s[(li + 2) * CTC + ch]
                  + w3 * s[(li + 3) * CTC + ch];
        acc = acc / (1.f + expf(-acc));
        g_xBC[(size_t)(blt + li) * CDIM + ct + ch] = acc;
    }
}

// ---------------- K3b: dt = softplus(raw + bias) ----------------
__global__ void __launch_bounds__(256) k_dt(const float* __restrict__ dt_bias) {
    int idx = blockIdx.x * 256 + threadIdx.x;
    if (idx >= BL * HN) return;
    int h = idx & 31;
    float v = g_zx[(size_t)(idx >> 5) * PROJ + DI + CDIM + h] + dt_bias[h];
    g_dt[idx] = (v > 20.f) ? v : log1pf(expf(v));
}

// ---------------- K4: intra-chunk via TF32 mma ----------------
#define SBSTR 132
#define SXSTR 68
#define OFF_C  0
#define OFF_B  8448
#define OFF_XT 16896
#define OFF_XD 21248
#define OFF_G  25600
#define OFF_BT 29952
#define SMEM_K4 ((29952 + 128 * 68) * 4)   // 154624 bytes

__global__ void __launch_bounds__(256) k_chunk(const float* __restrict__ A_log) {
    extern __shared__ float sm[];
    float* sC  = sm + OFF_C;
    float* sB  = sm + OFF_B;
    float* sXT = sm + OFF_XT;
    float* sXD = sm + OFF_XD;
    float* sG  = sm + OFF_G;
    float* sBT = sm + OFF_BT;
    __shared__ float sDt[64], sAc[64], sDec[64];

    int bid = blockIdx.x;
    int h = bid & 31, c = (bid >> 5) & 31, b = bid >> 10;
    int tid = threadIdx.x;
    int w = tid >> 5, lane = tid & 31, gq = lane >> 2, tq = lane & 3;
    float Aval = -expf(A_log[h]);
    int posBase = b * Lq + c * 64;

    if (tid < 64) sDt[tid] = g_dt[(posBase + tid) * HN + h];
    #pragma unroll
    for (int k = 0; k < 8; k++) {
        int e4 = tid + k * 256;
        int row = e4 >> 5, col = (e4 & 31) * 4;
        const float* base = &g_xBC[(size_t)(posBase + row) * CDIM + DI];
        float4 bv = *(const float4*)(base + col);
        float4 cv = *(const float4*)(base + DS + col);
        bv.x = f2tf(bv.x); bv.y = f2tf(bv.y); bv.z = f2tf(bv.z); bv.w = f2tf(bv.w);
        cv.x = f2tf(cv.x); cv.y = f2tf(cv.y); cv.z = f2tf(cv.z); cv.w = f2tf(cv.w);
        *(float4*)(sB + row * SBSTR + col) = bv;
        *(float4*)(sC + row * SBSTR + col) = cv;
    }
    __syncthreads();
    if (tid == 0) {
        float acc = 0.f;
        for (int s = 0; s < 64; s++) { acc += sDt[s] * Aval; sAc[s] = acc; }
    }
    #pragma unroll
    for (int k = 0; k < 32; k++) {
        int e = tid + k * 256;
        int n = e & 127, s = e >> 7;
        sBT[n * SXSTR + s] = sB[s * SBSTR + n];
    }
    __syncthreads();
    if (tid < 64) sDec[tid] = expf(sAc[63] - sAc[tid]);
    __syncthreads();
    #pragma unroll
    for (int k = 0; k < 16; k++) {
        int e = tid + k * 256;
        int p = e & 63, s = e >> 6;
        float xv = g_xBC[(size_t)(posBase + s) * CDIM + h * 64 + p] * sDt[s];
        sXT[p * SXSTR + s] = f2tf(xv);
        sXD[p * SXSTR + s] = f2tf(xv * sDec[s]);
    }
    __syncthreads();

    {
        int wm = (w >> 1) * 16, wn = (w & 1) * 32;
        float acc[4][4] = {};
        #pragma unroll
        for (int kk = 0; kk < 16; kk++) {
            int k = kk * 8;
            uint32_t af[4];
            int r0 = wm + gq;
            af[0] = __float_as_uint(sC[r0 * SBSTR + k + tq]);
            af[1] = __float_as_uint(sC[(r0 + 8) * SBSTR + k + tq]);
            af[2] = __float_as_uint(sC[r0 * SBSTR + k + tq + 4]);
            af[3] = __float_as_uint(sC[(r0 + 8) * SBSTR + k + tq + 4]);
            #pragma unroll
            for (int in = 0; in < 4; in++) {
                int n0 = wn + in * 8 + gq;
                uint32_t bf[2];
                bf[0] = __float_as_uint(sB[n0 * SBSTR + k + tq]);
                bf[1] = __float_as_uint(sB[n0 * SBSTR + k + tq + 4]);
                mma_tf32(acc[in], af, bf);
            }
        }
        int l0 = wm + gq, l1 = l0 + 8;
        float a0 = sAc[l0], a1 = sAc[l1];
        #pragma unroll
        for (int in = 0; in < 4; in++) {
            int s0 = wn + in * 8 + 2 * tq, s1 = s0 + 1;
            float as0 = sAc[s0], as1 = sAc[s1];
            sG[l0 * SXSTR + s0] = (l0 >= s0) ? f2tf(expf(a0 - as0) * acc[in][0]) : 0.f;
            sG[l0 * SXSTR + s1] = (l0 >= s1) ? f2tf(expf(a0 - as1) * acc[in][1]) : 0.f;
            sG[l1 * SXSTR + s0] = (l1 >= s0) ? f2tf(expf(a1 - as0) * acc[in][2]) : 0.f;
            sG[l1 * SXSTR + s1] = (l1 >= s1) ? f2tf(expf(a1 - as1) * acc[in][3]) : 0.f;
        }
    }
    __syncthreads();

    {
        int wm = (w >> 1) * 16, wn = (w & 1) * 32;
        float acc[4][4] = {};
        #pragma unroll
        for (int kk = 0; kk < 8; kk++) {
            int k = kk * 8;
            uint32_t af[4];
            int r0 = wm + gq;
            af[0] = __float_as_uint(sG[r0 * SXSTR + k + tq]);
            af[1] = __float_as_uint(sG[(r0 + 8) * SXSTR + k + tq]);
            af[2] = __float_as_uint(sG[r0 * SXSTR + k + tq + 4]);
            af[3] = __float_as_uint(sG[(r0 + 8) * SXSTR + k + tq + 4]);
            #pragma unroll
            for (int in = 0; in < 4; in++) {
                int n0 = wn + in * 8 + gq;
                uint32_t bf[2];
                bf[0] = __float_as_uint(sXT[n0 * SXSTR + k + tq]);
                bf[1] = __float_as_uint(sXT[n0 * SXSTR + k + tq + 4]);
                mma_tf32(acc[in], af, bf);
            }
        }
        int l0 = wm + gq, l1 = l0 + 8;
        float* y0 = &g_Y[(size_t)(posBase + l0) * DI + h * 64];
        float* y1 = &g_Y[(size_t)(posBase + l1) * DI + h * 64];
        #pragma unroll
        for (int in = 0; in < 4; in++) {
            int p0 = wn + in * 8 + 2 * tq;
            y0[p0] = acc[in][0]; y0[p0 + 1] = acc[in][1];
            y1[p0] = acc[in][2]; y1[p0 + 1] = acc[in][3];
        }
    }

    {
        int wm = (w >> 1) * 16, wn = (w & 1) * 64;
        float acc[8][4] = {};
        #pragma unroll
        for (int kk = 0; kk < 8; kk++) {
            int k = kk * 8;
            uint32_t af[4];
            int r0 = wm + gq;
            af[0] = __float_as_uint(sXD[r0 * SXSTR + k + tq]);
            af[1] = __float_as_uint(sXD[(r0 + 8) * SXSTR + k + tq]);
            af[2] = __float_as_uint(sXD[r0 * SXSTR + k + tq + 4]);
            af[3] = __float_as_uint(sXD[(r0 + 8) * SXSTR + k + tq + 4]);
            #pragma unroll
            for (int in = 0; in < 8; in++) {
                int n0 = wn + in * 8 + gq;
                uint32_t bf[2];
                bf[0] = __float_as_uint(sBT[n0 * SXSTR + k + tq]);
                bf[1] = __float_as_uint(sBT[n0 * SXSTR + k + tq + 4]);
                mma_tf32(acc[in], af, bf);
            }
        }
        size_t sbase = ((size_t)((b * NC + c) * HN + h)) * (64 * 128);
        int p0 = wm + gq, p1 = p0 + 8;
        #pragma unroll
        for (int in = 0; in < 8; in++) {
            int n0 = wn + in * 8 + 2 * tq;
            g_states[sbase + (size_t)p0 * 128 + n0]     = acc[in][0];
            g_states[sbase + (size_t)p0 * 128 + n0 + 1] = acc[in][1];
            g_states[sbase + (size_t)p1 * 128 + n0]     = acc[in][2];
            g_states[sbase + (size_t)p1 * 128 + n0 + 1] = acc[in][3];
        }
    }
    if (tid == 0) g_asum[(b * HN + h) * NC + c] = sAc[63];
}

// ---------------- K5: inter-chunk prefix scan (parallel: 1 float4/thread) --
__global__ void __launch_bounds__(256) k_scan() {
    int bid = blockIdx.x;
    int seg = bid & 7;
    int bh = bid >> 3;
    int b = bh >> 5, h = bh & 31;
    int e = seg * 256 + threadIdx.x;
    const float* asum = &g_asum[(b * HN + h) * NC];
    float4 S = make_float4(0.f, 0.f, 0.f, 0.f);
    #pragma unroll 4
    for (int c = 0; c < NC; c++) {
        size_t base4 = ((size_t)((b * NC + c) * HN + h)) * 2048;
        float dec = expf(asum[c]);
        ((float4*)g_sin)[base4 + e] = S;
        float4 st = ((const float4*)g_states)[base4 + e];
        S.x = S.x * dec + st.x;
        S.y = S.y * dec + st.y;
        S.z = S.z * dec + st.z;
        S.w = S.w * dec + st.w;
    }
}

// ---------------- K6: Yo = exp(Ac) * C * S^T via mma; Y += Yo + xs*D -------
#define SMEM_K6 (8448 * 2 * 4)   // 67584 bytes
__global__ void __launch_bounds__(256) k_inter(const float* __restrict__ A_log,
                                               const float* __restrict__ Dp) {
    extern __shared__ float sm[];
    float* sC = sm;
    float* sS = sm + 8448;
    __shared__ float sDt[64], sAc[64];

    int bid = blockIdx.x;
    int h = bid & 31, c = (bid >> 5) & 31, b = bid >> 10;
    int tid = threadIdx.x;
    int w = tid >> 5, lane = tid & 31, gq = lane >> 2, tq = lane & 3;
    float Aval = -expf(A_log[h]);
    float Dv = Dp[h];
    int posBase = b * Lq + c * 64;

    if (tid < 64) sDt[tid] = g_dt[(posBase + tid) * HN + h];
    size_t sbase = ((size_t)((b * NC + c) * HN + h)) * 8192;
    #pragma unroll
    for (int k = 0; k < 8; k++) {
        int e4 = tid + k * 256;
        int row = e4 >> 5, col = (e4 & 31) * 4;
        float4 cv = *(const float4*)&g_xBC[(size_t)(posBase + row) * CDIM + DI + DS + col];
        float4 sv = *(const float4*)&g_sin[sbase + (size_t)row * 128 + col];
        cv.x = f2tf(cv.x); cv.y = f2tf(cv.y); cv.z = f2tf(cv.z); cv.w = f2tf(cv.w);
        sv.x = f2tf(sv.x); sv.y = f2tf(sv.y); sv.z = f2tf(sv.z); sv.w = f2tf(sv.w);
        *(float4*)(sC + row * SBSTR + col) = cv;
        *(float4*)(sS + row * SBSTR + col) = sv;
    }
    __syncthreads();
    if (tid == 0) {
        float acc = 0.f;
        for (int s = 0; s < 64; s++) { acc += sDt[s] * Aval; sAc[s] = acc; }
    }
    __syncthreads();

    int wm = (w >> 1) * 16, wn = (w & 1) * 32;
    float acc[4][4] = {};
    #pragma unroll
    for (int kk = 0; kk < 16; kk++) {
        int k = kk * 8;
        uint32_t af[4];
        int r0 = wm + gq;
        af[0] = __float_as_uint(sC[r0 * SBSTR + k + tq]);
        af[1] = __float_as_uint(sC[(r0 + 8) * SBSTR + k + tq]);
        af[2] = __float_as_uint(sC[r0 * SBSTR + k + tq + 4]);
        af[3] = __float_as_uint(sC[(r0 + 8) * SBSTR + k + tq + 4]);
        #pragma unroll
        for (int in = 0; in < 4; in++) {
            int n0 = wn + in * 8 + gq;
            uint32_t bf[2];
            bf[0] = __float_as_uint(sS[n0 * SBSTR + k + tq]);
            bf[1] = __float_as_uint(sS[n0 * SBSTR + k + tq + 4]);
            mma_tf32(acc[in], af, bf);
        }
    }
    int l0 = wm + gq, l1 = l0 + 8;
    float e0 = expf(sAc[l0]), e1 = expf(sAc[l1]);
    float* y0 = &g_Y[(size_t)(posBase + l0) * DI + h * 64];
    float* y1 = &g_Y[(size_t)(posBase + l1) * DI + h * 64];
    const float* x0 = &g_xBC[(size_t)(posBase + l0) * CDIM + h * 64];
    const float* x1 = &g_xBC[(size_t)(posBase + l1) * CDIM + h * 64];
    #pragma unroll
    for (int in = 0; in < 4; in++) {
        int p0 = wn + in * 8 + 2 * tq;
        y0[p0]     += e0 * acc[in][0] + x0[p0] * Dv;
        y0[p0 + 1] += e0 * acc[in][1] + x0[p0 + 1] * Dv;
        y1[p0]     += e1 * acc[in][2] + x1[p0] * Dv;
        y1[p0 + 1] += e1 * acc[in][3] + x1[p0 + 1] * Dv;
    }
}

// ---------------- K7: gated rmsnorm -> g_yn (tf32-rounded) ----------------
__global__ void __launch_bounds__(256) k_gate(const float* __restrict__ w) {
    __shared__ float sv[DI];
    int row = blockIdx.x;
    int tid = threadIdx.x;
    float s = 0.f;
    for (int i = tid; i < DI; i += 256) {
        float z = g_zx[(size_t)row * PROJ + i];
        float y = g_Y[(size_t)row * DI + i];
        float v = y * z / (1.f + expf(-z));
        sv[i] = v;
        s += v * v;
    }
    float tot = block_sum(s);
    float inv = rsqrtf(tot / DI + 1e-5f);
    for (int i = tid; i < DI; i += 256)
        g_yn[(size_t)row * DI + i] = f2tf(sv[i] * inv * w[i]);
}

// ---------------- launcher ----------------
extern "C" void kernel_launch(void* const* d_in, const int* in_sizes, int n_in,
                              void* d_out, int out_size) {
    const float* x       = (const float*)d_in[0];
    const float* norm_w  = (const float*)d_in[1];
    const float* in_W    = (const float*)d_in[2];
    const float* conv_w  = (const float*)d_in[3];
    const float* conv_b  = (const float*)d_in[4];
    const float* dt_bias = (const float*)d_in[5];
    const float* A_log   = (const float*)d_in[6];
    const float* Dp      = (const float*)d_in[7];
    const float* ni_w    = (const float*)d_in[8];
    const float* out_W   = (const float*)d_in[9];
    float* out = (float*)d_out;

    cudaFuncSetAttribute(k_gemm1, cudaFuncAttributeMaxDynamicSharedMemorySize, SMEM_GEMM);
    cudaFuncSetAttribute(k_gemm2, cudaFuncAttributeMaxDynamicSharedMemorySize, SMEM_GEMM);
    cudaFuncSetAttribute(k_chunk, cudaFuncAttributeMaxDynamicSharedMemorySize, SMEM_K4);
    cudaFuncSetAttribute(k_inter, cudaFuncAttributeMaxDynamicSharedMemorySize, SMEM_K6);

    float* d_Win;  cudaGetSymbolAddress((void**)&d_Win, g_Win);
    float* d_Wout; cudaGetSymbolAddress((void**)&d_Wout, g_Wout);

    k_cvt<<<(PROJ * DM / 4 + 255) / 256, 256>>>(in_W, d_Win, PROJ * DM / 4);
    k_cvt<<<(DM * DI / 4 + 255) / 256, 256>>>(out_W, d_Wout, DM * DI / 4);
    k_rmsnorm<<<BL, 256>>>(x, norm_w);
    k_gemm1<<<dim3((PROJ + 127) / 128, BL / 128), 128, SMEM_GEMM>>>();
    k_conv<<<dim3(CDIM / CTC, BL / CTL), 256>>>(conv_w, conv_b);
    k_dt<<<(BL * HN + 255) / 256, 256>>>(dt_bias);
    k_chunk<<<Bq * NC * HN, 256, SMEM_K4>>>(A_log);
    k_scan<<<Bq * HN * 8, 256>>>();
    k_inter<<<Bq * NC * HN, 256, SMEM_K6>>>(A_log, Dp);
    k_gate<<<BL, 256>>>(ni_w);
    k_gemm2<<<dim3(DM / 128, BL / 128), 128, SMEM_GEMM>>>(x, out);
}

// round 12
// speedup vs baseline: 5.7705x; 1.2588x over previous
#include <cuda_runtime.h>
#include <cuda_fp16.h>
#include <math.h>
#include <stdint.h>

#define Bq 4
#define Lq 2048
#define DM 1024
#define DI 2048
#define HN 32
#define HD 64
#define DS 128
#define CDIM 2304
#define PROJ 4384
#define CH 64
#define NC 32
#define BL 8192

// ---------------- scratch (device globals; no allocations) ----------------
__device__ __half g_xnh[(size_t)BL * DM];       // rmsnorm(x), fp16
__device__ float g_zx[(size_t)BL * PROJ];       // zxbcdt
__device__ float g_xBC[(size_t)BL * CDIM];      // conv+silu output
__device__ float g_dt[BL * HN];                 // softplus dt
__device__ float g_Y[(size_t)BL * DI];          // SSD output (Yd then +=Yo)
__device__ float g_states[(size_t)Bq * NC * HN * HD * DS];
__device__ float g_sin[(size_t)Bq * NC * HN * HD * DS];
__device__ float g_asum[Bq * HN * NC];
__device__ __half g_ynh[(size_t)BL * DI];       // gated+normed Y, fp16
__device__ __half g_Winh[(size_t)PROJ * DM];    // fp16 in_proj_W
__device__ __half g_Wouth[(size_t)DM * DI];     // fp16 out_proj_W

// ---------------- helpers ----------------
__device__ __forceinline__ float block_sum(float v) {
    __shared__ float red[8];
    #pragma unroll
    for (int o = 16; o; o >>= 1) v += __shfl_down_sync(0xffffffffu, v, o);
    if ((threadIdx.x & 31) == 0) red[threadIdx.x >> 5] = v;
    __syncthreads();
    if (threadIdx.x < 32) {
        v = (threadIdx.x < 8) ? red[threadIdx.x] : 0.f;
        #pragma unroll
        for (int o = 4; o; o >>= 1) v += __shfl_down_sync(0xffffffffu, v, o);
        if (threadIdx.x == 0) red[0] = v;
    }
    __syncthreads();
    return red[0];
}

__device__ __forceinline__ float f2tf(float x) {
    uint32_t u;
    asm("cvt.rna.tf32.f32 %0, %1;" : "=r"(u) : "f"(x));
    return __uint_as_float(u);
}

__device__ __forceinline__ void mma_tf32(float c[4], const uint32_t a[4], const uint32_t b[2]) {
    asm volatile(
        "mma.sync.aligned.m16n8k8.row.col.f32.tf32.tf32.f32 "
        "{%0,%1,%2,%3}, {%4,%5,%6,%7}, {%8,%9}, {%0,%1,%2,%3};"
        : "+f"(c[0]), "+f"(c[1]), "+f"(c[2]), "+f"(c[3])
        : "r"(a[0]), "r"(a[1]), "r"(a[2]), "r"(a[3]), "r"(b[0]), "r"(b[1]));
}

__device__ __forceinline__ void mma_f16(float c[4], const uint32_t a[4], const uint32_t b[2]) {
    asm volatile(
        "mma.sync.aligned.m16n8k16.row.col.f32.f16.f16.f32 "
        "{%0,%1,%2,%3}, {%4,%5,%6,%7}, {%8,%9}, {%0,%1,%2,%3};"
        : "+f"(c[0]), "+f"(c[1]), "+f"(c[2]), "+f"(c[3])
        : "r"(a[0]), "r"(a[1]), "r"(a[2]), "r"(a[3]), "r"(b[0]), "r"(b[1]));
}

// ---------------- K0: convert weights fp32 -> fp16 ----------------
__global__ void __launch_bounds__(256) k_cvt_h(const float* __restrict__ src,
                                               __half* __restrict__ dst, int n4) {
    int i = blockIdx.x * 256 + threadIdx.x;
    if (i >= n4) return;
    float4 v = ((const float4*)src)[i];
    __half2 h0 = __floats2half2_rn(v.x, v.y);
    __half2 h1 = __floats2half2_rn(v.z, v.w);
    uint2 u;
    u.x = *(uint32_t*)&h0;
    u.y = *(uint32_t*)&h1;
    ((uint2*)dst)[i] = u;
}

// ---------------- K1: rmsnorm(x) -> g_xnh (fp16) ----------------
__global__ void __launch_bounds__(256) k_rmsnorm(const float* __restrict__ x,
                                                 const float* __restrict__ w) {
    int row = blockIdx.x;
    const float* xr = x + (size_t)row * DM;
    float s = 0.f;
    for (int i = threadIdx.x; i < DM; i += 256) { float v = xr[i]; s += v * v; }
    float tot = block_sum(s);
    float inv = rsqrtf(tot / DM + 1e-5f);
    for (int i = threadIdx.x; i < DM; i += 256)
        g_xnh[(size_t)row * DM + i] = __float2half_rn(xr[i] * inv * w[i]);
}

// ---------------- FP16 pipelined GEMM: C[M,N] = A[M,K]*B[N,K]^T (+Res) -----
// CTA 128x128, 4 warps (64x64 each), k-tile 64 halves (128B rows),
// 2-stage cp.async pipeline, register double-buffered fragments.
#define SROW 72                       // half stride per row (36 b32)
#define SA_H (128 * SROW)             // halves per tile
#define STAGE_H (2 * SA_H)            // A + B per stage
#define SMEM_GEMM (STAGE_H * 2 * 2)   // 2 stages, 2 bytes/half = 73728 bytes

__device__ __forceinline__ uint32_t lds32h(const __half* p) {
    return *(const uint32_t*)p;
}

__device__ __forceinline__ void stage_copy16(const __half* __restrict__ A,
                                             const __half* __restrict__ Bw,
                                             __half* sA, __half* sB,
                                             int bm, int bn, int Nn, int K,
                                             int k0, int tid) {
    #pragma unroll
    for (int i = 0; i < 8; i++) {
        int c = tid + 128 * i;                 // 1024 16B chunks for A
        int row = c >> 3, c8 = (c & 7) * 8;
        uint32_t d = (uint32_t)__cvta_generic_to_shared(sA + row * SROW + c8);
        const __half* g = A + (size_t)(bm + row) * K + k0 + c8;
        asm volatile("cp.async.cg.shared.global [%0], [%1], 16;" :: "r"(d), "l"(g));
    }
    #pragma unroll
    for (int i = 0; i < 8; i++) {
        int c = tid + 128 * i;                 // 1024 16B chunks for B
        int row = c >> 3, c8 = (c & 7) * 8;
        uint32_t d = (uint32_t)__cvta_generic_to_shared(sB + row * SROW + c8);
        int n = bn + row;
        int ok = (n < Nn);
        const __half* g = Bw + (size_t)(ok ? n : 0) * K + k0 + c8;
        int sz = ok ? 16 : 0;
        asm volatile("cp.async.cg.shared.global [%0], [%1], 16, %2;" :: "r"(d), "l"(g), "r"(sz));
    }
}

__device__ __forceinline__ void load_frag16(const __half* sA, const __half* sB,
                                            int kk, uint32_t af[4][4], uint32_t bf[8][2],
                                            int wm, int wn, int g, int t) {
    int k16 = kk * 16;
    #pragma unroll
    for (int im = 0; im < 4; im++) {
        int r0 = wm + im * 16 + g;
        af[im][0] = lds32h(sA + r0 * SROW + k16 + 2 * t);
        af[im][1] = lds32h(sA + (r0 + 8) * SROW + k16 + 2 * t);
        af[im][2] = lds32h(sA + r0 * SROW + k16 + 8 + 2 * t);
        af[im][3] = lds32h(sA + (r0 + 8) * SROW + k16 + 8 + 2 * t);
    }
    #pragma unroll
    for (int in = 0; in < 8; in++) {
        int n0 = wn + in * 8 + g;
        bf[in][0] = lds32h(sB + n0 * SROW + k16 + 2 * t);
        bf[in][1] = lds32h(sB + n0 * SROW + k16 + 8 + 2 * t);
    }
}

__device__ __forceinline__ void stage_compute16(const __half* sA, const __half* sB,
                                                float acc[4][8][4],
                                                int wm, int wn, int g, int t) {
    uint32_t af[2][4][4], bf[2][8][2];
    load_frag16(sA, sB, 0, af[0], bf[0], wm, wn, g, t);
    #pragma unroll
    for (int kk = 0; kk < 4; kk++) {
        int cur = kk & 1;
        if (kk < 3)
            load_frag16(sA, sB, kk + 1, af[cur ^ 1], bf[cur ^ 1], wm, wn, g, t);
        #pragma unroll
        for (int im = 0; im < 4; im++)
            #pragma unroll
            for (int in = 0; in < 8; in++)
                mma_f16(acc[im][in], af[cur][im], bf[cur][in]);
    }
}

__device__ __forceinline__ void gemm_f16_body(const __half* __restrict__ A,
                                              const __half* __restrict__ Bw,
                                              const float* __restrict__ Res,
                                              float* __restrict__ C,
                                              int M, int Nn, int K) {
    extern __shared__ __half smh[];
    int bm = blockIdx.y * 128, bn = blockIdx.x * 128;
    int tid = threadIdx.x;
    int w = tid >> 5, lane = tid & 31, g = lane >> 2, t = lane & 3;
    int wm = (w >> 1) * 64, wn = (w & 1) * 64;

    float acc[4][8][4] = {};

    stage_copy16(A, Bw, smh, smh + SA_H, bm, bn, Nn, K, 0, tid);
    asm volatile("cp.async.commit_group;");

    int nk = K / 64;
    for (int kt = 0; kt < nk; kt++) {
        asm volatile("cp.async.wait_group 0;");
        __syncthreads();
        if (kt + 1 < nk) {
            int s = (kt + 1) & 1;
            stage_copy16(A, Bw, smh + s * STAGE_H, smh + s * STAGE_H + SA_H,
                         bm, bn, Nn, K, (kt + 1) * 64, tid);
            asm volatile("cp.async.commit_group;");
        }
        int cur = kt & 1;
        stage_compute16(smh + cur * STAGE_H, smh + cur * STAGE_H + SA_H,
                        acc, wm, wn, g, t);
    }

    #pragma unroll
    for (int im = 0; im < 4; im++) {
        int row = bm + wm + im * 16 + g;
        #pragma unroll
        for (int in = 0; in < 8; in++) {
            int col = bn + wn + in * 8 + 2 * t;
            if (col < Nn) {
                size_t o0 = (size_t)row * Nn + col;
                size_t o1 = (size_t)(row + 8) * Nn + col;
                float v0 = acc[im][in][0], v1 = acc[im][in][1];
                float v2 = acc[im][in][2], v3 = acc[im][in][3];
                if (Res) {
                    v0 += Res[o0]; v1 += Res[o0 + 1];
                    v2 += Res[o1]; v3 += Res[o1 + 1];
                }
                C[o0] = v0; C[o0 + 1] = v1;
                C[o1] = v2; C[o1 + 1] = v3;
            }
        }
    }
}

__global__ void __launch_bounds__(128) k_gemm1() {
    gemm_f16_body(g_xnh, g_Winh, nullptr, g_zx, BL, PROJ, DM);
}
__global__ void __launch_bounds__(128) k_gemm2(const float* __restrict__ x,
                                               float* __restrict__ out) {
    gemm_f16_body(g_ynh, g_Wouth, x, out, BL, DM, DI);
}

// ---------------- K3: tiled causal depthwise conv (w=4) + silu -> g_xBC ----
#define CTL 32
#define CTC 128
__global__ void __launch_bounds__(256) k_conv(const float* __restrict__ cw,
                                              const float* __restrict__ cb) {
    __shared__ float s[(CTL + 3) * CTC];
    int ct = blockIdx.x * CTC;
    int blt = blockIdx.y * CTL;
    int l0 = blt & (Lq - 1);
    int tid = threadIdx.x;

    for (int idx = tid; idx < (CTL + 3) * CTC; idx += 256) {
        int r = (idx >> 7) - 3;
        int ch = idx & 127;
        float v = 0.f;
        if (l0 + r >= 0)
            v = g_zx[(size_t)(blt + r) * PROJ + DI + ct + ch];
        s[idx] = v;
    }
    __syncthreads();

    int ch = tid & 127;
    int li0 = (tid >> 7) * 16;
    float w0 = cw[0 * CDIM + ct + ch];
    float w1 = cw[1 * CDIM + ct + ch];
    float w2 = cw[2 * CDIM + ct + ch];
    float w3 = cw[3 * CDIM + ct + ch];
    float bias = cb[ct + ch];

    #pragma unroll
    for (int i = 0; i < 16; i++) {
        int li = li0 + i;
        float acc = bias
                  + w0 * s[li * CTC + ch]
                  + w1 * s[(li + 1) * CTC + ch]
                  + w2 * s[(li + 2) * CTC + ch]
                  + w3 * s[(li + 3) * CTC + ch];
        acc = acc / (1.f + expf(-acc));
        g_xBC[(size_t)(blt + li) * CDIM + ct + ch] = acc;
    }
}

// ---------------- K3b: dt = softplus(raw + bias) ----------------
__global__ void __launch_bounds__(256) k_dt(const float* __restrict__ dt_bias) {
    int idx = blockIdx.x * 256 + threadIdx.x;
    if (idx >= BL * HN) return;
    int h = idx & 31;
    float v = g_zx[(size_t)(idx >> 5) * PROJ + DI + CDIM + h] + dt_bias[h];
    g_dt[idx] = (v > 20.f) ? v : log1pf(expf(v));
}

// ---------------- K4: intra-chunk via TF32 mma ----------------
#define SBSTR 132
#define SXSTR 68
#define OFF_C  0
#define OFF_B  8448
#define OFF_XT 16896
#define OFF_XD 21248
#define OFF_G  25600
#define OFF_BT 29952
#define SMEM_K4 ((29952 + 128 * 68) * 4)   // 154624 bytes

__global__ void __launch_bounds__(256) k_chunk(const float* __restrict__ A_log) {
    extern __shared__ float sm[];
    float* sC  = sm + OFF_C;
    float* sB  = sm + OFF_B;
    float* sXT = sm + OFF_XT;
    float* sXD = sm + OFF_XD;
    float* sG  = sm + OFF_G;
    float* sBT = sm + OFF_BT;
    __shared__ float sDt[64], sAc[64], sDec[64];

    int bid = blockIdx.x;
    int h = bid & 31, c = (bid >> 5) & 31, b = bid >> 10;
    int tid = threadIdx.x;
    int w = tid >> 5, lane = tid & 31, gq = lane >> 2, tq = lane & 3;
    float Aval = -expf(A_log[h]);
    int posBase = b * Lq + c * 64;

    if (tid < 64) sDt[tid] = g_dt[(posBase + tid) * HN + h];
    #pragma unroll
    for (int k = 0; k < 8; k++) {
        int e4 = tid + k * 256;
        int row = e4 >> 5, col = (e4 & 31) * 4;
        const float* base = &g_xBC[(size_t)(posBase + row) * CDIM + DI];
        float4 bv = *(const float4*)(base + col);
        float4 cv = *(const float4*)(base + DS + col);
        bv.x = f2tf(bv.x); bv.y = f2tf(bv.y); bv.z = f2tf(bv.z); bv.w = f2tf(bv.w);
        cv.x = f2tf(cv.x); cv.y = f2tf(cv.y); cv.z = f2tf(cv.z); cv.w = f2tf(cv.w);
        *(float4*)(sB + row * SBSTR + col) = bv;
        *(float4*)(sC + row * SBSTR + col) = cv;
    }
    __syncthreads();
    if (tid == 0) {
        float acc = 0.f;
        for (int s = 0; s < 64; s++) { acc += sDt[s] * Aval; sAc[s] = acc; }
    }
    #pragma unroll
    for (int k = 0; k < 32; k++) {
        int e = tid + k * 256;
        int n = e & 127, s = e >> 7;
        sBT[n * SXSTR + s] = sB[s * SBSTR + n];
    }
    __syncthreads();
    if (tid < 64) sDec[tid] = expf(sAc[63] - sAc[tid]);
    __syncthreads();
    #pragma unroll
    for (int k = 0; k < 16; k++) {
        int e = tid + k * 256;
        int p = e & 63, s = e >> 6;
        float xv = g_xBC[(size_t)(posBase + s) * CDIM + h * 64 + p] * sDt[s];
        sXT[p * SXSTR + s] = f2tf(xv);
        sXD[p * SXSTR + s] = f2tf(xv * sDec[s]);
    }
    __syncthreads();

    {
        int wm = (w >> 1) * 16, wn = (w & 1) * 32;
        float acc[4][4] = {};
        #pragma unroll
        for (int kk = 0; kk < 16; kk++) {
            int k = kk * 8;
            uint32_t af[4];
            int r0 = wm + gq;
            af[0] = __float_as_uint(sC[r0 * SBSTR + k + tq]);
            af[1] = __float_as_uint(sC[(r0 + 8) * SBSTR + k + tq]);
            af[2] = __float_as_uint(sC[r0 * SBSTR + k + tq + 4]);
            af[3] = __float_as_uint(sC[(r0 + 8) * SBSTR + k + tq + 4]);
            #pragma unroll
            for (int in = 0; in < 4; in++) {
                int n0 = wn + in * 8 + gq;
                uint32_t bf[2];
                bf[0] = __float_as_uint(sB[n0 * SBSTR + k + tq]);
                bf[1] = __float_as_uint(sB[n0 * SBSTR + k + tq + 4]);
                mma_tf32(acc[in], af, bf);
            }
        }
        int l0 = wm + gq, l1 = l0 + 8;
        float a0 = sAc[l0], a1 = sAc[l1];
        #pragma unroll
        for (int in = 0; in < 4; in++) {
            int s0 = wn + in * 8 + 2 * tq, s1 = s0 + 1;
            float as0 = sAc[s0], as1 = sAc[s1];
            sG[l0 * SXSTR + s0] = (l0 >= s0) ? f2tf(expf(a0 - as0) * acc[in][0]) : 0.f;
            sG[l0 * SXSTR + s1] = (l0 >= s1) ? f2tf(expf(a0 - as1) * acc[in][1]) : 0.f;
            sG[l1 * SXSTR + s0] = (l1 >= s0) ? f2tf(expf(a1 - as0) * acc[in][2]) : 0.f;
            sG[l1 * SXSTR + s1] = (l1 >= s1) ? f2tf(expf(a1 - as1) * acc[in][3]) : 0.f;
        }
    }
    __syncthreads();

    {
        int wm = (w >> 1) * 16, wn = (w & 1) * 32;
        float acc[4][4] = {};
        #pragma unroll
        for (int kk = 0; kk < 8; kk++) {
            int k = kk * 8;
            uint32_t af[4];
            int r0 = wm + gq;
            af[0] = __float_as_uint(sG[r0 * SXSTR + k + tq]);
            af[1] = __float_as_uint(sG[(r0 + 8) * SXSTR + k + tq]);
            af[2] = __float_as_uint(sG[r0 * SXSTR + k + tq + 4]);
            af[3] = __float_as_uint(sG[(r0 + 8) * SXSTR + k + tq + 4]);
            #pragma unroll
            for (int in = 0; in < 4; in++) {
                int n0 = wn + in * 8 + gq;
                uint32_t bf[2];
                bf[0] = __float_as_uint(sXT[n0 * SXSTR + k + tq]);
                bf[1] = __float_as_uint(sXT[n0 * SXSTR + k + tq + 4]);
                mma_tf32(acc[in], af, bf);
            }
        }
        int l0 = wm + gq, l1 = l0 + 8;
        float* y0 = &g_Y[(size_t)(posBase + l0) * DI + h * 64];
        float* y1 = &g_Y[(size_t)(posBase + l1) * DI + h * 64];
        #pragma unroll
        for (int in = 0; in < 4; in++) {
            int p0 = wn + in * 8 + 2 * tq;
            y0[p0] = acc[in][0]; y0[p0 + 1] = acc[in][1];
            y1[p0] = acc[in][2]; y1[p0 + 1] = acc[in][3];
        }
    }

    {
        int wm = (w >> 1) * 16, wn = (w & 1) * 64;
        float acc[8][4] = {};
        #pragma unroll
        for (int kk = 0; kk < 8; kk++) {
            int k = kk * 8;
            uint32_t af[4];
            int r0 = wm + gq;
            af[0] = __float_as_uint(sXD[r0 * SXSTR + k + tq]);
            af[1] = __float_as_uint(sXD[(r0 + 8) * SXSTR + k + tq]);
            af[2] = __float_as_uint(sXD[r0 * SXSTR + k + tq + 4]);
            af[3] = __float_as_uint(sXD[(r0 + 8) * SXSTR + k + tq + 4]);
            #pragma unroll
            for (int in = 0; in < 8; in++) {
                int n0 = wn + in * 8 + gq;
                uint32_t bf[2];
                bf[0] = __float_as_uint(sBT[n0 * SXSTR + k + tq]);
                bf[1] = __float_as_uint(sBT[n0 * SXSTR + k + tq + 4]);
                mma_tf32(acc[in], af, bf);
            }
        }
        size_t sbase = ((size_t)((b * NC + c) * HN + h)) * (64 * 128);
        int p0 = wm + gq, p1 = p0 + 8;
        #pragma unroll
        for (int in = 0; in < 8; in++) {
            int n0 = wn + in * 8 + 2 * tq;
            g_states[sbase + (size_t)p0 * 128 + n0]     = acc[in][0];
            g_states[sbase + (size_t)p0 * 128 + n0 + 1] = acc[in][1];
            g_states[sbase + (size_t)p1 * 128 + n0]     = acc[in][2];
            g_states[sbase + (size_t)p1 * 128 + n0 + 1] = acc[in][3];
        }
    }
    if (tid == 0) g_asum[(b * HN + h) * NC + c] = sAc[63];
}

// ---------------- K5: inter-chunk prefix scan (parallel: 1 float4/thread) --
__global__ void __launch_bounds__(256) k_scan() {
    int bid = blockIdx.x;
    int seg = bid & 7;
    int bh = bid >> 3;
    int b = bh >> 5, h = bh & 31;
    int e = seg * 256 + threadIdx.x;
    const float* asum = &g_asum[(b * HN + h) * NC];
    float4 S = make_float4(0.f, 0.f, 0.f, 0.f);
    #pragma unroll 4
    for (int c = 0; c < NC; c++) {
        size_t base4 = ((size_t)((b * NC + c) * HN + h)) * 2048;
        float dec = expf(asum[c]);
        ((float4*)g_sin)[base4 + e] = S;
        float4 st = ((const float4*)g_states)[base4 + e];
        S.x = S.x * dec + st.x;
        S.y = S.y * dec + st.y;
        S.z = S.z * dec + st.z;
        S.w = S.w * dec + st.w;
    }
}

// ---------------- K6: Yo = exp(Ac) * C * S^T via mma; Y += Yo + xs*D -------
#define SMEM_K6 (8448 * 2 * 4)   // 67584 bytes
__global__ void __launch_bounds__(256) k_inter(const float* __restrict__ A_log,
                                               const float* __restrict__ Dp) {
    extern __shared__ float sm[];
    float* sC = sm;
    float* sS = sm + 8448;
    __shared__ float sDt[64], sAc[64];

    int bid = blockIdx.x;
    int h = bid & 31, c = (bid >> 5) & 31, b = bid >> 10;
    int tid = threadIdx.x;
    int w = tid >> 5, lane = tid & 31, gq = lane >> 2, tq = lane & 3;
    float Aval = -expf(A_log[h]);
    float Dv = Dp[h];
    int posBase = b * Lq + c * 64;

    if (tid < 64) sDt[tid] = g_dt[(posBase + tid) * HN + h];
    size_t sbase = ((size_t)((b * NC + c) * HN + h)) * 8192;
    #pragma unroll
    for (int k = 0; k < 8; k++) {
        int e4 = tid + k * 256;
        int row = e4 >> 5, col = (e4 & 31) * 4;
        float4 cv = *(const float4*)&g_xBC[(size_t)(posBase + row) * CDIM + DI + DS + col];
        float4 sv = *(const float4*)&g_sin[sbase + (size_t)row * 128 + col];
        cv.x = f2tf(cv.x); cv.y = f2tf(cv.y); cv.z = f2tf(cv.z); cv.w = f2tf(cv.w);
        sv.x = f2tf(sv.x); sv.y = f2tf(sv.y); sv.z = f2tf(sv.z); sv.w = f2tf(sv.w);
        *(float4*)(sC + row * SBSTR + col) = cv;
        *(float4*)(sS + row * SBSTR + col) = sv;
    }
    __syncthreads();
    if (tid == 0) {
        float acc = 0.f;
        for (int s = 0; s < 64; s++) { acc += sDt[s] * Aval; sAc[s] = acc; }
    }
    __syncthreads();

    int wm = (w >> 1) * 16, wn = (w & 1) * 32;
    float acc[4][4] = {};
    #pragma unroll
    for (int kk = 0; kk < 16; kk++) {
        int k = kk * 8;
        uint32_t af[4];
        int r0 = wm + gq;
        af[0] = __float_as_uint(sC[r0 * SBSTR + k + tq]);
        af[1] = __float_as_uint(sC[(r0 + 8) * SBSTR + k + tq]);
        af[2] = __float_as_uint(sC[r0 * SBSTR + k + tq + 4]);
        af[3] = __float_as_uint(sC[(r0 + 8) * SBSTR + k + tq + 4]);
        #pragma unroll
        for (int in = 0; in < 4; in++) {
            int n0 = wn + in * 8 + gq;
            uint32_t bf[2];
            bf[0] = __float_as_uint(sS[n0 * SBSTR + k + tq]);
            bf[1] = __float_as_uint(sS[n0 * SBSTR + k + tq + 4]);
            mma_tf32(acc[in], af, bf);
        }
    }
    int l0 = wm + gq, l1 = l0 + 8;
    float e0 = expf(sAc[l0]), e1 = expf(sAc[l1]);
    float* y0 = &g_Y[(size_t)(posBase + l0) * DI + h * 64];
    float* y1 = &g_Y[(size_t)(posBase + l1) * DI + h * 64];
    const float* x0 = &g_xBC[(size_t)(posBase + l0) * CDIM + h * 64];
    const float* x1 = &g_xBC[(size_t)(posBase + l1) * CDIM + h * 64];
    #pragma unroll
    for (int in = 0; in < 4; in++) {
        int p0 = wn + in * 8 + 2 * tq;
        y0[p0]     += e0 * acc[in][0] + x0[p0] * Dv;
        y0[p0 + 1] += e0 * acc[in][1] + x0[p0 + 1] * Dv;
        y1[p0]     += e1 * acc[in][2] + x1[p0] * Dv;
        y1[p0 + 1] += e1 * acc[in][3] + x1[p0 + 1] * Dv;
    }
}

// ---------------- K7: gated rmsnorm -> g_ynh (fp16) ----------------
__global__ void __launch_bounds__(256) k_gate(const float* __restrict__ w) {
    __shared__ float sv[DI];
    int row = blockIdx.x;
    int tid = threadIdx.x;
    float s = 0.f;
    for (int i = tid; i < DI; i += 256) {
        float z = g_zx[(size_t)row * PROJ + i];
        float y = g_Y[(size_t)row * DI + i];
        float v = y * z / (1.f + expf(-z));
        sv[i] = v;
        s += v * v;
    }
    float tot = block_sum(s);
    float inv = rsqrtf(tot / DI + 1e-5f);
    for (int i = tid; i < DI; i += 256)
        g_ynh[(size_t)row * DI + i] = __float2half_rn(sv[i] * inv * w[i]);
}

// ---------------- launcher ----------------
extern "C" void kernel_launch(void* const* d_in, const int* in_sizes, int n_in,
                              void* d_out, int out_size) {
    const float* x       = (const float*)d_in[0];
    const float* norm_w  = (const float*)d_in[1];
    const float* in_W    = (const float*)d_in[2];
    const float* conv_w  = (const float*)d_in[3];
    const float* conv_b  = (const float*)d_in[4];
    const float* dt_bias = (const float*)d_in[5];
    const float* A_log   = (const float*)d_in[6];
    const float* Dp      = (const float*)d_in[7];
    const float* ni_w    = (const float*)d_in[8];
    const float* out_W   = (const float*)d_in[9];
    float* out = (float*)d_out;

    cudaFuncSetAttribute(k_gemm1, cudaFuncAttributeMaxDynamicSharedMemorySize, SMEM_GEMM);
    cudaFuncSetAttribute(k_gemm2, cudaFuncAttributeMaxDynamicSharedMemorySize, SMEM_GEMM);
    cudaFuncSetAttribute(k_chunk, cudaFuncAttributeMaxDynamicSharedMemorySize, SMEM_K4);
    cudaFuncSetAttribute(k_inter, cudaFuncAttributeMaxDynamicSharedMemorySize, SMEM_K6);

    __half* d_Winh;  cudaGetSymbolAddress((void**)&d_Winh, g_Winh);
    __half* d_Wouth; cudaGetSymbolAddress((void**)&d_Wouth, g_Wouth);

    k_cvt_h<<<(PROJ * DM / 4 + 255) / 256, 256>>>(in_W, d_Winh, PROJ * DM / 4);
    k_cvt_h<<<(DM * DI / 4 + 255) / 256, 256>>>(out_W, d_Wouth, DM * DI / 4);
    k_rmsnorm<<<BL, 256>>>(x, norm_w);
    k_gemm1<<<dim3((PROJ + 127) / 128, BL / 128), 128, SMEM_GEMM>>>();
    k_conv<<<dim3(CDIM / CTC, BL / CTL), 256>>>(conv_w, conv_b);
    k_dt<<<(BL * HN + 255) / 256, 256>>>(dt_bias);
    k_chunk<<<Bq * NC * HN, 256, SMEM_K4>>>(A_log);
    k_scan<<<Bq * HN * 8, 256>>>();
    k_inter<<<Bq * NC * HN, 256, SMEM_K6>>>(A_log, Dp);
    k_gate<<<BL, 256>>>(ni_w);
    k_gemm2<<<dim3(DM / 128, BL / 128), 128, SMEM_GEMM>>>(x, out);
}

// round 13
// speedup vs baseline: 6.2333x; 1.0802x over previous
#include <cuda_runtime.h>
#include <cuda_fp16.h>
#include <math.h>
#include <stdint.h>

#define Bq 4
#define Lq 2048
#define DM 1024
#define DI 2048
#define HN 32
#define HD 64
#define DS 128
#define CDIM 2304
#define PROJ 4384
#define CH 64
#define NC 32
#define BL 8192

// ---------------- scratch (device globals; no allocations) ----------------
__device__ __half g_xnh[(size_t)BL * DM];       // rmsnorm(x), fp16
__device__ float g_zx[(size_t)BL * PROJ];       // zxbcdt
__device__ float g_xBC[(size_t)BL * CDIM];      // conv+silu output
__device__ float g_dt[BL * HN];                 // softplus dt
__device__ float g_Y[(size_t)BL * DI];          // SSD output (Yd then +=Yo)
__device__ float g_states[(size_t)Bq * NC * HN * HD * DS];
__device__ float g_sin[(size_t)Bq * NC * HN * HD * DS];
__device__ float g_asum[Bq * HN * NC];
__device__ __half g_ynh[(size_t)BL * DI];       // gated+normed Y, fp16
__device__ __half g_Winh[(size_t)PROJ * DM];    // fp16 in_proj_W
__device__ __half g_Wouth[(size_t)DM * DI];     // fp16 out_proj_W

// ---------------- helpers ----------------
__device__ __forceinline__ float block_sum(float v) {
    __shared__ float red[8];
    #pragma unroll
    for (int o = 16; o; o >>= 1) v += __shfl_down_sync(0xffffffffu, v, o);
    if ((threadIdx.x & 31) == 0) red[threadIdx.x >> 5] = v;
    __syncthreads();
    if (threadIdx.x < 32) {
        v = (threadIdx.x < 8) ? red[threadIdx.x] : 0.f;
        #pragma unroll
        for (int o = 4; o; o >>= 1) v += __shfl_down_sync(0xffffffffu, v, o);
        if (threadIdx.x == 0) red[0] = v;
    }
    __syncthreads();
    return red[0];
}

__device__ __forceinline__ void mma_f16(float c[4], const uint32_t a[4], const uint32_t b[2]) {
    asm volatile(
        "mma.sync.aligned.m16n8k16.row.col.f32.f16.f16.f32 "
        "{%0,%1,%2,%3}, {%4,%5,%6,%7}, {%8,%9}, {%0,%1,%2,%3};"
        : "+f"(c[0]), "+f"(c[1]), "+f"(c[2]), "+f"(c[3])
        : "r"(a[0]), "r"(a[1]), "r"(a[2]), "r"(a[3]), "r"(b[0]), "r"(b[1]));
}

__device__ __forceinline__ uint32_t lds32h(const __half* p) {
    return *(const uint32_t*)p;
}

// ---------------- K0: convert weights fp32 -> fp16 ----------------
__global__ void __launch_bounds__(256) k_cvt_h(const float* __restrict__ src,
                                               __half* __restrict__ dst, int n4) {
    int i = blockIdx.x * 256 + threadIdx.x;
    if (i >= n4) return;
    float4 v = ((const float4*)src)[i];
    __half2 h0 = __floats2half2_rn(v.x, v.y);
    __half2 h1 = __floats2half2_rn(v.z, v.w);
    uint2 u;
    u.x = *(uint32_t*)&h0;
    u.y = *(uint32_t*)&h1;
    ((uint2*)dst)[i] = u;
}

// ---------------- K1: rmsnorm(x) -> g_xnh (fp16) ----------------
__global__ void __launch_bounds__(256) k_rmsnorm(const float* __restrict__ x,
                                                 const float* __restrict__ w) {
    int row = blockIdx.x;
    const float* xr = x + (size_t)row * DM;
    float s = 0.f;
    for (int i = threadIdx.x; i < DM; i += 256) { float v = xr[i]; s += v * v; }
    float tot = block_sum(s);
    float inv = rsqrtf(tot / DM + 1e-5f);
    for (int i = threadIdx.x; i < DM; i += 256)
        g_xnh[(size_t)row * DM + i] = __float2half_rn(xr[i] * inv * w[i]);
}

// ---------------- FP16 pipelined GEMM (unchanged from R12) ----------------
#define SROW 72
#define SA_H (128 * SROW)
#define STAGE_H (2 * SA_H)
#define SMEM_GEMM (STAGE_H * 2 * 2)

__device__ __forceinline__ void stage_copy16(const __half* __restrict__ A,
                                             const __half* __restrict__ Bw,
                                             __half* sA, __half* sB,
                                             int bm, int bn, int Nn, int K,
                                             int k0, int tid) {
    #pragma unroll
    for (int i = 0; i < 8; i++) {
        int c = tid + 128 * i;
        int row = c >> 3, c8 = (c & 7) * 8;
        uint32_t d = (uint32_t)__cvta_generic_to_shared(sA + row * SROW + c8);
        const __half* g = A + (size_t)(bm + row) * K + k0 + c8;
        asm volatile("cp.async.cg.shared.global [%0], [%1], 16;" :: "r"(d), "l"(g));
    }
    #pragma unroll
    for (int i = 0; i < 8; i++) {
        int c = tid + 128 * i;
        int row = c >> 3, c8 = (c & 7) * 8;
        uint32_t d = (uint32_t)__cvta_generic_to_shared(sB + row * SROW + c8);
        int n = bn + row;
        int ok = (n < Nn);
        const __half* g = Bw + (size_t)(ok ? n : 0) * K + k0 + c8;
        int sz = ok ? 16 : 0;
        asm volatile("cp.async.cg.shared.global [%0], [%1], 16, %2;" :: "r"(d), "l"(g), "r"(sz));
    }
}

__device__ __forceinline__ void load_frag16(const __half* sA, const __half* sB,
                                            int kk, uint32_t af[4][4], uint32_t bf[8][2],
                                            int wm, int wn, int g, int t) {
    int k16 = kk * 16;
    #pragma unroll
    for (int im = 0; im < 4; im++) {
        int r0 = wm + im * 16 + g;
        af[im][0] = lds32h(sA + r0 * SROW + k16 + 2 * t);
        af[im][1] = lds32h(sA + (r0 + 8) * SROW + k16 + 2 * t);
        af[im][2] = lds32h(sA + r0 * SROW + k16 + 8 + 2 * t);
        af[im][3] = lds32h(sA + (r0 + 8) * SROW + k16 + 8 + 2 * t);
    }
    #pragma unroll
    for (int in = 0; in < 8; in++) {
        int n0 = wn + in * 8 + g;
        bf[in][0] = lds32h(sB + n0 * SROW + k16 + 2 * t);
        bf[in][1] = lds32h(sB + n0 * SROW + k16 + 8 + 2 * t);
    }
}

__device__ __forceinline__ void stage_compute16(const __half* sA, const __half* sB,
                                                float acc[4][8][4],
                                                int wm, int wn, int g, int t) {
    uint32_t af[2][4][4], bf[2][8][2];
    load_frag16(sA, sB, 0, af[0], bf[0], wm, wn, g, t);
    #pragma unroll
    for (int kk = 0; kk < 4; kk++) {
        int cur = kk & 1;
        if (kk < 3)
            load_frag16(sA, sB, kk + 1, af[cur ^ 1], bf[cur ^ 1], wm, wn, g, t);
        #pragma unroll
        for (int im = 0; im < 4; im++)
            #pragma unroll
            for (int in = 0; in < 8; in++)
                mma_f16(acc[im][in], af[cur][im], bf[cur][in]);
    }
}

__device__ __forceinline__ void gemm_f16_body(const __half* __restrict__ A,
                                              const __half* __restrict__ Bw,
                                              const float* __restrict__ Res,
                                              float* __restrict__ C,
                                              int M, int Nn, int K) {
    extern __shared__ __half smh[];
    int bm = blockIdx.y * 128, bn = blockIdx.x * 128;
    int tid = threadIdx.x;
    int w = tid >> 5, lane = tid & 31, g = lane >> 2, t = lane & 3;
    int wm = (w >> 1) * 64, wn = (w & 1) * 64;

    float acc[4][8][4] = {};

    stage_copy16(A, Bw, smh, smh + SA_H, bm, bn, Nn, K, 0, tid);
    asm volatile("cp.async.commit_group;");

    int nk = K / 64;
    for (int kt = 0; kt < nk; kt++) {
        asm volatile("cp.async.wait_group 0;");
        __syncthreads();
        if (kt + 1 < nk) {
            int s = (kt + 1) & 1;
            stage_copy16(A, Bw, smh + s * STAGE_H, smh + s * STAGE_H + SA_H,
                         bm, bn, Nn, K, (kt + 1) * 64, tid);
            asm volatile("cp.async.commit_group;");
        }
        int cur = kt & 1;
        stage_compute16(smh + cur * STAGE_H, smh + cur * STAGE_H + SA_H,
                        acc, wm, wn, g, t);
    }

    #pragma unroll
    for (int im = 0; im < 4; im++) {
        int row = bm + wm + im * 16 + g;
        #pragma unroll
        for (int in = 0; in < 8; in++) {
            int col = bn + wn + in * 8 + 2 * t;
            if (col < Nn) {
                size_t o0 = (size_t)row * Nn + col;
                size_t o1 = (size_t)(row + 8) * Nn + col;
                float v0 = acc[im][in][0], v1 = acc[im][in][1];
                float v2 = acc[im][in][2], v3 = acc[im][in][3];
                if (Res) {
                    v0 += Res[o0]; v1 += Res[o0 + 1];
                    v2 += Res[o1]; v3 += Res[o1 + 1];
                }
                C[o0] = v0; C[o0 + 1] = v1;
                C[o1] = v2; C[o1 + 1] = v3;
            }
        }
    }
}

__global__ void __launch_bounds__(128) k_gemm1() {
    gemm_f16_body(g_xnh, g_Winh, nullptr, g_zx, BL, PROJ, DM);
}
__global__ void __launch_bounds__(128) k_gemm2(const float* __restrict__ x,
                                               float* __restrict__ out) {
    gemm_f16_body(g_ynh, g_Wouth, x, out, BL, DM, DI);
}

// ---------------- K3: tiled causal depthwise conv (w=4) + silu -> g_xBC ----
#define CTL 32
#define CTC 128
__global__ void __launch_bounds__(256) k_conv(const float* __restrict__ cw,
                                              const float* __restrict__ cb) {
    __shared__ float s[(CTL + 3) * CTC];
    int ct = blockIdx.x * CTC;
    int blt = blockIdx.y * CTL;
    int l0 = blt & (Lq - 1);
    int tid = threadIdx.x;

    for (int idx = tid; idx < (CTL + 3) * CTC; idx += 256) {
        int r = (idx >> 7) - 3;
        int ch = idx & 127;
        float v = 0.f;
        if (l0 + r >= 0)
            v = g_zx[(size_t)(blt + r) * PROJ + DI + ct + ch];
        s[idx] = v;
    }
    __syncthreads();

    int ch = tid & 127;
    int li0 = (tid >> 7) * 16;
    float w0 = cw[0 * CDIM + ct + ch];
    float w1 = cw[1 * CDIM + ct + ch];
    float w2 = cw[2 * CDIM + ct + ch];
    float w3 = cw[3 * CDIM + ct + ch];
    float bias = cb[ct + ch];

    #pragma unroll
    for (int i = 0; i < 16; i++) {
        int li = li0 + i;
        float acc = bias
                  + w0 * s[li * CTC + ch]
                  + w1 * s[(li + 1) * CTC + ch]
                  + w2 * s[(li + 2) * CTC + ch]
                  + w3 * s[(li + 3) * CTC + ch];
        acc = acc / (1.f + expf(-acc));
        g_xBC[(size_t)(blt + li) * CDIM + ct + ch] = acc;
    }
}

// ---------------- K3b: dt = softplus(raw + bias) ----------------
__global__ void __launch_bounds__(256) k_dt(const float* __restrict__ dt_bias) {
    int idx = blockIdx.x * 256 + threadIdx.x;
    if (idx >= BL * HN) return;
    int h = idx & 31;
    float v = g_zx[(size_t)(idx >> 5) * PROJ + DI + CDIM + h] + dt_bias[h];
    g_dt[idx] = (v > 20.f) ? v : log1pf(expf(v));
}

// ---------------- K4: intra-chunk via FP16 mma ----------------
// smem half offsets: stride 136 halves for 128-wide, 72 for 64-wide
#define HSTR 136
#define XSTR 72
#define HOFF_C  0
#define HOFF_B  8704
#define HOFF_XT 17408
#define HOFF_XD 22016
#define HOFF_G  26624
#define HOFF_BT 31232
#define SMEM_K4 ((31232 + 128 * 72) * 2)   // 80896 bytes

__global__ void __launch_bounds__(256) k_chunk(const float* __restrict__ A_log) {
    extern __shared__ __half smh4[];
    __half* sC  = smh4 + HOFF_C;    // [64 l][136] K=128 n
    __half* sB  = smh4 + HOFF_B;    // [64 s][136] K=128 n
    __half* sXT = smh4 + HOFF_XT;   // [64 p][72]  K=64 s
    __half* sXD = smh4 + HOFF_XD;   // [64 p][72]  K=64 s
    __half* sG  = smh4 + HOFF_G;    // [64 l][72]  K=64 s
    __half* sBT = smh4 + HOFF_BT;   // [128 n][72] K=64 s
    __shared__ float sDt[64], sAc[64], sDec[64];

    int bid = blockIdx.x;
    int h = bid & 31, c = (bid >> 5) & 31, b = bid >> 10;
    int tid = threadIdx.x;
    int w = tid >> 5, lane = tid & 31, gq = lane >> 2, tq = lane & 3;
    float Aval = -expf(A_log[h]);
    int posBase = b * Lq + c * 64;

    if (tid < 64) sDt[tid] = g_dt[(posBase + tid) * HN + h];
    // fill B, C (half)
    #pragma unroll
    for (int k = 0; k < 8; k++) {
        int e4 = tid + k * 256;              // 2048 float4 reads
        int row = e4 >> 5, col = (e4 & 31) * 4;
        const float* base = &g_xBC[(size_t)(posBase + row) * CDIM + DI];
        float4 bv = *(const float4*)(base + col);
        float4 cv = *(const float4*)(base + DS + col);
        __half2 b0 = __floats2half2_rn(bv.x, bv.y);
        __half2 b1 = __floats2half2_rn(bv.z, bv.w);
        __half2 c0 = __floats2half2_rn(cv.x, cv.y);
        __half2 c1 = __floats2half2_rn(cv.z, cv.w);
        *(__half2*)(sB + row * HSTR + col) = b0;
        *(__half2*)(sB + row * HSTR + col + 2) = b1;
        *(__half2*)(sC + row * HSTR + col) = c0;
        *(__half2*)(sC + row * HSTR + col + 2) = c1;
    }
    __syncthreads();
    if (tid == 0) {
        float acc = 0.f;
        for (int s = 0; s < 64; s++) { acc += sDt[s] * Aval; sAc[s] = acc; }
    }
    // BT build (half)
    #pragma unroll
    for (int k = 0; k < 32; k++) {
        int e = tid + k * 256;               // 8192
        int n = e & 127, s = e >> 7;
        sBT[n * XSTR + s] = sB[s * HSTR + n];
    }
    __syncthreads();
    if (tid < 64) sDec[tid] = expf(sAc[63] - sAc[tid]);
    __syncthreads();
    // XT, XD (half)
    #pragma unroll
    for (int k = 0; k < 16; k++) {
        int e = tid + k * 256;               // 4096
        int p = e & 63, s = e >> 6;
        float xv = g_xBC[(size_t)(posBase + s) * CDIM + h * 64 + p] * sDt[s];
        sXT[p * XSTR + s] = __float2half_rn(xv);
        sXD[p * XSTR + s] = __float2half_rn(xv * sDec[s]);
    }
    __syncthreads();

    // --- G = C * B^T  (M=64 l, N=64 s, K=128 n), warp tile 16x32 ---
    {
        int wm = (w >> 1) * 16, wn = (w & 1) * 32;
        float acc[4][4] = {};
        #pragma unroll
        for (int kk = 0; kk < 8; kk++) {
            int k16 = kk * 16;
            uint32_t af[4];
            int r0 = wm + gq;
            af[0] = lds32h(sC + r0 * HSTR + k16 + 2 * tq);
            af[1] = lds32h(sC + (r0 + 8) * HSTR + k16 + 2 * tq);
            af[2] = lds32h(sC + r0 * HSTR + k16 + 8 + 2 * tq);
            af[3] = lds32h(sC + (r0 + 8) * HSTR + k16 + 8 + 2 * tq);
            #pragma unroll
            for (int in = 0; in < 4; in++) {
                int n0 = wn + in * 8 + gq;
                uint32_t bf[2];
                bf[0] = lds32h(sB + n0 * HSTR + k16 + 2 * tq);
                bf[1] = lds32h(sB + n0 * HSTR + k16 + 8 + 2 * tq);
                mma_f16(acc[in], af, bf);
            }
        }
        int l0 = wm + gq, l1 = l0 + 8;
        float a0 = sAc[l0], a1 = sAc[l1];
        #pragma unroll
        for (int in = 0; in < 4; in++) {
            int s0 = wn + in * 8 + 2 * tq, s1 = s0 + 1;
            float as0 = sAc[s0], as1 = sAc[s1];
            sG[l0 * XSTR + s0] = __float2half_rn((l0 >= s0) ? expf(a0 - as0) * acc[in][0] : 0.f);
            sG[l0 * XSTR + s1] = __float2half_rn((l0 >= s1) ? expf(a0 - as1) * acc[in][1] : 0.f);
            sG[l1 * XSTR + s0] = __float2half_rn((l1 >= s0) ? expf(a1 - as0) * acc[in][2] : 0.f);
            sG[l1 * XSTR + s1] = __float2half_rn((l1 >= s1) ? expf(a1 - as1) * acc[in][3] : 0.f);
        }
    }
    __syncthreads();

    // --- Yd = G * X  (M=64 l, N=64 p, K=64 s) ---
    {
        int wm = (w >> 1) * 16, wn = (w & 1) * 32;
        float acc[4][4] = {};
        #pragma unroll
        for (int kk = 0; kk < 4; kk++) {
            int k16 = kk * 16;
            uint32_t af[4];
            int r0 = wm + gq;
            af[0] = lds32h(sG + r0 * XSTR + k16 + 2 * tq);
            af[1] = lds32h(sG + (r0 + 8) * XSTR + k16 + 2 * tq);
            af[2] = lds32h(sG + r0 * XSTR + k16 + 8 + 2 * tq);
            af[3] = lds32h(sG + (r0 + 8) * XSTR + k16 + 8 + 2 * tq);
            #pragma unroll
            for (int in = 0; in < 4; in++) {
                int n0 = wn + in * 8 + gq;
                uint32_t bf[2];
                bf[0] = lds32h(sXT + n0 * XSTR + k16 + 2 * tq);
                bf[1] = lds32h(sXT + n0 * XSTR + k16 + 8 + 2 * tq);
                mma_f16(acc[in], af, bf);
            }
        }
        int l0 = wm + gq, l1 = l0 + 8;
        float* y0 = &g_Y[(size_t)(posBase + l0) * DI + h * 64];
        float* y1 = &g_Y[(size_t)(posBase + l1) * DI + h * 64];
        #pragma unroll
        for (int in = 0; in < 4; in++) {
            int p0 = wn + in * 8 + 2 * tq;
            y0[p0] = acc[in][0]; y0[p0 + 1] = acc[in][1];
            y1[p0] = acc[in][2]; y1[p0 + 1] = acc[in][3];
        }
    }

    // --- states[p][n] = sum_s XD[p][s] * BT[n][s]  (M=64, N=128, K=64) ---
    {
        int wm = (w >> 1) * 16, wn = (w & 1) * 64;
        float acc[8][4] = {};
        #pragma unroll
        for (int kk = 0; kk < 4; kk++) {
            int k16 = kk * 16;
            uint32_t af[4];
            int r0 = wm + gq;
            af[0] = lds32h(sXD + r0 * XSTR + k16 + 2 * tq);
            af[1] = lds32h(sXD + (r0 + 8) * XSTR + k16 + 2 * tq);
            af[2] = lds32h(sXD + r0 * XSTR + k16 + 8 + 2 * tq);
            af[3] = lds32h(sXD + (r0 + 8) * XSTR + k16 + 8 + 2 * tq);
            #pragma unroll
            for (int in = 0; in < 8; in++) {
                int n0 = wn + in * 8 + gq;
                uint32_t bf[2];
                bf[0] = lds32h(sBT + n0 * XSTR + k16 + 2 * tq);
                bf[1] = lds32h(sBT + n0 * XSTR + k16 + 8 + 2 * tq);
                mma_f16(acc[in], af, bf);
            }
        }
        size_t sbase = ((size_t)((b * NC + c) * HN + h)) * (64 * 128);
        int p0 = wm + gq, p1 = p0 + 8;
        #pragma unroll
        for (int in = 0; in < 8; in++) {
            int n0 = wn + in * 8 + 2 * tq;
            g_states[sbase + (size_t)p0 * 128 + n0]     = acc[in][0];
            g_states[sbase + (size_t)p0 * 128 + n0 + 1] = acc[in][1];
            g_states[sbase + (size_t)p1 * 128 + n0]     = acc[in][2];
            g_states[sbase + (size_t)p1 * 128 + n0 + 1] = acc[in][3];
        }
    }
    if (tid == 0) g_asum[(b * HN + h) * NC + c] = sAc[63];
}

// ---------------- K5: inter-chunk prefix scan (parallel: 1 float4/thread) --
__global__ void __launch_bounds__(256) k_scan() {
    int bid = blockIdx.x;
    int seg = bid & 7;
    int bh = bid >> 3;
    int b = bh >> 5, h = bh & 31;
    int e = seg * 256 + threadIdx.x;
    const float* asum = &g_asum[(b * HN + h) * NC];
    float4 S = make_float4(0.f, 0.f, 0.f, 0.f);
    #pragma unroll 4
    for (int c = 0; c < NC; c++) {
        size_t base4 = ((size_t)((b * NC + c) * HN + h)) * 2048;
        float dec = expf(asum[c]);
        ((float4*)g_sin)[base4 + e] = S;
        float4 st = ((const float4*)g_states)[base4 + e];
        S.x = S.x * dec + st.x;
        S.y = S.y * dec + st.y;
        S.z = S.z * dec + st.z;
        S.w = S.w * dec + st.w;
    }
}

// ---------------- K6: Yo = exp(Ac) * C * S^T via fp16 mma; Y += Yo + xs*D --
#define SMEM_K6 (8704 * 2 * 2)   // 34816 bytes
__global__ void __launch_bounds__(256) k_inter(const float* __restrict__ A_log,
                                               const float* __restrict__ Dp) {
    extern __shared__ __half smh6[];
    __half* sC = smh6;             // [64 l][136]
    __half* sS = smh6 + 8704;      // [64 p][136]
    __shared__ float sDt[64], sAc[64];

    int bid = blockIdx.x;
    int h = bid & 31, c = (bid >> 5) & 31, b = bid >> 10;
    int tid = threadIdx.x;
    int w = tid >> 5, lane = tid & 31, gq = lane >> 2, tq = lane & 3;
    float Aval = -expf(A_log[h]);
    float Dv = Dp[h];
    int posBase = b * Lq + c * 64;

    if (tid < 64) sDt[tid] = g_dt[(posBase + tid) * HN + h];
    size_t sbase = ((size_t)((b * NC + c) * HN + h)) * 8192;
    #pragma unroll
    for (int k = 0; k < 8; k++) {
        int e4 = tid + k * 256;
        int row = e4 >> 5, col = (e4 & 31) * 4;
        float4 cv = *(const float4*)&g_xBC[(size_t)(posBase + row) * CDIM + DI + DS + col];
        float4 sv = *(const float4*)&g_sin[sbase + (size_t)row * 128 + col];
        __half2 c0 = __floats2half2_rn(cv.x, cv.y);
        __half2 c1 = __floats2half2_rn(cv.z, cv.w);
        __half2 s0 = __floats2half2_rn(sv.x, sv.y);
        __half2 s1 = __floats2half2_rn(sv.z, sv.w);
        *(__half2*)(sC + row * HSTR + col) = c0;
        *(__half2*)(sC + row * HSTR + col + 2) = c1;
        *(__half2*)(sS + row * HSTR + col) = s0;
        *(__half2*)(sS + row * HSTR + col + 2) = s1;
    }
    __syncthreads();
    if (tid == 0) {
        float acc = 0.f;
        for (int s = 0; s < 64; s++) { acc += sDt[s] * Aval; sAc[s] = acc; }
    }
    __syncthreads();

    int wm = (w >> 1) * 16, wn = (w & 1) * 32;
    float acc[4][4] = {};
    #pragma unroll
    for (int kk = 0; kk < 8; kk++) {
        int k16 = kk * 16;
        uint32_t af[4];
        int r0 = wm + gq;
        af[0] = lds32h(sC + r0 * HSTR + k16 + 2 * tq);
        af[1] = lds32h(sC + (r0 + 8) * HSTR + k16 + 2 * tq);
        af[2] = lds32h(sC + r0 * HSTR + k16 + 8 + 2 * tq);
        af[3] = lds32h(sC + (r0 + 8) * HSTR + k16 + 8 + 2 * tq);
        #pragma unroll
        for (int in = 0; in < 4; in++) {
            int n0 = wn + in * 8 + gq;
            uint32_t bf[2];
            bf[0] = lds32h(sS + n0 * HSTR + k16 + 2 * tq);
            bf[1] = lds32h(sS + n0 * HSTR + k16 + 8 + 2 * tq);
            mma_f16(acc[in], af, bf);
        }
    }
    int l0 = wm + gq, l1 = l0 + 8;
    float e0 = expf(sAc[l0]), e1 = expf(sAc[l1]);
    float* y0 = &g_Y[(size_t)(posBase + l0) * DI + h * 64];
    float* y1 = &g_Y[(size_t)(posBase + l1) * DI + h * 64];
    const float* x0 = &g_xBC[(size_t)(posBase + l0) * CDIM + h * 64];
    const float* x1 = &g_xBC[(size_t)(posBase + l1) * CDIM + h * 64];
    #pragma unroll
    for (int in = 0; in < 4; in++) {
        int p0 = wn + in * 8 + 2 * tq;
        y0[p0]     += e0 * acc[in][0] + x0[p0] * Dv;
        y0[p0 + 1] += e0 * acc[in][1] + x0[p0 + 1] * Dv;
        y1[p0]     += e1 * acc[in][2] + x1[p0] * Dv;
        y1[p0 + 1] += e1 * acc[in][3] + x1[p0 + 1] * Dv;
    }
}

// ---------------- K7: gated rmsnorm -> g_ynh (fp16) ----------------
__global__ void __launch_bounds__(256) k_gate(const float* __restrict__ w) {
    __shared__ float sv[DI];
    int row = blockIdx.x;
    int tid = threadIdx.x;
    float s = 0.f;
    for (int i = tid; i < DI; i += 256) {
        float z = g_zx[(size_t)row * PROJ + i];
        float y = g_Y[(size_t)row * DI + i];
        float v = y * z / (1.f + expf(-z));
        sv[i] = v;
        s += v * v;
    }
    float tot = block_sum(s);
    float inv = rsqrtf(tot / DI + 1e-5f);
    for (int i = tid; i < DI; i += 256)
        g_ynh[(size_t)row * DI + i] = __float2half_rn(sv[i] * inv * w[i]);
}

// ---------------- launcher ----------------
extern "C" void kernel_launch(void* const* d_in, const int* in_sizes, int n_in,
                              void* d_out, int out_size) {
    const float* x       = (const float*)d_in[0];
    const float* norm_w  = (const float*)d_in[1];
    const float* in_W    = (const float*)d_in[2];
    const float* conv_w  = (const float*)d_in[3];
    const float* conv_b  = (const float*)d_in[4];
    const float* dt_bias = (const float*)d_in[5];
    const float* A_log   = (const float*)d_in[6];
    const float* Dp      = (const float*)d_in[7];
    const float* ni_w    = (const float*)d_in[8];
    const float* out_W   = (const float*)d_in[9];
    float* out = (float*)d_out;

    cudaFuncSetAttribute(k_gemm1, cudaFuncAttributeMaxDynamicSharedMemorySize, SMEM_GEMM);
    cudaFuncSetAttribute(k_gemm2, cudaFuncAttributeMaxDynamicSharedMemorySize, SMEM_GEMM);
    cudaFuncSetAttribute(k_chunk, cudaFuncAttributeMaxDynamicSharedMemorySize, SMEM_K4);
    cudaFuncSetAttribute(k_inter, cudaFuncAttributeMaxDynamicSharedMemorySize, SMEM_K6);

    __half* d_Winh;  cudaGetSymbolAddress((void**)&d_Winh, g_Winh);
    __half* d_Wouth; cudaGetSymbolAddress((void**)&d_Wouth, g_Wouth);

    k_cvt_h<<<(PROJ * DM / 4 + 255) / 256, 256>>>(in_W, d_Winh, PROJ * DM / 4);
    k_cvt_h<<<(DM * DI / 4 + 255) / 256, 256>>>(out_W, d_Wouth, DM * DI / 4);
    k_rmsnorm<<<BL, 256>>>(x, norm_w);
    k_gemm1<<<dim3((PROJ + 127) / 128, BL / 128), 128, SMEM_GEMM>>>();
    k_conv<<<dim3(CDIM / CTC, BL / CTL), 256>>>(conv_w, conv_b);
    k_dt<<<(BL * HN + 255) / 256, 256>>>(dt_bias);
    k_chunk<<<Bq * NC * HN, 256, SMEM_K4>>>(A_log);
    k_scan<<<Bq * HN * 8, 256>>>();
    k_inter<<<Bq * NC * HN, 256, SMEM_K6>>>(A_log, Dp);
    k_gate<<<BL, 256>>>(ni_w);
    k_gemm2<<<dim3(DM / 128, BL / 128), 128, SMEM_GEMM>>>(x, out);
}

// round 14
// speedup vs baseline: 7.2075x; 1.1563x over previous
#include <cuda_runtime.h>
#include <cuda_fp16.h>
#include <math.h>
#include <stdint.h>

#define Bq 4
#define Lq 2048
#define DM 1024
#define DI 2048
#define HN 32
#define HD 64
#define DS 128
#define CDIM 2304
#define PROJ 4384
#define CH 64
#define NC 32
#define BL 8192

// ---------------- scratch (device globals; no allocations) ----------------
__device__ __half g_xnh[(size_t)BL * DM];       // rmsnorm(x), fp16
__device__ float g_zx[(size_t)BL * PROJ];       // zxbcdt
__device__ float g_xBC[(size_t)BL * CDIM];      // conv+silu output
__device__ float g_dt[BL * HN];                 // softplus dt
__device__ float g_Y[(size_t)BL * DI];          // SSD output (Yd then +=Yo)
__device__ __half g_statesh[(size_t)Bq * NC * HN * HD * DS];  // fp16 chunk states
__device__ __half g_sinh[(size_t)Bq * NC * HN * HD * DS];     // fp16 prefix states
__device__ float g_asum[Bq * HN * NC];
__device__ __half g_ynh[(size_t)BL * DI];       // gated+normed Y, fp16
__device__ __half g_Winh[(size_t)PROJ * DM];    // fp16 in_proj_W
__device__ __half g_Wouth[(size_t)DM * DI];     // fp16 out_proj_W

// ---------------- helpers ----------------
__device__ __forceinline__ float block_sum(float v) {
    __shared__ float red[8];
    #pragma unroll
    for (int o = 16; o; o >>= 1) v += __shfl_down_sync(0xffffffffu, v, o);
    if ((threadIdx.x & 31) == 0) red[threadIdx.x >> 5] = v;
    __syncthreads();
    if (threadIdx.x < 32) {
        v = (threadIdx.x < 8) ? red[threadIdx.x] : 0.f;
        #pragma unroll
        for (int o = 4; o; o >>= 1) v += __shfl_down_sync(0xffffffffu, v, o);
        if (threadIdx.x == 0) red[0] = v;
    }
    __syncthreads();
    return red[0];
}

__device__ __forceinline__ void mma_f16(float c[4], const uint32_t a[4], const uint32_t b[2]) {
    asm volatile(
        "mma.sync.aligned.m16n8k16.row.col.f32.f16.f16.f32 "
        "{%0,%1,%2,%3}, {%4,%5,%6,%7}, {%8,%9}, {%0,%1,%2,%3};"
        : "+f"(c[0]), "+f"(c[1]), "+f"(c[2]), "+f"(c[3])
        : "r"(a[0]), "r"(a[1]), "r"(a[2]), "r"(a[3]), "r"(b[0]), "r"(b[1]));
}

__device__ __forceinline__ uint32_t lds32h(const __half* p) {
    return *(const uint32_t*)p;
}

__device__ __forceinline__ void ldm_x4(const __half* p, uint32_t& r0, uint32_t& r1,
                                       uint32_t& r2, uint32_t& r3) {
    uint32_t a = (uint32_t)__cvta_generic_to_shared(p);
    asm volatile("ldmatrix.sync.aligned.m8n8.x4.shared.b16 {%0,%1,%2,%3}, [%4];"
                 : "=r"(r0), "=r"(r1), "=r"(r2), "=r"(r3) : "r"(a));
}

// ---------------- K0: convert weights fp32 -> fp16 ----------------
__global__ void __launch_bounds__(256) k_cvt_h(const float* __restrict__ src,
                                               __half* __restrict__ dst, int n4) {
    int i = blockIdx.x * 256 + threadIdx.x;
    if (i >= n4) return;
    float4 v = ((const float4*)src)[i];
    __half2 h0 = __floats2half2_rn(v.x, v.y);
    __half2 h1 = __floats2half2_rn(v.z, v.w);
    uint2 u;
    u.x = *(uint32_t*)&h0;
    u.y = *(uint32_t*)&h1;
    ((uint2*)dst)[i] = u;
}

// ---------------- K1: rmsnorm(x) -> g_xnh (fp16) ----------------
__global__ void __launch_bounds__(256) k_rmsnorm(const float* __restrict__ x,
                                                 const float* __restrict__ w) {
    int row = blockIdx.x;
    const float* xr = x + (size_t)row * DM;
    float s = 0.f;
    for (int i = threadIdx.x; i < DM; i += 256) { float v = xr[i]; s += v * v; }
    float tot = block_sum(s);
    float inv = rsqrtf(tot / DM + 1e-5f);
    for (int i = threadIdx.x; i < DM; i += 256)
        g_xnh[(size_t)row * DM + i] = __float2half_rn(xr[i] * inv * w[i]);
}

// ---------------- FP16 pipelined GEMM with ldmatrix ----------------
#define SROW 72
#define SA_H (128 * SROW)
#define STAGE_H (2 * SA_H)
#define SMEM_GEMM (STAGE_H * 2 * 2)

__device__ __forceinline__ void stage_copy16(const __half* __restrict__ A,
                                             const __half* __restrict__ Bw,
                                             __half* sA, __half* sB,
                                             int bm, int bn, int Nn, int K,
                                             int k0, int tid) {
    #pragma unroll
    for (int i = 0; i < 8; i++) {
        int c = tid + 128 * i;
        int row = c >> 3, c8 = (c & 7) * 8;
        uint32_t d = (uint32_t)__cvta_generic_to_shared(sA + row * SROW + c8);
        const __half* g = A + (size_t)(bm + row) * K + k0 + c8;
        asm volatile("cp.async.cg.shared.global [%0], [%1], 16;" :: "r"(d), "l"(g));
    }
    #pragma unroll
    for (int i = 0; i < 8; i++) {
        int c = tid + 128 * i;
        int row = c >> 3, c8 = (c & 7) * 8;
        uint32_t d = (uint32_t)__cvta_generic_to_shared(sB + row * SROW + c8);
        int n = bn + row;
        int ok = (n < Nn);
        const __half* g = Bw + (size_t)(ok ? n : 0) * K + k0 + c8;
        int sz = ok ? 16 : 0;
        asm volatile("cp.async.cg.shared.global [%0], [%1], 16, %2;" :: "r"(d), "l"(g), "r"(sz));
    }
}

// ldmatrix fragment loads: A 4x(16x16 via x4), B 4x(two n8k16 via x4)
__device__ __forceinline__ void load_frag16(const __half* sA, const __half* sB,
                                            int kk, uint32_t af[4][4], uint32_t bf[8][2],
                                            int wm, int wn, int lane) {
    int k16 = kk * 16;
    int lr = lane & 15, lc = (lane >> 4) * 8;
    #pragma unroll
    for (int im = 0; im < 4; im++)
        ldm_x4(sA + (wm + im * 16 + lr) * SROW + k16 + lc,
               af[im][0], af[im][1], af[im][2], af[im][3]);
    #pragma unroll
    for (int ip = 0; ip < 4; ip++)
        ldm_x4(sB + (wn + ip * 16 + lr) * SROW + k16 + lc,
               bf[2 * ip][0], bf[2 * ip + 1][0], bf[2 * ip][1], bf[2 * ip + 1][1]);
}

__device__ __forceinline__ void stage_compute16(const __half* sA, const __half* sB,
                                                float acc[4][8][4],
                                                int wm, int wn, int lane) {
    uint32_t af[2][4][4], bf[2][8][2];
    load_frag16(sA, sB, 0, af[0], bf[0], wm, wn, lane);
    #pragma unroll
    for (int kk = 0; kk < 4; kk++) {
        int cur = kk & 1;
        if (kk < 3)
            load_frag16(sA, sB, kk + 1, af[cur ^ 1], bf[cur ^ 1], wm, wn, lane);
        #pragma unroll
        for (int im = 0; im < 4; im++)
            #pragma unroll
            for (int in = 0; in < 8; in++)
                mma_f16(acc[im][in], af[cur][im], bf[cur][in]);
    }
}

__device__ __forceinline__ void gemm_f16_body(const __half* __restrict__ A,
                                              const __half* __restrict__ Bw,
                                              const float* __restrict__ Res,
                                              float* __restrict__ C,
                                              int M, int Nn, int K) {
    extern __shared__ __half smh[];
    int bm = blockIdx.y * 128, bn = blockIdx.x * 128;
    int tid = threadIdx.x;
    int w = tid >> 5, lane = tid & 31, g = lane >> 2, t = lane & 3;
    int wm = (w >> 1) * 64, wn = (w & 1) * 64;

    float acc[4][8][4] = {};

    stage_copy16(A, Bw, smh, smh + SA_H, bm, bn, Nn, K, 0, tid);
    asm volatile("cp.async.commit_group;");

    int nk = K / 64;
    for (int kt = 0; kt < nk; kt++) {
        asm volatile("cp.async.wait_group 0;");
        __syncthreads();
        if (kt + 1 < nk) {
            int s = (kt + 1) & 1;
            stage_copy16(A, Bw, smh + s * STAGE_H, smh + s * STAGE_H + SA_H,
                         bm, bn, Nn, K, (kt + 1) * 64, tid);
            asm volatile("cp.async.commit_group;");
        }
        int cur = kt & 1;
        stage_compute16(smh + cur * STAGE_H, smh + cur * STAGE_H + SA_H,
                        acc, wm, wn, lane);
    }

    #pragma unroll
    for (int im = 0; im < 4; im++) {
        int row = bm + wm + im * 16 + g;
        #pragma unroll
        for (int in = 0; in < 8; in++) {
            int col = bn + wn + in * 8 + 2 * t;
            if (col < Nn) {
                size_t o0 = (size_t)row * Nn + col;
                size_t o1 = (size_t)(row + 8) * Nn + col;
                float v0 = acc[im][in][0], v1 = acc[im][in][1];
                float v2 = acc[im][in][2], v3 = acc[im][in][3];
                if (Res) {
                    v0 += Res[o0]; v1 += Res[o0 + 1];
                    v2 += Res[o1]; v3 += Res[o1 + 1];
                }
                C[o0] = v0; C[o0 + 1] = v1;
                C[o1] = v2; C[o1 + 1] = v3;
            }
        }
    }
}

__global__ void __launch_bounds__(128) k_gemm1() {
    gemm_f16_body(g_xnh, g_Winh, nullptr, g_zx, BL, PROJ, DM);
}
__global__ void __launch_bounds__(128) k_gemm2(const float* __restrict__ x,
                                               float* __restrict__ out) {
    gemm_f16_body(g_ynh, g_Wouth, x, out, BL, DM, DI);
}

// ---------------- K3: tiled causal depthwise conv (w=4) + silu -> g_xBC ----
#define CTL 32
#define CTC 128
__global__ void __launch_bounds__(256) k_conv(const float* __restrict__ cw,
                                              const float* __restrict__ cb) {
    __shared__ float s[(CTL + 3) * CTC];
    int ct = blockIdx.x * CTC;
    int blt = blockIdx.y * CTL;
    int l0 = blt & (Lq - 1);
    int tid = threadIdx.x;

    for (int idx = tid; idx < (CTL + 3) * CTC; idx += 256) {
        int r = (idx >> 7) - 3;
        int ch = idx & 127;
        float v = 0.f;
        if (l0 + r >= 0)
            v = g_zx[(size_t)(blt + r) * PROJ + DI + ct + ch];
        s[idx] = v;
    }
    __syncthreads();

    int ch = tid & 127;
    int li0 = (tid >> 7) * 16;
    float w0 = cw[0 * CDIM + ct + ch];
    float w1 = cw[1 * CDIM + ct + ch];
    float w2 = cw[2 * CDIM + ct + ch];
    float w3 = cw[3 * CDIM + ct + ch];
    float bias = cb[ct + ch];

    #pragma unroll
    for (int i = 0; i < 16; i++) {
        int li = li0 + i;
        float acc = bias
                  + w0 * s[li * CTC + ch]
                  + w1 * s[(li + 1) * CTC + ch]
                  + w2 * s[(li + 2) * CTC + ch]
                  + w3 * s[(li + 3) * CTC + ch];
        acc = acc / (1.f + expf(-acc));
        g_xBC[(size_t)(blt + li) * CDIM + ct + ch] = acc;
    }
}

// ---------------- K3b: dt = softplus(raw + bias) ----------------
__global__ void __launch_bounds__(256) k_dt(const float* __restrict__ dt_bias) {
    int idx = blockIdx.x * 256 + threadIdx.x;
    if (idx >= BL * HN) return;
    int h = idx & 31;
    float v = g_zx[(size_t)(idx >> 5) * PROJ + DI + CDIM + h] + dt_bias[h];
    g_dt[idx] = (v > 20.f) ? v : log1pf(expf(v));
}

// ---------------- K4: intra-chunk via FP16 mma ----------------
#define HSTR 136
#define XSTR 72
#define HOFF_C  0
#define HOFF_B  8704
#define HOFF_XT 17408
#define HOFF_XD 22016
#define HOFF_G  26624
#define HOFF_BT 31232
#define SMEM_K4 ((31232 + 128 * 72) * 2)   // 80896 bytes

__global__ void __launch_bounds__(256) k_chunk(const float* __restrict__ A_log) {
    extern __shared__ __half smh4[];
    __half* sC  = smh4 + HOFF_C;
    __half* sB  = smh4 + HOFF_B;
    __half* sXT = smh4 + HOFF_XT;
    __half* sXD = smh4 + HOFF_XD;
    __half* sG  = smh4 + HOFF_G;
    __half* sBT = smh4 + HOFF_BT;
    __shared__ float sDt[64], sAc[64], sDec[64];

    int bid = blockIdx.x;
    int h = bid & 31, c = (bid >> 5) & 31, b = bid >> 10;
    int tid = threadIdx.x;
    int w = tid >> 5, lane = tid & 31, gq = lane >> 2, tq = lane & 3;
    float Aval = -expf(A_log[h]);
    int posBase = b * Lq + c * 64;

    if (tid < 64) sDt[tid] = g_dt[(posBase + tid) * HN + h];
    #pragma unroll
    for (int k = 0; k < 8; k++) {
        int e4 = tid + k * 256;
        int row = e4 >> 5, col = (e4 & 31) * 4;
        const float* base = &g_xBC[(size_t)(posBase + row) * CDIM + DI];
        float4 bv = *(const float4*)(base + col);
        float4 cv = *(const float4*)(base + DS + col);
        __half2 b0 = __floats2half2_rn(bv.x, bv.y);
        __half2 b1 = __floats2half2_rn(bv.z, bv.w);
        __half2 c0 = __floats2half2_rn(cv.x, cv.y);
        __half2 c1 = __floats2half2_rn(cv.z, cv.w);
        *(__half2*)(sB + row * HSTR + col) = b0;
        *(__half2*)(sB + row * HSTR + col + 2) = b1;
        *(__half2*)(sC + row * HSTR + col) = c0;
        *(__half2*)(sC + row * HSTR + col + 2) = c1;
    }
    __syncthreads();
    if (tid == 0) {
        float acc = 0.f;
        for (int s = 0; s < 64; s++) { acc += sDt[s] * Aval; sAc[s] = acc; }
    }
    #pragma unroll
    for (int k = 0; k < 32; k++) {
        int e = tid + k * 256;
        int n = e & 127, s = e >> 7;
        sBT[n * XSTR + s] = sB[s * HSTR + n];
    }
    __syncthreads();
    if (tid < 64) sDec[tid] = expf(sAc[63] - sAc[tid]);
    __syncthreads();
    #pragma unroll
    for (int k = 0; k < 16; k++) {
        int e = tid + k * 256;
        int p = e & 63, s = e >> 6;
        float xv = g_xBC[(size_t)(posBase + s) * CDIM + h * 64 + p] * sDt[s];
        sXT[p * XSTR + s] = __float2half_rn(xv);
        sXD[p * XSTR + s] = __float2half_rn(xv * sDec[s]);
    }
    __syncthreads();

    {
        int wm = (w >> 1) * 16, wn = (w & 1) * 32;
        float acc[4][4] = {};
        #pragma unroll
        for (int kk = 0; kk < 8; kk++) {
            int k16 = kk * 16;
            uint32_t af[4];
            int r0 = wm + gq;
            af[0] = lds32h(sC + r0 * HSTR + k16 + 2 * tq);
            af[1] = lds32h(sC + (r0 + 8) * HSTR + k16 + 2 * tq);
            af[2] = lds32h(sC + r0 * HSTR + k16 + 8 + 2 * tq);
            af[3] = lds32h(sC + (r0 + 8) * HSTR + k16 + 8 + 2 * tq);
            #pragma unroll
            for (int in = 0; in < 4; in++) {
                int n0 = wn + in * 8 + gq;
                uint32_t bf[2];
                bf[0] = lds32h(sB + n0 * HSTR + k16 + 2 * tq);
                bf[1] = lds32h(sB + n0 * HSTR + k16 + 8 + 2 * tq);
                mma_f16(acc[in], af, bf);
            }
        }
        int l0 = wm + gq, l1 = l0 + 8;
        float a0 = sAc[l0], a1 = sAc[l1];
        #pragma unroll
        for (int in = 0; in < 4; in++) {
            int s0 = wn + in * 8 + 2 * tq, s1 = s0 + 1;
            float as0 = sAc[s0], as1 = sAc[s1];
            sG[l0 * XSTR + s0] = __float2half_rn((l0 >= s0) ? expf(a0 - as0) * acc[in][0] : 0.f);
            sG[l0 * XSTR + s1] = __float2half_rn((l0 >= s1) ? expf(a0 - as1) * acc[in][1] : 0.f);
            sG[l1 * XSTR + s0] = __float2half_rn((l1 >= s0) ? expf(a1 - as0) * acc[in][2] : 0.f);
            sG[l1 * XSTR + s1] = __float2half_rn((l1 >= s1) ? expf(a1 - as1) * acc[in][3] : 0.f);
        }
    }
    __syncthreads();

    {
        int wm = (w >> 1) * 16, wn = (w & 1) * 32;
        float acc[4][4] = {};
        #pragma unroll
        for (int kk = 0; kk < 4; kk++) {
            int k16 = kk * 16;
            uint32_t af[4];
            int r0 = wm + gq;
            af[0] = lds32h(sG + r0 * XSTR + k16 + 2 * tq);
            af[1] = lds32h(sG + (r0 + 8) * XSTR + k16 + 2 * tq);
            af[2] = lds32h(sG + r0 * XSTR + k16 + 8 + 2 * tq);
            af[3] = lds32h(sG + (r0 + 8) * XSTR + k16 + 8 + 2 * tq);
            #pragma unroll
            for (int in = 0; in < 4; in++) {
                int n0 = wn + in * 8 + gq;
                uint32_t bf[2];
                bf[0] = lds32h(sXT + n0 * XSTR + k16 + 2 * tq);
                bf[1] = lds32h(sXT + n0 * XSTR + k16 + 8 + 2 * tq);
                mma_f16(acc[in], af, bf);
            }
        }
        int l0 = wm + gq, l1 = l0 + 8;
        float* y0 = &g_Y[(size_t)(posBase + l0) * DI + h * 64];
        float* y1 = &g_Y[(size_t)(posBase + l1) * DI + h * 64];
        #pragma unroll
        for (int in = 0; in < 4; in++) {
            int p0 = wn + in * 8 + 2 * tq;
            y0[p0] = acc[in][0]; y0[p0 + 1] = acc[in][1];
            y1[p0] = acc[in][2]; y1[p0 + 1] = acc[in][3];
        }
    }

    {
        int wm = (w >> 1) * 16, wn = (w & 1) * 64;
        float acc[8][4] = {};
        #pragma unroll
        for (int kk = 0; kk < 4; kk++) {
            int k16 = kk * 16;
            uint32_t af[4];
            int r0 = wm + gq;
            af[0] = lds32h(sXD + r0 * XSTR + k16 + 2 * tq);
            af[1] = lds32h(sXD + (r0 + 8) * XSTR + k16 + 2 * tq);
            af[2] = lds32h(sXD + r0 * XSTR + k16 + 8 + 2 * tq);
            af[3] = lds32h(sXD + (r0 + 8) * XSTR + k16 + 8 + 2 * tq);
            #pragma unroll
            for (int in = 0; in < 8; in++) {
                int n0 = wn + in * 8 + gq;
                uint32_t bf[2];
                bf[0] = lds32h(sBT + n0 * XSTR + k16 + 2 * tq);
                bf[1] = lds32h(sBT + n0 * XSTR + k16 + 8 + 2 * tq);
                mma_f16(acc[in], af, bf);
            }
        }
        size_t sbase = ((size_t)((b * NC + c) * HN + h)) * (64 * 128);
        int p0 = wm + gq, p1 = p0 + 8;
        #pragma unroll
        for (int in = 0; in < 8; in++) {
            int n0 = wn + in * 8 + 2 * tq;
            *(__half2*)(g_statesh + sbase + (size_t)p0 * 128 + n0) =
                __floats2half2_rn(acc[in][0], acc[in][1]);
            *(__half2*)(g_statesh + sbase + (size_t)p1 * 128 + n0) =
                __floats2half2_rn(acc[in][2], acc[in][3]);
        }
    }
    if (tid == 0) g_asum[(b * HN + h) * NC + c] = sAc[63];
}

// ---------------- K5: inter-chunk prefix scan (fp16 storage, fp32 accum) ---
// grid = Bq*HN*4; each thread owns one uint4 (8 halves) across the 32 chunks.
__global__ void __launch_bounds__(256) k_scan() {
    int bid = blockIdx.x;
    int seg = bid & 3;
    int bh = bid >> 2;
    int b = bh >> 5, h = bh & 31;
    int e = seg * 256 + threadIdx.x;     // uint4 index: 1024 per state
    const float* asum = &g_asum[(b * HN + h) * NC];
    float S[8];
    #pragma unroll
    for (int j = 0; j < 8; j++) S[j] = 0.f;
    for (int c = 0; c < NC; c++) {
        size_t base = ((size_t)((b * NC + c) * HN + h)) * 1024;  // uint4 units
        float dec = expf(asum[c]);
        __half2 o[4];
        #pragma unroll
        for (int j = 0; j < 4; j++) o[j] = __floats2half2_rn(S[2 * j], S[2 * j + 1]);
        ((uint4*)g_sinh)[base + e] = *(uint4*)o;
        uint4 stv = ((const uint4*)g_statesh)[base + e];
        __half2* sth = (__half2*)&stv;
        #pragma unroll
        for (int j = 0; j < 4; j++) {
            float2 f = __half22float2(sth[j]);
            S[2 * j]     = S[2 * j] * dec + f.x;
            S[2 * j + 1] = S[2 * j + 1] * dec + f.y;
        }
    }
}

// ---------------- K6: Yo = exp(Ac) * C * S^T via fp16 mma; Y += Yo + xs*D --
#define SMEM_K6 (8704 * 2 * 2)   // 34816 bytes
__global__ void __launch_bounds__(256) k_inter(const float* __restrict__ A_log,
                                               const float* __restrict__ Dp) {
    extern __shared__ __half smh6[];
    __half* sC = smh6;
    __half* sS = smh6 + 8704;
    __shared__ float sDt[64], sAc[64];

    int bid = blockIdx.x;
    int h = bid & 31, c = (bid >> 5) & 31, b = bid >> 10;
    int tid = threadIdx.x;
    int w = tid >> 5, lane = tid & 31, gq = lane >> 2, tq = lane & 3;
    float Aval = -expf(A_log[h]);
    float Dv = Dp[h];
    int posBase = b * Lq + c * 64;

    if (tid < 64) sDt[tid] = g_dt[(posBase + tid) * HN + h];
    size_t sbase = ((size_t)((b * NC + c) * HN + h)) * 8192;
    #pragma unroll
    for (int k = 0; k < 8; k++) {
        int e4 = tid + k * 256;
        int row = e4 >> 5, col = (e4 & 31) * 4;
        float4 cv = *(const float4*)&g_xBC[(size_t)(posBase + row) * CDIM + DI + DS + col];
        __half2 c0 = __floats2half2_rn(cv.x, cv.y);
        __half2 c1 = __floats2half2_rn(cv.z, cv.w);
        *(__half2*)(sC + row * HSTR + col) = c0;
        *(__half2*)(sC + row * HSTR + col + 2) = c1;
    }
    // prefix state: already half, straight copy (8 halves per thread-iter)
    #pragma unroll
    for (int k = 0; k < 4; k++) {
        int e = tid + k * 256;               // uint4 index over 1024
        int row = e >> 4, col = (e & 15) * 8;
        uint4 v = ((const uint4*)(g_sinh + sbase))[e];
        *(uint4*)(sS + row * HSTR + col) = v;
    }
    __syncthreads();
    if (tid == 0) {
        float acc = 0.f;
        for (int s = 0; s < 64; s++) { acc += sDt[s] * Aval; sAc[s] = acc; }
    }
    __syncthreads();

    int wm = (w >> 1) * 16, wn = (w & 1) * 32;
    float acc[4][4] = {};
    #pragma unroll
    for (int kk = 0; kk < 8; kk++) {
        int k16 = kk * 16;
        uint32_t af[4];
        int r0 = wm + gq;
        af[0] = lds32h(sC + r0 * HSTR + k16 + 2 * tq);
        af[1] = lds32h(sC + (r0 + 8) * HSTR + k16 + 2 * tq);
        af[2] = lds32h(sC + r0 * HSTR + k16 + 8 + 2 * tq);
        af[3] = lds32h(sC + (r0 + 8) * HSTR + k16 + 8 + 2 * tq);
        #pragma unroll
        for (int in = 0; in < 4; in++) {
            int n0 = wn + in * 8 + gq;
            uint32_t bf[2];
            bf[0] = lds32h(sS + n0 * HSTR + k16 + 2 * tq);
            bf[1] = lds32h(sS + n0 * HSTR + k16 + 8 + 2 * tq);
            mma_f16(acc[in], af, bf);
        }
    }
    int l0 = wm + gq, l1 = l0 + 8;
    float e0 = expf(sAc[l0]), e1 = expf(sAc[l1]);
    float* y0 = &g_Y[(size_t)(posBase + l0) * DI + h * 64];
    float* y1 = &g_Y[(size_t)(posBase + l1) * DI + h * 64];
    const float* x0 = &g_xBC[(size_t)(posBase + l0) * CDIM + h * 64];
    const float* x1 = &g_xBC[(size_t)(posBase + l1) * CDIM + h * 64];
    #pragma unroll
    for (int in = 0; in < 4; in++) {
        int p0 = wn + in * 8 + 2 * tq;
        y0[p0]     += e0 * acc[in][0] + x0[p0] * Dv;
        y0[p0 + 1] += e0 * acc[in][1] + x0[p0 + 1] * Dv;
        y1[p0]     += e1 * acc[in][2] + x1[p0] * Dv;
        y1[p0 + 1] += e1 * acc[in][3] + x1[p0 + 1] * Dv;
    }
}

// ---------------- K7: gated rmsnorm -> g_ynh (fp16) ----------------
__global__ void __launch_bounds__(256) k_gate(const float* __restrict__ w) {
    __shared__ float sv[DI];
    int row = blockIdx.x;
    int tid = threadIdx.x;
    float s = 0.f;
    for (int i = tid; i < DI; i += 256) {
        float z = g_zx[(size_t)row * PROJ + i];
        float y = g_Y[(size_t)row * DI + i];
        float v = y * z / (1.f + expf(-z));
        sv[i] = v;
        s += v * v;
    }
    float tot = block_sum(s);
    float inv = rsqrtf(tot / DI + 1e-5f);
    for (int i = tid; i < DI; i += 256)
        g_ynh[(size_t)row * DI + i] = __float2half_rn(sv[i] * inv * w[i]);
}

// ---------------- launcher ----------------
extern "C" void kernel_launch(void* const* d_in, const int* in_sizes, int n_in,
                              void* d_out, int out_size) {
    const float* x       = (const float*)d_in[0];
    const float* norm_w  = (const float*)d_in[1];
    const float* in_W    = (const float*)d_in[2];
    const float* conv_w  = (const float*)d_in[3];
    const float* conv_b  = (const float*)d_in[4];
    const float* dt_bias = (const float*)d_in[5];
    const float* A_log   = (const float*)d_in[6];
    const float* Dp      = (const float*)d_in[7];
    const float* ni_w    = (const float*)d_in[8];
    const float* out_W   = (const float*)d_in[9];
    float* out = (float*)d_out;

    cudaFuncSetAttribute(k_gemm1, cudaFuncAttributeMaxDynamicSharedMemorySize, SMEM_GEMM);
    cudaFuncSetAttribute(k_gemm2, cudaFuncAttributeMaxDynamicSharedMemorySize, SMEM_GEMM);
    cudaFuncSetAttribute(k_chunk, cudaFuncAttributeMaxDynamicSharedMemorySize, SMEM_K4);
    cudaFuncSetAttribute(k_inter, cudaFuncAttributeMaxDynamicSharedMemorySize, SMEM_K6);

    __half* d_Winh;  cudaGetSymbolAddress((void**)&d_Winh, g_Winh);
    __half* d_Wouth; cudaGetSymbolAddress((void**)&d_Wouth, g_Wouth);

    k_cvt_h<<<(PROJ * DM / 4 + 255) / 256, 256>>>(in_W, d_Winh, PROJ * DM / 4);
    k_cvt_h<<<(DM * DI / 4 + 255) / 256, 256>>>(out_W, d_Wouth, DM * DI / 4);
    k_rmsnorm<<<BL, 256>>>(x, norm_w);
    k_gemm1<<<dim3((PROJ + 127) / 128, BL / 128), 128, SMEM_GEMM>>>();
    k_conv<<<dim3(CDIM / CTC, BL / CTL), 256>>>(conv_w, conv_b);
    k_dt<<<(BL * HN + 255) / 256, 256>>>(dt_bias);
    k_chunk<<<Bq * NC * HN, 256, SMEM_K4>>>(A_log);
    k_scan<<<Bq * HN * 4, 256>>>();
    k_inter<<<Bq * NC * HN, 256, SMEM_K6>>>(A_log, Dp);
    k_gate<<<BL, 256>>>(ni_w);
    k_gemm2<<<dim3(DM / 128, BL / 128), 128, SMEM_GEMM>>>(x, out);
}

// round 16
// speedup vs baseline: 8.5764x; 1.1899x over previous
#include <cuda_runtime.h>
#include <cuda_fp16.h>
#include <math.h>
#include <stdint.h>

#define Bq 4
#define Lq 2048
#define DM 1024
#define DI 2048
#define HN 32
#define HD 64
#define DS 128
#define CDIM 2304
#define PROJ 4384
#define CH 64
#define NC 32
#define BL 8192

// ---------------- scratch (device globals; no allocations) ----------------
__device__ __half g_xnh[(size_t)BL * DM];       // rmsnorm(x), fp16
__device__ float g_zx[(size_t)BL * PROJ];       // zxbcdt
__device__ __half g_xBCh[(size_t)BL * CDIM];    // conv+silu output (fp16)
__device__ float g_dt[BL * HN];                 // softplus dt
__device__ float g_Y[(size_t)BL * DI];          // SSD output (written once)
__device__ __half g_statesh[(size_t)Bq * NC * HN * HD * DS];
__device__ __half g_sinh[(size_t)Bq * NC * HN * HD * DS];
__device__ float g_asum[Bq * HN * NC];
__device__ __half g_ynh[(size_t)BL * DI];       // gated+normed Y, fp16
__device__ __half g_Winh[(size_t)PROJ * DM];
__device__ __half g_Wouth[(size_t)DM * DI];

// ---------------- helpers ----------------
__device__ __forceinline__ float block_sum(float v) {
    __shared__ float red[8];
    #pragma unroll
    for (int o = 16; o; o >>= 1) v += __shfl_down_sync(0xffffffffu, v, o);
    if ((threadIdx.x & 31) == 0) red[threadIdx.x >> 5] = v;
    __syncthreads();
    if (threadIdx.x < 32) {
        v = (threadIdx.x < 8) ? red[threadIdx.x] : 0.f;
        #pragma unroll
        for (int o = 4; o; o >>= 1) v += __shfl_down_sync(0xffffffffu, v, o);
        if (threadIdx.x == 0) red[0] = v;
    }
    __syncthreads();
    return red[0];
}

__device__ __forceinline__ void mma_f16(float c[4], const uint32_t a[4], const uint32_t b[2]) {
    asm volatile(
        "mma.sync.aligned.m16n8k16.row.col.f32.f16.f16.f32 "
        "{%0,%1,%2,%3}, {%4,%5,%6,%7}, {%8,%9}, {%0,%1,%2,%3};"
        : "+f"(c[0]), "+f"(c[1]), "+f"(c[2]), "+f"(c[3])
        : "r"(a[0]), "r"(a[1]), "r"(a[2]), "r"(a[3]), "r"(b[0]), "r"(b[1]));
}

__device__ __forceinline__ uint32_t lds32h(const __half* p) {
    return *(const uint32_t*)p;
}

__device__ __forceinline__ void ldm_x4(const __half* p, uint32_t& r0, uint32_t& r1,
                                       uint32_t& r2, uint32_t& r3) {
    uint32_t a = (uint32_t)__cvta_generic_to_shared(p);
    asm volatile("ldmatrix.sync.aligned.m8n8.x4.shared.b16 {%0,%1,%2,%3}, [%4];"
                 : "=r"(r0), "=r"(r1), "=r"(r2), "=r"(r3) : "r"(a));
}

// ---------------- K0: convert weights fp32 -> fp16 ----------------
__global__ void __launch_bounds__(256) k_cvt_h(const float* __restrict__ src,
                                               __half* __restrict__ dst, int n4) {
    int i = blockIdx.x * 256 + threadIdx.x;
    if (i >= n4) return;
    float4 v = ((const float4*)src)[i];
    __half2 h0 = __floats2half2_rn(v.x, v.y);
    __half2 h1 = __floats2half2_rn(v.z, v.w);
    uint2 u;
    u.x = *(uint32_t*)&h0;
    u.y = *(uint32_t*)&h1;
    ((uint2*)dst)[i] = u;
}

// ---------------- K1: rmsnorm(x) -> g_xnh (fp16) ----------------
__global__ void __launch_bounds__(256) k_rmsnorm(const float* __restrict__ x,
                                                 const float* __restrict__ w) {
    int row = blockIdx.x;
    const float* xr = x + (size_t)row * DM;
    float s = 0.f;
    for (int i = threadIdx.x; i < DM; i += 256) { float v = xr[i]; s += v * v; }
    float tot = block_sum(s);
    float inv = rsqrtf(tot / DM + 1e-5f);
    for (int i = threadIdx.x; i < DM; i += 256)
        g_xnh[(size_t)row * DM + i] = __float2half_rn(xr[i] * inv * w[i]);
}

// ---------------- FP16 pipelined GEMM with ldmatrix ----------------
#define SROW 72
#define SA_H (128 * SROW)
#define STAGE_H (2 * SA_H)
#define SMEM_GEMM (STAGE_H * 2 * 2)

__device__ __forceinline__ void stage_copy16(const __half* __restrict__ A,
                                             const __half* __restrict__ Bw,
                                             __half* sA, __half* sB,
                                             int bm, int bn, int Nn, int K,
                                             int k0, int tid) {
    #pragma unroll
    for (int i = 0; i < 8; i++) {
        int c = tid + 128 * i;
        int row = c >> 3, c8 = (c & 7) * 8;
        uint32_t d = (uint32_t)__cvta_generic_to_shared(sA + row * SROW + c8);
        const __half* g = A + (size_t)(bm + row) * K + k0 + c8;
        asm volatile("cp.async.cg.shared.global [%0], [%1], 16;" :: "r"(d), "l"(g));
    }
    #pragma unroll
    for (int i = 0; i < 8; i++) {
        int c = tid + 128 * i;
        int row = c >> 3, c8 = (c & 7) * 8;
        uint32_t d = (uint32_t)__cvta_generic_to_shared(sB + row * SROW + c8);
        int n = bn + row;
        int ok = (n < Nn);
        const __half* g = Bw + (size_t)(ok ? n : 0) * K + k0 + c8;
        int sz = ok ? 16 : 0;
        asm volatile("cp.async.cg.shared.global [%0], [%1], 16, %2;" :: "r"(d), "l"(g), "r"(sz));
    }
}

__device__ __forceinline__ void load_frag16(const __half* sA, const __half* sB,
                                            int kk, uint32_t af[4][4], uint32_t bf[8][2],
                                            int wm, int wn, int lane) {
    int k16 = kk * 16;
    int lr = lane & 15, lc = (lane >> 4) * 8;
    #pragma unroll
    for (int im = 0; im < 4; im++)
        ldm_x4(sA + (wm + im * 16 + lr) * SROW + k16 + lc,
               af[im][0], af[im][1], af[im][2], af[im][3]);
    #pragma unroll
    for (int ip = 0; ip < 4; ip++)
        ldm_x4(sB + (wn + ip * 16 + lr) * SROW + k16 + lc,
               bf[2 * ip][0], bf[2 * ip + 1][0], bf[2 * ip][1], bf[2 * ip + 1][1]);
}

__device__ __forceinline__ void stage_compute16(const __half* sA, const __half* sB,
                                                float acc[4][8][4],
                                                int wm, int wn, int lane) {
    uint32_t af[2][4][4], bf[2][8][2];
    load_frag16(sA, sB, 0, af[0], bf[0], wm, wn, lane);
    #pragma unroll
    for (int kk = 0; kk < 4; kk++) {
        int cur = kk & 1;
        if (kk < 3)
            load_frag16(sA, sB, kk + 1, af[cur ^ 1], bf[cur ^ 1], wm, wn, lane);
        #pragma unroll
        for (int im = 0; im < 4; im++)
            #pragma unroll
            for (int in = 0; in < 8; in++)
                mma_f16(acc[im][in], af[cur][im], bf[cur][in]);
    }
}

__device__ __forceinline__ void gemm_f16_body(const __half* __restrict__ A,
                                              const __half* __restrict__ Bw,
                                              const float* __restrict__ Res,
                                              float* __restrict__ C,
                                              int M, int Nn, int K) {
    extern __shared__ __half smh[];
    int bm = blockIdx.y * 128, bn = blockIdx.x * 128;
    int tid = threadIdx.x;
    int w = tid >> 5, lane = tid & 31, g = lane >> 2, t = lane & 3;
    int wm = (w >> 1) * 64, wn = (w & 1) * 64;

    float acc[4][8][4] = {};

    stage_copy16(A, Bw, smh, smh + SA_H, bm, bn, Nn, K, 0, tid);
    asm volatile("cp.async.commit_group;");

    int nk = K / 64;
    for (int kt = 0; kt < nk; kt++) {
        asm volatile("cp.async.wait_group 0;");
        __syncthreads();
        if (kt + 1 < nk) {
            int s = (kt + 1) & 1;
            stage_copy16(A, Bw, smh + s * STAGE_H, smh + s * STAGE_H + SA_H,
                         bm, bn, Nn, K, (kt + 1) * 64, tid);
            asm volatile("cp.async.commit_group;");
        }
        int cur = kt & 1;
        stage_compute16(smh + cur * STAGE_H, smh + cur * STAGE_H + SA_H,
                        acc, wm, wn, lane);
    }

    #pragma unroll
    for (int im = 0; im < 4; im++) {
        int row = bm + wm + im * 16 + g;
        #pragma unroll
        for (int in = 0; in < 8; in++) {
            int col = bn + wn + in * 8 + 2 * t;
            if (col < Nn) {
                size_t o0 = (size_t)row * Nn + col;
                size_t o1 = (size_t)(row + 8) * Nn + col;
                float v0 = acc[im][in][0], v1 = acc[im][in][1];
                float v2 = acc[im][in][2], v3 = acc[im][in][3];
                if (Res) {
                    v0 += Res[o0]; v1 += Res[o0 + 1];
                    v2 += Res[o1]; v3 += Res[o1 + 1];
                }
                C[o0] = v0; C[o0 + 1] = v1;
                C[o1] = v2; C[o1 + 1] = v3;
            }
        }
    }
}

__global__ void __launch_bounds__(128) k_gemm1() {
    gemm_f16_body(g_xnh, g_Winh, nullptr, g_zx, BL, PROJ, DM);
}
__global__ void __launch_bounds__(128) k_gemm2(const float* __restrict__ x,
                                               float* __restrict__ out) {
    gemm_f16_body(g_ynh, g_Wouth, x, out, BL, DM, DI);
}

// ---------------- K3: tiled causal conv (w=4) + silu -> g_xBCh (fp16) -----
#define CTL 32
#define CTC 128
__global__ void __launch_bounds__(256) k_conv(const float* __restrict__ cw,
                                              const float* __restrict__ cb) {
    __shared__ float s[(CTL + 3) * CTC];
    int ct = blockIdx.x * CTC;
    int blt = blockIdx.y * CTL;
    int l0 = blt & (Lq - 1);
    int tid = threadIdx.x;

    for (int idx = tid; idx < (CTL + 3) * CTC; idx += 256) {
        int r = (idx >> 7) - 3;
        int ch = idx & 127;
        float v = 0.f;
        if (l0 + r >= 0)
            v = g_zx[(size_t)(blt + r) * PROJ + DI + ct + ch];
        s[idx] = v;
    }
    __syncthreads();

    int ch = tid & 127;
    int li0 = (tid >> 7) * 16;
    float w0 = cw[0 * CDIM + ct + ch];
    float w1 = cw[1 * CDIM + ct + ch];
    float w2 = cw[2 * CDIM + ct + ch];
    float w3 = cw[3 * CDIM + ct + ch];
    float bias = cb[ct + ch];

    #pragma unroll
    for (int i = 0; i < 16; i++) {
        int li = li0 + i;
        float acc = bias
                  + w0 * s[li * CTC + ch]
                  + w1 * s[(li + 1) * CTC + ch]
                  + w2 * s[(li + 2) * CTC + ch]
                  + w3 * s[(li + 3) * CTC + ch];
        acc = acc / (1.f + expf(-acc));
        g_xBCh[(size_t)(blt + li) * CDIM + ct + ch] = __float2half_rn(acc);
    }
}

// ---------------- K3b: dt = softplus(raw + bias) ----------------
__global__ void __launch_bounds__(256) k_dt(const float* __restrict__ dt_bias) {
    int idx = blockIdx.x * 256 + threadIdx.x;
    if (idx >= BL * HN) return;
    int h = idx & 31;
    float v = g_zx[(size_t)(idx >> 5) * PROJ + DI + CDIM + h] + dt_bias[h];
    g_dt[idx] = (v > 20.f) ? v : log1pf(expf(v));
}

// ---------------- K4a: states pass (fp16 mma) ----------------
#define HSTR 136
#define XSTR 72
__global__ void __launch_bounds__(256) k_states(const float* __restrict__ A_log) {
    __shared__ __half sB[64 * HSTR];
    __shared__ __half sBT[128 * XSTR];
    __shared__ __half sXD[64 * XSTR];
    __shared__ float sDt[64], sAc[64], sDec[64];

    int bid = blockIdx.x;
    int h = bid & 31, c = (bid >> 5) & 31, b = bid >> 10;
    int tid = threadIdx.x;
    int w = tid >> 5, lane = tid & 31, gq = lane >> 2, tq = lane & 3;
    float Aval = -expf(A_log[h]);
    int posBase = b * Lq + c * 64;

    if (tid < 64) sDt[tid] = g_dt[(posBase + tid) * HN + h];
    #pragma unroll
    for (int k = 0; k < 4; k++) {
        int e = tid + k * 256;
        int row = e >> 4, c8 = (e & 15) * 8;
        uint4 v = *(const uint4*)(g_xBCh + (size_t)(posBase + row) * CDIM + DI + c8);
        *(uint4*)(sB + row * HSTR + c8) = v;
    }
    __syncthreads();
    if (tid == 0) {
        float acc = 0.f;
        for (int s = 0; s < 64; s++) { acc += sDt[s] * Aval; sAc[s] = acc; }
    }
    #pragma unroll
    for (int k = 0; k < 32; k++) {
        int e = tid + k * 256;
        int n = e & 127, s = e >> 7;
        sBT[n * XSTR + s] = sB[s * HSTR + n];
    }
    __syncthreads();
    if (tid < 64) sDec[tid] = expf(sAc[63] - sAc[tid]);
    __syncthreads();
    #pragma unroll
    for (int k = 0; k < 16; k++) {
        int e = tid + k * 256;
        int p = e & 63, s = e >> 6;
        float xv = __half2float(g_xBCh[(size_t)(posBase + s) * CDIM + h * 64 + p]);
        sXD[p * XSTR + s] = __float2half_rn(xv * sDt[s] * sDec[s]);
    }
    __syncthreads();

    int wm = (w >> 1) * 16, wn = (w & 1) * 64;
    float acc[8][4] = {};
    #pragma unroll
    for (int kk = 0; kk < 4; kk++) {
        int k16 = kk * 16;
        uint32_t af[4];
        int r0 = wm + gq;
        af[0] = lds32h(sXD + r0 * XSTR + k16 + 2 * tq);
        af[1] = lds32h(sXD + (r0 + 8) * XSTR + k16 + 2 * tq);
        af[2] = lds32h(sXD + r0 * XSTR + k16 + 8 + 2 * tq);
        af[3] = lds32h(sXD + (r0 + 8) * XSTR + k16 + 8 + 2 * tq);
        #pragma unroll
        for (int in = 0; in < 8; in++) {
            int n0 = wn + in * 8 + gq;
            uint32_t bf[2];
            bf[0] = lds32h(sBT + n0 * XSTR + k16 + 2 * tq);
            bf[1] = lds32h(sBT + n0 * XSTR + k16 + 8 + 2 * tq);
            mma_f16(acc[in], af, bf);
        }
    }
    size_t sbase = ((size_t)((b * NC + c) * HN + h)) * (64 * 128);
    int p0 = wm + gq, p1 = p0 + 8;
    #pragma unroll
    for (int in = 0; in < 8; in++) {
        int n0 = wn + in * 8 + 2 * tq;
        *(__half2*)(g_statesh + sbase + (size_t)p0 * 128 + n0) =
            __floats2half2_rn(acc[in][0], acc[in][1]);
        *(__half2*)(g_statesh + sbase + (size_t)p1 * 128 + n0) =
            __floats2half2_rn(acc[in][2], acc[in][3]);
    }
    if (tid == 0) g_asum[(b * HN + h) * NC + c] = sAc[63];
}

// ---------------- K5: inter-chunk prefix scan (fp16 storage, fp32 accum) ---
__global__ void __launch_bounds__(256) k_scan() {
    int bid = blockIdx.x;
    int seg = bid & 3;
    int bh = bid >> 2;
    int b = bh >> 5, h = bh & 31;
    int e = seg * 256 + threadIdx.x;
    const float* asum = &g_asum[(b * HN + h) * NC];
    float S[8];
    #pragma unroll
    for (int j = 0; j < 8; j++) S[j] = 0.f;
    for (int c = 0; c < NC; c++) {
        size_t base = ((size_t)((b * NC + c) * HN + h)) * 1024;
        float dec = expf(asum[c]);
        __half2 o[4];
        #pragma unroll
        for (int j = 0; j < 4; j++) o[j] = __floats2half2_rn(S[2 * j], S[2 * j + 1]);
        ((uint4*)g_sinh)[base + e] = *(uint4*)o;
        uint4 stv = ((const uint4*)g_statesh)[base + e];
        __half2* sth = (__half2*)&stv;
        #pragma unroll
        for (int j = 0; j < 4; j++) {
            float2 f = __half22float2(sth[j]);
            S[2 * j]     = S[2 * j] * dec + f.x;
            S[2 * j + 1] = S[2 * j + 1] * dec + f.y;
        }
    }
}

// ---------------- K4b: output pass: G||Yo fused matmul, Yd, write Y once ---
#define OFF2_C   0
#define OFF2_BS  8704
#define OFF2_XT  26112
#define OFF2_G   30720
#define OFF2_YO  35328
#define SMEM_OUT ((35328 + 64 * XSTR) * 2)   // 79872 bytes

__global__ void __launch_bounds__(256) k_out(const float* __restrict__ A_log,
                                             const float* __restrict__ Dp) {
    extern __shared__ __half smo[];
    __half* sC  = smo + OFF2_C;    // [64 l][136]
    __half* sBS = smo + OFF2_BS;   // [128][136]: rows 0-63 B, 64-127 prefix S
    __half* sXT = smo + OFF2_XT;   // [64 p][72]
    __half* sG  = smo + OFF2_G;    // [64 l][72]
    __half* sYo = smo + OFF2_YO;   // [64 l][72]
    __shared__ float sDt[64], sAc[64];

    int bid = blockIdx.x;
    int h = bid & 31, c = (bid >> 5) & 31, b = bid >> 10;
    int tid = threadIdx.x;
    int w = tid >> 5, lane = tid & 31, gq = lane >> 2, tq = lane & 3;
    float Aval = -expf(A_log[h]);
    float Dv = Dp[h];
    int posBase = b * Lq + c * 64;
    size_t sinbase = ((size_t)((b * NC + c) * HN + h)) * 8192;

    // phase 1: sDt + sC + sBS staging (no sDt readers here)
    if (tid < 64) sDt[tid] = g_dt[(posBase + tid) * HN + h];
    #pragma unroll
    for (int k = 0; k < 4; k++) {
        int e = tid + k * 256;
        int row = e >> 4, c8 = (e & 15) * 8;
        uint4 v = *(const uint4*)(g_xBCh + (size_t)(posBase + row) * CDIM + DI + DS + c8);
        *(uint4*)(sC + row * HSTR + c8) = v;
    }
    #pragma unroll
    for (int k = 0; k < 8; k++) {
        int e = tid + k * 256;
        int row = e >> 4, c8 = (e & 15) * 8;
        uint4 v;
        if (row < 64)
            v = *(const uint4*)(g_xBCh + (size_t)(posBase + row) * CDIM + DI + c8);
        else
            v = *(const uint4*)(g_sinh + sinbase + (size_t)(row - 64) * 128 + c8);
        *(uint4*)(sBS + row * HSTR + c8) = v;
    }
    __syncthreads();

    // phase 2: sAc (tid 0) + sXT staging (reads sDt — safe after sync)
    if (tid == 0) {
        float acc = 0.f;
        for (int s = 0; s < 64; s++) { acc += sDt[s] * Aval; sAc[s] = acc; }
    }
    #pragma unroll
    for (int k = 0; k < 16; k++) {
        int e = tid + k * 256;
        int p = e & 63, s = e >> 6;
        float xv = __half2float(g_xBCh[(size_t)(posBase + s) * CDIM + h * 64 + p]);
        sXT[p * XSTR + s] = __float2half_rn(xv * sDt[s]);
    }
    __syncthreads();

    // fused G||Yo = C * [B;S]^T  (M=64, N=128, K=128)
    {
        int wm = (w >> 1) * 16, wn = (w & 1) * 64;
        float acc[8][4] = {};
        #pragma unroll
        for (int kk = 0; kk < 8; kk++) {
            int k16 = kk * 16;
            uint32_t af[4];
            int r0 = wm + gq;
            af[0] = lds32h(sC + r0 * HSTR + k16 + 2 * tq);
            af[1] = lds32h(sC + (r0 + 8) * HSTR + k16 + 2 * tq);
            af[2] = lds32h(sC + r0 * HSTR + k16 + 8 + 2 * tq);
            af[3] = lds32h(sC + (r0 + 8) * HSTR + k16 + 8 + 2 * tq);
            #pragma unroll
            for (int in = 0; in < 8; in++) {
                int n0 = wn + in * 8 + gq;
                uint32_t bf[2];
                bf[0] = lds32h(sBS + n0 * HSTR + k16 + 2 * tq);
                bf[1] = lds32h(sBS + n0 * HSTR + k16 + 8 + 2 * tq);
                mma_f16(acc[in], af, bf);
            }
        }
        int l0 = wm + gq, l1 = l0 + 8;
        if ((w & 1) == 0) {
            float a0 = sAc[l0], a1 = sAc[l1];
            #pragma unroll
            for (int in = 0; in < 8; in++) {
                int s0 = in * 8 + 2 * tq, s1 = s0 + 1;
                float as0 = sAc[s0], as1 = sAc[s1];
                sG[l0 * XSTR + s0] = __float2half_rn((l0 >= s0) ? expf(a0 - as0) * acc[in][0] : 0.f);
                sG[l0 * XSTR + s1] = __float2half_rn((l0 >= s1) ? expf(a0 - as1) * acc[in][1] : 0.f);
                sG[l1 * XSTR + s0] = __float2half_rn((l1 >= s0) ? expf(a1 - as0) * acc[in][2] : 0.f);
                sG[l1 * XSTR + s1] = __float2half_rn((l1 >= s1) ? expf(a1 - as1) * acc[in][3] : 0.f);
            }
        } else {
            #pragma unroll
            for (int in = 0; in < 8; in++) {
                int p0 = in * 8 + 2 * tq;
                *(__half2*)(sYo + l0 * XSTR + p0) = __floats2half2_rn(acc[in][0], acc[in][1]);
                *(__half2*)(sYo + l1 * XSTR + p0) = __floats2half2_rn(acc[in][2], acc[in][3]);
            }
        }
    }
    __syncthreads();

    // Yd = G * XT (M=64, N=64, K=64); Y = Yd + exp(Ac)*Yo + D*xs (write once)
    {
        int wm = (w >> 1) * 16, wn = (w & 1) * 32;
        float acc[4][4] = {};
        #pragma unroll
        for (int kk = 0; kk < 4; kk++) {
            int k16 = kk * 16;
            uint32_t af[4];
            int r0 = wm + gq;
            af[0] = lds32h(sG + r0 * XSTR + k16 + 2 * tq);
            af[1] = lds32h(sG + (r0 + 8) * XSTR + k16 + 2 * tq);
            af[2] = lds32h(sG + r0 * XSTR + k16 + 8 + 2 * tq);
            af[3] = lds32h(sG + (r0 + 8) * XSTR + k16 + 8 + 2 * tq);
            #pragma unroll
            for (int in = 0; in < 4; in++) {
                int n0 = wn + in * 8 + gq;
                uint32_t bf[2];
                bf[0] = lds32h(sXT + n0 * XSTR + k16 + 2 * tq);
                bf[1] = lds32h(sXT + n0 * XSTR + k16 + 8 + 2 * tq);
                mma_f16(acc[in], af, bf);
            }
        }
        int l0 = wm + gq, l1 = l0 + 8;
        float e0 = expf(sAc[l0]), e1 = expf(sAc[l1]);
        float* y0 = &g_Y[(size_t)(posBase + l0) * DI + h * 64];
        float* y1 = &g_Y[(size_t)(posBase + l1) * DI + h * 64];
        const __half* x0 = g_xBCh + (size_t)(posBase + l0) * CDIM + h * 64;
        const __half* x1 = g_xBCh + (size_t)(posBase + l1) * CDIM + h * 64;
        #pragma unroll
        for (int in = 0; in < 4; in++) {
            int p0 = wn + in * 8 + 2 * tq;
            float2 yo0 = __half22float2(*(const __half2*)(sYo + l0 * XSTR + p0));
            float2 yo1 = __half22float2(*(const __half2*)(sYo + l1 * XSTR + p0));
            float2 xs0 = __half22float2(*(const __half2*)(x0 + p0));
            float2 xs1 = __half22float2(*(const __half2*)(x1 + p0));
            y0[p0]     = acc[in][0] + e0 * yo0.x + xs0.x * Dv;
            y0[p0 + 1] = acc[in][1] + e0 * yo0.y + xs0.y * Dv;
            y1[p0]     = acc[in][2] + e1 * yo1.x + xs1.x * Dv;
            y1[p0 + 1] = acc[in][3] + e1 * yo1.y + xs1.y * Dv;
        }
    }
}

// ---------------- K7: gated rmsnorm -> g_ynh (fp16) ----------------
__global__ void __launch_bounds__(256) k_gate(const float* __restrict__ w) {
    __shared__ float sv[DI];
    int row = blockIdx.x;
    int tid = threadIdx.x;
    float s = 0.f;
    for (int i = tid; i < DI; i += 256) {
        float z = g_zx[(size_t)row * PROJ + i];
        float y = g_Y[(size_t)row * DI + i];
        float v = y * z / (1.f + expf(-z));
        sv[i] = v;
        s += v * v;
    }
    float tot = block_sum(s);
    float inv = rsqrtf(tot / DI + 1e-5f);
    for (int i = tid; i < DI; i += 256)
        g_ynh[(size_t)row * DI + i] = __float2half_rn(sv[i] * inv * w[i]);
}

// ---------------- launcher ----------------
extern "C" void kernel_launch(void* const* d_in, const int* in_sizes, int n_in,
                              void* d_out, int out_size) {
    const float* x       = (const float*)d_in[0];
    const float* norm_w  = (const float*)d_in[1];
    const float* in_W    = (const float*)d_in[2];
    const float* conv_w  = (const float*)d_in[3];
    const float* conv_b  = (const float*)d_in[4];
    const float* dt_bias = (const float*)d_in[5];
    const float* A_log   = (const float*)d_in[6];
    const float* Dp      = (const float*)d_in[7];
    const float* ni_w    = (const float*)d_in[8];
    const float* out_W   = (const float*)d_in[9];
    float* out = (float*)d_out;

    cudaFuncSetAttribute(k_gemm1, cudaFuncAttributeMaxDynamicSharedMemorySize, SMEM_GEMM);
    cudaFuncSetAttribute(k_gemm2, cudaFuncAttributeMaxDynamicSharedMemorySize, SMEM_GEMM);
    cudaFuncSetAttribute(k_out, cudaFuncAttributeMaxDynamicSharedMemorySize, SMEM_OUT);

    __half* d_Winh;  cudaGetSymbolAddress((void**)&d_Winh, g_Winh);
    __half* d_Wouth; cudaGetSymbolAddress((void**)&d_Wouth, g_Wouth);

    k_cvt_h<<<(PROJ * DM / 4 + 255) / 256, 256>>>(in_W, d_Winh, PROJ * DM / 4);
    k_cvt_h<<<(DM * DI / 4 + 255) / 256, 256>>>(out_W, d_Wouth, DM * DI / 4);
    k_rmsnorm<<<BL, 256>>>(x, norm_w);
    k_gemm1<<<dim3((PROJ + 127) / 128, BL / 128), 128, SMEM_GEMM>>>();
    k_conv<<<dim3(CDIM / CTC, BL / CTL), 256>>>(conv_w, conv_b);
    k_dt<<<(BL * HN + 255) / 256, 256>>>(dt_bias);
    k_states<<<Bq * NC * HN, 256>>>(A_log);
    k_scan<<<Bq * HN * 4, 256>>>();
    k_out<<<Bq * NC * HN, 256, SMEM_OUT>>>(A_log, Dp);
    k_gate<<<BL, 256>>>(ni_w);
    k_gemm2<<<dim3(DM / 128, BL / 128), 128, SMEM_GEMM>>>(x, out);
}

// round 17
// speedup vs baseline: 8.7744x; 1.0231x over previous
#include <cuda_runtime.h>
#include <cuda_fp16.h>
#include <math.h>
#include <stdint.h>

#define Bq 4
#define Lq 2048
#define DM 1024
#define DI 2048
#define HN 32
#define HD 64
#define DS 128
#define CDIM 2304
#define PROJ 4384
#define CH 64
#define NC 32
#define BL 8192

// ---------------- scratch (device globals; no allocations) ----------------
__device__ __half g_xnh[(size_t)BL * DM];       // rmsnorm(x), fp16
__device__ __half g_zxh[(size_t)BL * PROJ];     // zxbcdt (fp16)
__device__ __half g_xBCh[(size_t)BL * CDIM];    // conv+silu output (fp16)
__device__ float g_dt[BL * HN];                 // softplus dt
__device__ float g_Y[(size_t)BL * DI];          // SSD output (written once)
__device__ __half g_statesh[(size_t)Bq * NC * HN * HD * DS];
__device__ __half g_sinh[(size_t)Bq * NC * HN * HD * DS];
__device__ float g_asum[Bq * HN * NC];
__device__ __half g_ynh[(size_t)BL * DI];       // gated+normed Y, fp16
__device__ __half g_Winh[(size_t)PROJ * DM];
__device__ __half g_Wouth[(size_t)DM * DI];

// ---------------- helpers ----------------
__device__ __forceinline__ float block_sum(float v) {
    __shared__ float red[8];
    #pragma unroll
    for (int o = 16; o; o >>= 1) v += __shfl_down_sync(0xffffffffu, v, o);
    if ((threadIdx.x & 31) == 0) red[threadIdx.x >> 5] = v;
    __syncthreads();
    if (threadIdx.x < 32) {
        v = (threadIdx.x < 8) ? red[threadIdx.x] : 0.f;
        #pragma unroll
        for (int o = 4; o; o >>= 1) v += __shfl_down_sync(0xffffffffu, v, o);
        if (threadIdx.x == 0) red[0] = v;
    }
    __syncthreads();
    return red[0];
}

__device__ __forceinline__ void mma_f16(float c[4], const uint32_t a[4], const uint32_t b[2]) {
    asm volatile(
        "mma.sync.aligned.m16n8k16.row.col.f32.f16.f16.f32 "
        "{%0,%1,%2,%3}, {%4,%5,%6,%7}, {%8,%9}, {%0,%1,%2,%3};"
        : "+f"(c[0]), "+f"(c[1]), "+f"(c[2]), "+f"(c[3])
        : "r"(a[0]), "r"(a[1]), "r"(a[2]), "r"(a[3]), "r"(b[0]), "r"(b[1]));
}

__device__ __forceinline__ uint32_t lds32h(const __half* p) {
    return *(const uint32_t*)p;
}

__device__ __forceinline__ void ldm_x4(const __half* p, uint32_t& r0, uint32_t& r1,
                                       uint32_t& r2, uint32_t& r3) {
    uint32_t a = (uint32_t)__cvta_generic_to_shared(p);
    asm volatile("ldmatrix.sync.aligned.m8n8.x4.shared.b16 {%0,%1,%2,%3}, [%4];"
                 : "=r"(r0), "=r"(r1), "=r"(r2), "=r"(r3) : "r"(a));
}

// ---------------- K0: convert weights fp32 -> fp16 ----------------
__global__ void __launch_bounds__(256) k_cvt_h(const float* __restrict__ src,
                                               __half* __restrict__ dst, int n4) {
    int i = blockIdx.x * 256 + threadIdx.x;
    if (i >= n4) return;
    float4 v = ((const float4*)src)[i];
    __half2 h0 = __floats2half2_rn(v.x, v.y);
    __half2 h1 = __floats2half2_rn(v.z, v.w);
    uint2 u;
    u.x = *(uint32_t*)&h0;
    u.y = *(uint32_t*)&h1;
    ((uint2*)dst)[i] = u;
}

// ---------------- K1: rmsnorm(x) -> g_xnh (fp16) ----------------
__global__ void __launch_bounds__(256) k_rmsnorm(const float* __restrict__ x,
                                                 const float* __restrict__ w) {
    int row = blockIdx.x;
    const float* xr = x + (size_t)row * DM;
    float s = 0.f;
    for (int i = threadIdx.x; i < DM; i += 256) { float v = xr[i]; s += v * v; }
    float tot = block_sum(s);
    float inv = rsqrtf(tot / DM + 1e-5f);
    for (int i = threadIdx.x; i < DM; i += 256)
        g_xnh[(size_t)row * DM + i] = __float2half_rn(xr[i] * inv * w[i]);
}

// ---------------- FP16 pipelined GEMM with ldmatrix ----------------
#define SROW 72
#define SA_H (128 * SROW)
#define STAGE_H (2 * SA_H)
#define SMEM_GEMM (STAGE_H * 2 * 2)

__device__ __forceinline__ void stage_copy16(const __half* __restrict__ A,
                                             const __half* __restrict__ Bw,
                                             __half* sA, __half* sB,
                                             int bm, int bn, int Nn, int K,
                                             int k0, int tid) {
    #pragma unroll
    for (int i = 0; i < 8; i++) {
        int c = tid + 128 * i;
        int row = c >> 3, c8 = (c & 7) * 8;
        uint32_t d = (uint32_t)__cvta_generic_to_shared(sA + row * SROW + c8);
        const __half* g = A + (size_t)(bm + row) * K + k0 + c8;
        asm volatile("cp.async.cg.shared.global [%0], [%1], 16;" :: "r"(d), "l"(g));
    }
    #pragma unroll
    for (int i = 0; i < 8; i++) {
        int c = tid + 128 * i;
        int row = c >> 3, c8 = (c & 7) * 8;
        uint32_t d = (uint32_t)__cvta_generic_to_shared(sB + row * SROW + c8);
        int n = bn + row;
        int ok = (n < Nn);
        const __half* g = Bw + (size_t)(ok ? n : 0) * K + k0 + c8;
        int sz = ok ? 16 : 0;
        asm volatile("cp.async.cg.shared.global [%0], [%1], 16, %2;" :: "r"(d), "l"(g), "r"(sz));
    }
}

__device__ __forceinline__ void load_frag16(const __half* sA, const __half* sB,
                                            int kk, uint32_t af[4][4], uint32_t bf[8][2],
                                            int wm, int wn, int lane) {
    int k16 = kk * 16;
    int lr = lane & 15, lc = (lane >> 4) * 8;
    #pragma unroll
    for (int im = 0; im < 4; im++)
        ldm_x4(sA + (wm + im * 16 + lr) * SROW + k16 + lc,
               af[im][0], af[im][1], af[im][2], af[im][3]);
    #pragma unroll
    for (int ip = 0; ip < 4; ip++)
        ldm_x4(sB + (wn + ip * 16 + lr) * SROW + k16 + lc,
               bf[2 * ip][0], bf[2 * ip + 1][0], bf[2 * ip][1], bf[2 * ip + 1][1]);
}

__device__ __forceinline__ void stage_compute16(const __half* sA, const __half* sB,
                                                float acc[4][8][4],
                                                int wm, int wn, int lane) {
    uint32_t af[2][4][4], bf[2][8][2];
    load_frag16(sA, sB, 0, af[0], bf[0], wm, wn, lane);
    #pragma unroll
    for (int kk = 0; kk < 4; kk++) {
        int cur = kk & 1;
        if (kk < 3)
            load_frag16(sA, sB, kk + 1, af[cur ^ 1], bf[cur ^ 1], wm, wn, lane);
        #pragma unroll
        for (int im = 0; im < 4; im++)
            #pragma unroll
            for (int in = 0; in < 8; in++)
                mma_f16(acc[im][in], af[cur][im], bf[cur][in]);
    }
}

// Ch != nullptr -> write half output; else write float (+ optional residual).
__device__ __forceinline__ void gemm_f16_body(const __half* __restrict__ A,
                                              const __half* __restrict__ Bw,
                                              const float* __restrict__ Res,
                                              float* __restrict__ Cf,
                                              __half* __restrict__ Ch,
                                              int M, int Nn, int K) {
    extern __shared__ __half smh[];
    int bm = blockIdx.y * 128, bn = blockIdx.x * 128;
    int tid = threadIdx.x;
    int w = tid >> 5, lane = tid & 31, g = lane >> 2, t = lane & 3;
    int wm = (w >> 1) * 64, wn = (w & 1) * 64;

    float acc[4][8][4] = {};

    stage_copy16(A, Bw, smh, smh + SA_H, bm, bn, Nn, K, 0, tid);
    asm volatile("cp.async.commit_group;");

    int nk = K / 64;
    for (int kt = 0; kt < nk; kt++) {
        asm volatile("cp.async.wait_group 0;");
        __syncthreads();
        if (kt + 1 < nk) {
            int s = (kt + 1) & 1;
            stage_copy16(A, Bw, smh + s * STAGE_H, smh + s * STAGE_H + SA_H,
                         bm, bn, Nn, K, (kt + 1) * 64, tid);
            asm volatile("cp.async.commit_group;");
        }
        int cur = kt & 1;
        stage_compute16(smh + cur * STAGE_H, smh + cur * STAGE_H + SA_H,
                        acc, wm, wn, lane);
    }

    #pragma unroll
    for (int im = 0; im < 4; im++) {
        int row = bm + wm + im * 16 + g;
        #pragma unroll
        for (int in = 0; in < 8; in++) {
            int col = bn + wn + in * 8 + 2 * t;
            if (col < Nn) {
                size_t o0 = (size_t)row * Nn + col;
                size_t o1 = (size_t)(row + 8) * Nn + col;
                float v0 = acc[im][in][0], v1 = acc[im][in][1];
                float v2 = acc[im][in][2], v3 = acc[im][in][3];
                if (Ch) {
                    *(__half2*)(Ch + o0) = __floats2half2_rn(v0, v1);
                    *(__half2*)(Ch + o1) = __floats2half2_rn(v2, v3);
                } else {
                    if (Res) {
                        v0 += Res[o0]; v1 += Res[o0 + 1];
                        v2 += Res[o1]; v3 += Res[o1 + 1];
                    }
                    Cf[o0] = v0; Cf[o0 + 1] = v1;
                    Cf[o1] = v2; Cf[o1 + 1] = v3;
                }
            }
        }
    }
}

__global__ void __launch_bounds__(128) k_gemm1() {
    gemm_f16_body(g_xnh, g_Winh, nullptr, nullptr, g_zxh, BL, PROJ, DM);
}
__global__ void __launch_bounds__(128) k_gemm2(const float* __restrict__ x,
                                               float* __restrict__ out) {
    gemm_f16_body(g_ynh, g_Wouth, x, out, nullptr, BL, DM, DI);
}

// ---------------- K3: tiled causal conv (w=4) + silu -> g_xBCh (fp16) -----
#define CTL 32
#define CTC 128
__global__ void __launch_bounds__(256) k_conv(const float* __restrict__ cw,
                                              const float* __restrict__ cb) {
    __shared__ float s[(CTL + 3) * CTC];
    int ct = blockIdx.x * CTC;
    int blt = blockIdx.y * CTL;
    int l0 = blt & (Lq - 1);
    int tid = threadIdx.x;

    for (int idx = tid; idx < (CTL + 3) * CTC; idx += 256) {
        int r = (idx >> 7) - 3;
        int ch = idx & 127;
        float v = 0.f;
        if (l0 + r >= 0)
            v = __half2float(g_zxh[(size_t)(blt + r) * PROJ + DI + ct + ch]);
        s[idx] = v;
    }
    __syncthreads();

    int ch = tid & 127;
    int li0 = (tid >> 7) * 16;
    float w0 = cw[0 * CDIM + ct + ch];
    float w1 = cw[1 * CDIM + ct + ch];
    float w2 = cw[2 * CDIM + ct + ch];
    float w3 = cw[3 * CDIM + ct + ch];
    float bias = cb[ct + ch];

    #pragma unroll
    for (int i = 0; i < 16; i++) {
        int li = li0 + i;
        float acc = bias
                  + w0 * s[li * CTC + ch]
                  + w1 * s[(li + 1) * CTC + ch]
                  + w2 * s[(li + 2) * CTC + ch]
                  + w3 * s[(li + 3) * CTC + ch];
        acc = acc / (1.f + expf(-acc));
        g_xBCh[(size_t)(blt + li) * CDIM + ct + ch] = __float2half_rn(acc);
    }
}

// ---------------- K3b: dt = softplus(raw + bias) ----------------
__global__ void __launch_bounds__(256) k_dt(const float* __restrict__ dt_bias) {
    int idx = blockIdx.x * 256 + threadIdx.x;
    if (idx >= BL * HN) return;
    int h = idx & 31;
    float v = __half2float(g_zxh[(size_t)(idx >> 5) * PROJ + DI + CDIM + h]) + dt_bias[h];
    g_dt[idx] = (v > 20.f) ? v : log1pf(expf(v));
}

// ---------------- K4a: states pass (fp16 mma) ----------------
#define HSTR 136
#define XSTR 72
__global__ void __launch_bounds__(256) k_states(const float* __restrict__ A_log) {
    __shared__ __half sB[64 * HSTR];
    __shared__ __half sBT[128 * XSTR];
    __shared__ __half sXD[64 * XSTR];
    __shared__ float sDt[64], sAc[64], sDec[64];

    int bid = blockIdx.x;
    int h = bid & 31, c = (bid >> 5) & 31, b = bid >> 10;
    int tid = threadIdx.x;
    int w = tid >> 5, lane = tid & 31, gq = lane >> 2, tq = lane & 3;
    float Aval = -expf(A_log[h]);
    int posBase = b * Lq + c * 64;

    if (tid < 64) sDt[tid] = g_dt[(posBase + tid) * HN + h];
    #pragma unroll
    for (int k = 0; k < 4; k++) {
        int e = tid + k * 256;
        int row = e >> 4, c8 = (e & 15) * 8;
        uint4 v = *(const uint4*)(g_xBCh + (size_t)(posBase + row) * CDIM + DI + c8);
        *(uint4*)(sB + row * HSTR + c8) = v;
    }
    __syncthreads();
    if (tid == 0) {
        float acc = 0.f;
        for (int s = 0; s < 64; s++) { acc += sDt[s] * Aval; sAc[s] = acc; }
    }
    #pragma unroll
    for (int k = 0; k < 32; k++) {
        int e = tid + k * 256;
        int n = e & 127, s = e >> 7;
        sBT[n * XSTR + s] = sB[s * HSTR + n];
    }
    __syncthreads();
    if (tid < 64) sDec[tid] = expf(sAc[63] - sAc[tid]);
    __syncthreads();
    #pragma unroll
    for (int k = 0; k < 16; k++) {
        int e = tid + k * 256;
        int p = e & 63, s = e >> 6;
        float xv = __half2float(g_xBCh[(size_t)(posBase + s) * CDIM + h * 64 + p]);
        sXD[p * XSTR + s] = __float2half_rn(xv * sDt[s] * sDec[s]);
    }
    __syncthreads();

    int wm = (w >> 1) * 16, wn = (w & 1) * 64;
    float acc[8][4] = {};
    #pragma unroll
    for (int kk = 0; kk < 4; kk++) {
        int k16 = kk * 16;
        uint32_t af[4];
        int r0 = wm + gq;
        af[0] = lds32h(sXD + r0 * XSTR + k16 + 2 * tq);
        af[1] = lds32h(sXD + (r0 + 8) * XSTR + k16 + 2 * tq);
        af[2] = lds32h(sXD + r0 * XSTR + k16 + 8 + 2 * tq);
        af[3] = lds32h(sXD + (r0 + 8) * XSTR + k16 + 8 + 2 * tq);
        #pragma unroll
        for (int in = 0; in < 8; in++) {
            int n0 = wn + in * 8 + gq;
            uint32_t bf[2];
            bf[0] = lds32h(sBT + n0 * XSTR + k16 + 2 * tq);
            bf[1] = lds32h(sBT + n0 * XSTR + k16 + 8 + 2 * tq);
            mma_f16(acc[in], af, bf);
        }
    }
    size_t sbase = ((size_t)((b * NC + c) * HN + h)) * (64 * 128);
    int p0 = wm + gq, p1 = p0 + 8;
    #pragma unroll
    for (int in = 0; in < 8; in++) {
        int n0 = wn + in * 8 + 2 * tq;
        *(__half2*)(g_statesh + sbase + (size_t)p0 * 128 + n0) =
            __floats2half2_rn(acc[in][0], acc[in][1]);
        *(__half2*)(g_statesh + sbase + (size_t)p1 * 128 + n0) =
            __floats2half2_rn(acc[in][2], acc[in][3]);
    }
    if (tid == 0) g_asum[(b * HN + h) * NC + c] = sAc[63];
}

// ---------------- K5: inter-chunk prefix scan (fp16 storage, fp32 accum) ---
__global__ void __launch_bounds__(256) k_scan() {
    int bid = blockIdx.x;
    int seg = bid & 3;
    int bh = bid >> 2;
    int b = bh >> 5, h = bh & 31;
    int e = seg * 256 + threadIdx.x;
    const float* asum = &g_asum[(b * HN + h) * NC];
    float S[8];
    #pragma unroll
    for (int j = 0; j < 8; j++) S[j] = 0.f;
    for (int c = 0; c < NC; c++) {
        size_t base = ((size_t)((b * NC + c) * HN + h)) * 1024;
        float dec = expf(asum[c]);
        __half2 o[4];
        #pragma unroll
        for (int j = 0; j < 4; j++) o[j] = __floats2half2_rn(S[2 * j], S[2 * j + 1]);
        ((uint4*)g_sinh)[base + e] = *(uint4*)o;
        uint4 stv = ((const uint4*)g_statesh)[base + e];
        __half2* sth = (__half2*)&stv;
        #pragma unroll
        for (int j = 0; j < 4; j++) {
            float2 f = __half22float2(sth[j]);
            S[2 * j]     = S[2 * j] * dec + f.x;
            S[2 * j + 1] = S[2 * j + 1] * dec + f.y;
        }
    }
}

// ---------------- K4b: output pass: G||Yo fused matmul, Yd, write Y once ---
#define OFF2_C   0
#define OFF2_BS  8704
#define OFF2_XT  26112
#define OFF2_G   30720
#define OFF2_YO  35328
#define SMEM_OUT ((35328 + 64 * XSTR) * 2)   // 79872 bytes

__global__ void __launch_bounds__(256) k_out(const float* __restrict__ A_log,
                                             const float* __restrict__ Dp) {
    extern __shared__ __half smo[];
    __half* sC  = smo + OFF2_C;
    __half* sBS = smo + OFF2_BS;
    __half* sXT = smo + OFF2_XT;
    __half* sG  = smo + OFF2_G;
    __half* sYo = smo + OFF2_YO;
    __shared__ float sDt[64], sAc[64];

    int bid = blockIdx.x;
    int h = bid & 31, c = (bid >> 5) & 31, b = bid >> 10;
    int tid = threadIdx.x;
    int w = tid >> 5, lane = tid & 31, gq = lane >> 2, tq = lane & 3;
    float Aval = -expf(A_log[h]);
    float Dv = Dp[h];
    int posBase = b * Lq + c * 64;
    size_t sinbase = ((size_t)((b * NC + c) * HN + h)) * 8192;

    if (tid < 64) sDt[tid] = g_dt[(posBase + tid) * HN + h];
    #pragma unroll
    for (int k = 0; k < 4; k++) {
        int e = tid + k * 256;
        int row = e >> 4, c8 = (e & 15) * 8;
        uint4 v = *(const uint4*)(g_xBCh + (size_t)(posBase + row) * CDIM + DI + DS + c8);
        *(uint4*)(sC + row * HSTR + c8) = v;
    }
    #pragma unroll
    for (int k = 0; k < 8; k++) {
        int e = tid + k * 256;
        int row = e >> 4, c8 = (e & 15) * 8;
        uint4 v;
        if (row < 64)
            v = *(const uint4*)(g_xBCh + (size_t)(posBase + row) * CDIM + DI + c8);
        else
            v = *(const uint4*)(g_sinh + sinbase + (size_t)(row - 64) * 128 + c8);
        *(uint4*)(sBS + row * HSTR + c8) = v;
    }
    __syncthreads();

    if (tid == 0) {
        float acc = 0.f;
        for (int s = 0; s < 64; s++) { acc += sDt[s] * Aval; sAc[s] = acc; }
    }
    #pragma unroll
    for (int k = 0; k < 16; k++) {
        int e = tid + k * 256;
        int p = e & 63, s = e >> 6;
        float xv = __half2float(g_xBCh[(size_t)(posBase + s) * CDIM + h * 64 + p]);
        sXT[p * XSTR + s] = __float2half_rn(xv * sDt[s]);
    }
    __syncthreads();

    {
        int wm = (w >> 1) * 16, wn = (w & 1) * 64;
        float acc[8][4] = {};
        #pragma unroll
        for (int kk = 0; kk < 8; kk++) {
            int k16 = kk * 16;
            uint32_t af[4];
            int r0 = wm + gq;
            af[0] = lds32h(sC + r0 * HSTR + k16 + 2 * tq);
            af[1] = lds32h(sC + (r0 + 8) * HSTR + k16 + 2 * tq);
            af[2] = lds32h(sC + r0 * HSTR + k16 + 8 + 2 * tq);
            af[3] = lds32h(sC + (r0 + 8) * HSTR + k16 + 8 + 2 * tq);
            #pragma unroll
            for (int in = 0; in < 8; in++) {
                int n0 = wn + in * 8 + gq;
                uint32_t bf[2];
                bf[0] = lds32h(sBS + n0 * HSTR + k16 + 2 * tq);
                bf[1] = lds32h(sBS + n0 * HSTR + k16 + 8 + 2 * tq);
                mma_f16(acc[in], af, bf);
            }
        }
        int l0 = wm + gq, l1 = l0 + 8;
        if ((w & 1) == 0) {
            float a0 = sAc[l0], a1 = sAc[l1];
            #pragma unroll
            for (int in = 0; in < 8; in++) {
                int s0 = in * 8 + 2 * tq, s1 = s0 + 1;
                float as0 = sAc[s0], as1 = sAc[s1];
                sG[l0 * XSTR + s0] = __float2half_rn((l0 >= s0) ? expf(a0 - as0) * acc[in][0] : 0.f);
                sG[l0 * XSTR + s1] = __float2half_rn((l0 >= s1) ? expf(a0 - as1) * acc[in][1] : 0.f);
                sG[l1 * XSTR + s0] = __float2half_rn((l1 >= s0) ? expf(a1 - as0) * acc[in][2] : 0.f);
                sG[l1 * XSTR + s1] = __float2half_rn((l1 >= s1) ? expf(a1 - as1) * acc[in][3] : 0.f);
            }
        } else {
            #pragma unroll
            for (int in = 0; in < 8; in++) {
                int p0 = in * 8 + 2 * tq;
                *(__half2*)(sYo + l0 * XSTR + p0) = __floats2half2_rn(acc[in][0], acc[in][1]);
                *(__half2*)(sYo + l1 * XSTR + p0) = __floats2half2_rn(acc[in][2], acc[in][3]);
            }
        }
    }
    __syncthreads();

    {
        int wm = (w >> 1) * 16, wn = (w & 1) * 32;
        float acc[4][4] = {};
        #pragma unroll
        for (int kk = 0; kk < 4; kk++) {
            int k16 = kk * 16;
            uint32_t af[4];
            int r0 = wm + gq;
            af[0] = lds32h(sG + r0 * XSTR + k16 + 2 * tq);
            af[1] = lds32h(sG + (r0 + 8) * XSTR + k16 + 2 * tq);
            af[2] = lds32h(sG + r0 * XSTR + k16 + 8 + 2 * tq);
            af[3] = lds32h(sG + (r0 + 8) * XSTR + k16 + 8 + 2 * tq);
            #pragma unroll
            for (int in = 0; in < 4; in++) {
                int n0 = wn + in * 8 + gq;
                uint32_t bf[2];
                bf[0] = lds32h(sXT + n0 * XSTR + k16 + 2 * tq);
                bf[1] = lds32h(sXT + n0 * XSTR + k16 + 8 + 2 * tq);
                mma_f16(acc[in], af, bf);
            }
        }
        int l0 = wm + gq, l1 = l0 + 8;
        float e0 = expf(sAc[l0]), e1 = expf(sAc[l1]);
        float* y0 = &g_Y[(size_t)(posBase + l0) * DI + h * 64];
        float* y1 = &g_Y[(size_t)(posBase + l1) * DI + h * 64];
        const __half* x0 = g_xBCh + (size_t)(posBase + l0) * CDIM + h * 64;
        const __half* x1 = g_xBCh + (size_t)(posBase + l1) * CDIM + h * 64;
        #pragma unroll
        for (int in = 0; in < 4; in++) {
            int p0 = wn + in * 8 + 2 * tq;
            float2 yo0 = __half22float2(*(const __half2*)(sYo + l0 * XSTR + p0));
            float2 yo1 = __half22float2(*(const __half2*)(sYo + l1 * XSTR + p0));
            float2 xs0 = __half22float2(*(const __half2*)(x0 + p0));
            float2 xs1 = __half22float2(*(const __half2*)(x1 + p0));
            y0[p0]     = acc[in][0] + e0 * yo0.x + xs0.x * Dv;
            y0[p0 + 1] = acc[in][1] + e0 * yo0.y + xs0.y * Dv;
            y1[p0]     = acc[in][2] + e1 * yo1.x + xs1.x * Dv;
            y1[p0 + 1] = acc[in][3] + e1 * yo1.y + xs1.y * Dv;
        }
    }
}

// ---------------- K7: gated rmsnorm -> g_ynh (fp16) ----------------
__global__ void __launch_bounds__(256) k_gate(const float* __restrict__ w) {
    __shared__ float sv[DI];
    int row = blockIdx.x;
    int tid = threadIdx.x;
    float s = 0.f;
    for (int i = tid; i < DI; i += 256) {
        float z = __half2float(g_zxh[(size_t)row * PROJ + i]);
        float y = g_Y[(size_t)row * DI + i];
        float v = y * z / (1.f + expf(-z));
        sv[i] = v;
        s += v * v;
    }
    float tot = block_sum(s);
    float inv = rsqrtf(tot / DI + 1e-5f);
    for (int i = tid; i < DI; i += 256)
        g_ynh[(size_t)row * DI + i] = __float2half_rn(sv[i] * inv * w[i]);
}

// ---------------- launcher ----------------
extern "C" void kernel_launch(void* const* d_in, const int* in_sizes, int n_in,
                              void* d_out, int out_size) {
    const float* x       = (const float*)d_in[0];
    const float* norm_w  = (const float*)d_in[1];
    const float* in_W    = (const float*)d_in[2];
    const float* conv_w  = (const float*)d_in[3];
    const float* conv_b  = (const float*)d_in[4];
    const float* dt_bias = (const float*)d_in[5];
    const float* A_log   = (const float*)d_in[6];
    const float* Dp      = (const float*)d_in[7];
    const float* ni_w    = (const float*)d_in[8];
    const float* out_W   = (const float*)d_in[9];
    float* out = (float*)d_out;

    cudaFuncSetAttribute(k_gemm1, cudaFuncAttributeMaxDynamicSharedMemorySize, SMEM_GEMM);
    cudaFuncSetAttribute(k_gemm2, cudaFuncAttributeMaxDynamicSharedMemorySize, SMEM_GEMM);
    cudaFuncSetAttribute(k_out, cudaFuncAttributeMaxDynamicSharedMemorySize, SMEM_OUT);

    __half* d_Winh;  cudaGetSymbolAddress((void**)&d_Winh, g_Winh);
    __half* d_Wouth; cudaGetSymbolAddress((void**)&d_Wouth, g_Wouth);

    k_cvt_h<<<(PROJ * DM / 4 + 255) / 256, 256>>>(in_W, d_Winh, PROJ * DM / 4);
    k_cvt_h<<<(DM * DI / 4 + 255) / 256, 256>>>(out_W, d_Wouth, DM * DI / 4);
    k_rmsnorm<<<BL, 256>>>(x, norm_w);
    k_gemm1<<<dim3((PROJ + 127) / 128, BL / 128), 128, SMEM_GEMM>>>();
    k_conv<<<dim3(CDIM / CTC, BL / CTL), 256>>>(conv_w, conv_b);
    k_dt<<<(BL * HN + 255) / 256, 256>>>(dt_bias);
    k_states<<<Bq * NC * HN, 256>>>(A_log);
    k_scan<<<Bq * HN * 4, 256>>>();
    k_out<<<Bq * NC * HN, 256, SMEM_OUT>>>(A_log, Dp);
    k_gate<<<BL, 256>>>(ni_w);
    k_gemm2<<<dim3(DM / 128, BL / 128), 128, SMEM_GEMM>>>(x, out);
}